// round 1
// baseline (speedup 1.0000x reference)
#include <cuda_runtime.h>
#include <math.h>

#define B_SZ 256
#define T_SZ 256
#define IN_DIM 64
#define HID 1024
#define DIM2 512
#define OUT_DIM 16
#define MT (B_SZ*T_SZ)   // 65536 rows

// ---------------- scratch (device globals; no allocation allowed) ----------
__device__ float g_x1[(size_t)MT*DIM2];         // 134 MB
__device__ float g_x2[(size_t)MT*HID];          // 268 MB
__device__ float g_gi[(size_t)MT*3*HID];        // 805 MB
__device__ float g_h[2][B_SZ*HID];              // 2 MB ping-pong hidden state
__device__ float g_rh[B_SZ*HID];                // relu(h)
__device__ float g_o3[B_SZ*DIM2];               // fc3 output

// ---------------- generic NT GEMM: C[M,N] = A[M,K] @ W[N,K]^T + bias -------
// BM=BN=64, BK=16, 256 threads, 4x4 micro-tile per thread.
template<bool RELU>
__global__ __launch_bounds__(256)
void gemm_nt(const float* __restrict__ A, const float* __restrict__ W,
             const float* __restrict__ bias, float* __restrict__ C,
             int M, int N, int K)
{
    __shared__ float As[16][68];   // [k][m], padded so float4 rows stay 16B aligned
    __shared__ float Ws[16][68];   // [k][n]
    const int tid = threadIdx.x;
    const int m0 = blockIdx.x * 64, n0 = blockIdx.y * 64;
    const int tx = tid & 15, ty = tid >> 4;

    float acc[4][4] = {};
    const int ar = tid >> 2;            // 0..63 (row within tile)
    const int ak = (tid & 3) * 4;       // 0,4,8,12 (k offset)
    const float* Aptr = A + (size_t)(m0 + ar) * K + ak;
    const float* Wptr = W + (size_t)(n0 + ar) * K + ak;

    for (int k0 = 0; k0 < K; k0 += 16) {
        float4 av = *(const float4*)(Aptr + k0);
        float4 wv = *(const float4*)(Wptr + k0);
        As[ak+0][ar] = av.x; As[ak+1][ar] = av.y; As[ak+2][ar] = av.z; As[ak+3][ar] = av.w;
        Ws[ak+0][ar] = wv.x; Ws[ak+1][ar] = wv.y; Ws[ak+2][ar] = wv.z; Ws[ak+3][ar] = wv.w;
        __syncthreads();
        #pragma unroll
        for (int k = 0; k < 16; k++) {
            float4 a = *(const float4*)&As[k][ty*4];
            float4 w = *(const float4*)&Ws[k][tx*4];
            float avv[4] = {a.x, a.y, a.z, a.w};
            float wvv[4] = {w.x, w.y, w.z, w.w};
            #pragma unroll
            for (int i = 0; i < 4; i++)
                #pragma unroll
                for (int j = 0; j < 4; j++)
                    acc[i][j] += avv[i] * wvv[j];
        }
        __syncthreads();
    }

    #pragma unroll
    for (int i = 0; i < 4; i++) {
        int m = m0 + ty*4 + i;
        #pragma unroll
        for (int j = 0; j < 4; j++) {
            int n = n0 + tx*4 + j;
            float v = acc[i][j] + bias[n];
            if (RELU) v = fmaxf(v, 0.f);
            C[(size_t)m * N + n] = v;
        }
    }
}

// ---------------- fused GRU step ------------------------------------------
// One launch per time step. Block tile: 64 batches x 32 hidden cols, computing
// all 3 gate GEMM columns (r,z,n) for its j-tile plus the elementwise update.
// Grid (B/64=4, HID/32=32) = 128 blocks (one wave on 148 SMs).
__global__ __launch_bounds__(256)
void gru_step(const float* __restrict__ h_in, float* __restrict__ h_out,
              const float* __restrict__ gi, const float* __restrict__ w_hh,
              const float* __restrict__ b_hh, int t)
{
    __shared__ float hs[32][68];       // [k][m], m padded for aligned float4
    __shared__ float wt[3][32][36];    // [gate][k][j], j padded (36*4 % 16 == 0)
    const int tid = threadIdx.x;
    const int m0 = blockIdx.x * 64;
    const int j0 = blockIdx.y * 32;
    const int tx = tid & 15, ty = tid >> 4;

    float acc[3][4][2] = {};

    for (int k0 = 0; k0 < HID; k0 += 32) {
        // load h tile: 64 rows x 32 k
        {
            int k = tid & 31, r0 = tid >> 5;
            #pragma unroll
            for (int i = 0; i < 8; i++) {
                int r = r0 + i * 8;
                hs[k][r] = h_in[(size_t)(m0 + r) * HID + k0 + k];
            }
        }
        // load w tile: 3 gates x 32 j x 32 k  (w_hh is [3*HID][HID] row-major)
        #pragma unroll
        for (int i = 0; i < 12; i++) {
            int idx = tid + i * 256;
            int g = idx >> 10, rem = idx & 1023;
            int jr = rem >> 5, k = rem & 31;
            wt[g][k][jr] = w_hh[(size_t)(g * HID + j0 + jr) * HID + k0 + k];
        }
        __syncthreads();
        #pragma unroll 8
        for (int k = 0; k < 32; k++) {
            float4 a = *(const float4*)&hs[k][ty*4];
            float av[4] = {a.x, a.y, a.z, a.w};
            #pragma unroll
            for (int g = 0; g < 3; g++) {
                float2 w = *(const float2*)&wt[g][k][tx*2];
                #pragma unroll
                for (int i = 0; i < 4; i++) {
                    acc[g][i][0] += av[i] * w.x;
                    acc[g][i][1] += av[i] * w.y;
                }
            }
        }
        __syncthreads();
    }

    // gates + state update
    #pragma unroll
    for (int i = 0; i < 4; i++) {
        int m = m0 + ty*4 + i;
        const float* gip = gi + ((size_t)m * T_SZ + t) * (3 * HID);
        #pragma unroll
        for (int c = 0; c < 2; c++) {
            int j = j0 + tx*2 + c;
            float hr  = acc[0][i][c] + b_hh[j];
            float hz  = acc[1][i][c] + b_hh[HID + j];
            float hnn = acc[2][i][c] + b_hh[2*HID + j];
            float ir  = gip[j];
            float iz  = gip[HID + j];
            float inn = gip[2*HID + j];
            float r = 1.f / (1.f + expf(-(ir + hr)));
            float z = 1.f / (1.f + expf(-(iz + hz)));
            float n = tanhf(inn + r * hnn);
            float hp = h_in[(size_t)m * HID + j];
            h_out[(size_t)m * HID + j] = (1.f - z) * n + z * hp;
        }
    }
}

// ---------------- small helper kernels ------------------------------------
__global__ void copy_kernel(const float* __restrict__ src, float* __restrict__ dst, int n)
{
    int i = blockIdx.x * blockDim.x + threadIdx.x;
    if (i < n) dst[i] = src[i];
}

__global__ void finalize_h(const float* __restrict__ h, float* __restrict__ rh,
                           float* __restrict__ out_hn)
{
    int i = blockIdx.x * blockDim.x + threadIdx.x;
    if (i < B_SZ * HID) {
        float v = h[i];
        rh[i] = fmaxf(v, 0.f);
        out_hn[i] = v;          // hn_out is the raw (pre-relu) hidden state
    }
}

// params[b][o] = sum_d o3[b][d] * heads_w[c[b]][o][d] + heads_b[c[b]][o]
__global__ __launch_bounds__(128)
void heads_kernel(const float* __restrict__ o3, const int* __restrict__ cult,
                  const float* __restrict__ hw, const float* __restrict__ hb,
                  float* __restrict__ outp)
{
    int b = blockIdx.x;
    int c = cult[b];
    __shared__ float sv[DIM2];
    for (int i = threadIdx.x; i < DIM2; i += blockDim.x)
        sv[i] = o3[(size_t)b * DIM2 + i];
    __syncthreads();
    int o = threadIdx.x >> 3, l = threadIdx.x & 7;   // 8 lanes per output
    const float* w = hw + ((size_t)c * OUT_DIM + o) * DIM2;
    float s = 0.f;
    for (int d = l; d < DIM2; d += 8) s += sv[d] * w[d];
    s += __shfl_down_sync(0xffffffffu, s, 4);
    s += __shfl_down_sync(0xffffffffu, s, 2);
    s += __shfl_down_sync(0xffffffffu, s, 1);
    if (l == 0) outp[b * OUT_DIM + o] = s + hb[c * OUT_DIM + o];
}

// ---------------- launch ---------------------------------------------------
extern "C" void kernel_launch(void* const* d_in, const int* in_sizes, int n_in,
                              void* d_out, int out_size)
{
    const float* input = (const float*)d_in[0];
    const float* hn    = (const float*)d_in[1];
    const int*   cult  = (const int*)  d_in[2];
    const float* fc1_w = (const float*)d_in[3];
    const float* fc1_b = (const float*)d_in[4];
    const float* fc2_w = (const float*)d_in[5];
    const float* fc2_b = (const float*)d_in[6];
    const float* w_ih  = (const float*)d_in[7];
    const float* w_hh  = (const float*)d_in[8];
    const float* b_ih  = (const float*)d_in[9];
    const float* b_hh  = (const float*)d_in[10];
    const float* fc3_w = (const float*)d_in[11];
    const float* fc3_b = (const float*)d_in[12];
    const float* hw    = (const float*)d_in[13];
    const float* hb    = (const float*)d_in[14];
    float* outp = (float*)d_out;

    float *x1, *x2, *gi, *h0, *h1, *rh, *o3;
    cudaGetSymbolAddress((void**)&x1, g_x1);
    cudaGetSymbolAddress((void**)&x2, g_x2);
    cudaGetSymbolAddress((void**)&gi, g_gi);
    cudaGetSymbolAddress((void**)&h0, g_h);          // g_h[0]
    h1 = h0 + (size_t)B_SZ * HID;                    // g_h[1]
    cudaGetSymbolAddress((void**)&rh, g_rh);
    cudaGetSymbolAddress((void**)&o3, g_o3);

    // fc1: [65536,64] @ [512,64]^T -> x1
    gemm_nt<false><<<dim3(MT/64, DIM2/64), 256>>>(input, fc1_w, fc1_b, x1, MT, DIM2, IN_DIM);
    // fc2: x1 @ [1024,512]^T -> x2
    gemm_nt<false><<<dim3(MT/64, HID/64), 256>>>(x1, fc2_w, fc2_b, x2, MT, HID, DIM2);
    // gi_all: x2 @ [3072,1024]^T + b_ih -> gi
    gemm_nt<false><<<dim3(MT/64, (3*HID)/64), 256>>>(x2, w_ih, b_ih, gi, MT, 3*HID, HID);

    // h <- h0 (input hn[0])
    copy_kernel<<<(B_SZ*HID + 255)/256, 256>>>(hn, h0, B_SZ*HID);

    // sequential GRU
    float* bufs[2] = {h0, h1};
    for (int t = 0; t < T_SZ; t++) {
        gru_step<<<dim3(B_SZ/64, HID/32), 256>>>(bufs[t & 1], bufs[(t + 1) & 1],
                                                 gi, w_hh, b_hh, t);
    }
    float* hfin = bufs[T_SZ & 1];   // T even -> g_h[0]

    // write hn_out to tail of d_out, relu copy for fc3
    int hn_off = out_size - B_SZ * HID;   // params first, then hn_out
    finalize_h<<<(B_SZ*HID + 255)/256, 256>>>(hfin, rh, outp + hn_off);

    // fc3 with relu epilogue: relu(h) @ [512,1024]^T
    gemm_nt<true><<<dim3(B_SZ/64, DIM2/64), 256>>>(rh, fc3_w, fc3_b, o3, B_SZ, DIM2, HID);

    // per-sample head
    heads_kernel<<<B_SZ, 128>>>(o3, cult, hw, hb, outp);
}

// round 2
// speedup vs baseline: 1.5985x; 1.5985x over previous
#include <cuda_runtime.h>
#include <math.h>

#define B_SZ 256
#define T_SZ 256
#define IN_DIM 64
#define HID 1024
#define DIM2 512
#define OUT_DIM 16
#define MT (B_SZ*T_SZ)   // 65536 rows

// ---------------- scratch (device globals; no allocation allowed) ----------
__device__ float g_x1[(size_t)MT*DIM2];         // 134 MB
__device__ float g_x2[(size_t)MT*HID];          // 268 MB
__device__ float g_gi[(size_t)MT*3*HID];        // 805 MB, layout [t][b][3H]
__device__ float g_h[2][B_SZ*HID];              // ping-pong hidden state
__device__ float g_rh[B_SZ*HID];                // relu(h)
__device__ float g_o3[B_SZ*DIM2];               // fc3 output

// ---------------- tf32 helpers --------------------------------------------
__device__ __forceinline__ unsigned f2tf(float x) {
    unsigned u; asm("cvt.rna.tf32.f32 %0, %1;" : "=r"(u) : "f"(x)); return u;
}
__device__ __forceinline__ void mma8(float* c, const unsigned* a, const unsigned* b) {
    asm volatile("mma.sync.aligned.m16n8k8.row.col.f32.tf32.tf32.f32 "
        "{%0,%1,%2,%3}, {%4,%5,%6,%7}, {%8,%9}, {%0,%1,%2,%3};"
        : "+f"(c[0]), "+f"(c[1]), "+f"(c[2]), "+f"(c[3])
        : "r"(a[0]), "r"(a[1]), "r"(a[2]), "r"(a[3]), "r"(b[0]), "r"(b[1]));
}

// ---------------- generic tf32 MMA GEMM ------------------------------------
// C[M,N] = A[M,K] @ W[N,K]^T + bias.  BM=128, BN=64, BK=16, 256 thr (8 warps,
// 4x2 warp grid, 32x32 warp tiles). TRANS_OUT remaps row m=b*T+t -> t*B+b.
template<bool RELU, bool TRANS_OUT>
__global__ __launch_bounds__(256)
void gemm_mma(const float* __restrict__ A, const float* __restrict__ W,
              const float* __restrict__ bias, float* __restrict__ C,
              int M, int N, int K)
{
    __shared__ unsigned As[128][17];
    __shared__ unsigned Ws[64][17];
    const int tid = threadIdx.x, wid = tid >> 5, lane = tid & 31;
    const int m0 = blockIdx.x * 128, n0 = blockIdx.y * 64;
    const int wm = wid & 3, wn = wid >> 2;

    float acc[2][4][4] = {};

    const int arow = tid >> 1, akc = (tid & 1) * 8;   // A: 2 float4/thread
    const int wrow = tid >> 2, wkc = (tid & 3) * 4;   // W: 1 float4/thread
    const float* Ap = A + (size_t)(m0 + arow) * K + akc;
    const float* Wp = W + (size_t)(n0 + wrow) * K + wkc;

    for (int k0 = 0; k0 < K; k0 += 16) {
        float4 v0 = *(const float4*)(Ap + k0);
        float4 v1 = *(const float4*)(Ap + k0 + 4);
        As[arow][akc+0] = f2tf(v0.x); As[arow][akc+1] = f2tf(v0.y);
        As[arow][akc+2] = f2tf(v0.z); As[arow][akc+3] = f2tf(v0.w);
        As[arow][akc+4] = f2tf(v1.x); As[arow][akc+5] = f2tf(v1.y);
        As[arow][akc+6] = f2tf(v1.z); As[arow][akc+7] = f2tf(v1.w);
        float4 w0 = *(const float4*)(Wp + k0);
        Ws[wrow][wkc+0] = f2tf(w0.x); Ws[wrow][wkc+1] = f2tf(w0.y);
        Ws[wrow][wkc+2] = f2tf(w0.z); Ws[wrow][wkc+3] = f2tf(w0.w);
        __syncthreads();
        #pragma unroll
        for (int kk = 0; kk < 2; kk++) {
            const int kc = kk * 8 + (lane & 3);
            unsigned a[2][4];
            #pragma unroll
            for (int mt = 0; mt < 2; mt++) {
                int r = wm * 32 + mt * 16 + (lane >> 2);
                a[mt][0] = As[r][kc];     a[mt][1] = As[r+8][kc];
                a[mt][2] = As[r][kc+4];   a[mt][3] = As[r+8][kc+4];
            }
            #pragma unroll
            for (int nt = 0; nt < 4; nt++) {
                int bn = wn * 32 + nt * 8 + (lane >> 2);
                unsigned b[2] = { Ws[bn][kc], Ws[bn][kc+4] };
                mma8(acc[0][nt], a[0], b);
                mma8(acc[1][nt], a[1], b);
            }
        }
        __syncthreads();
    }

    #pragma unroll
    for (int mt = 0; mt < 2; mt++)
        #pragma unroll
        for (int nt = 0; nt < 4; nt++)
            #pragma unroll
            for (int half = 0; half < 2; half++) {
                int m = m0 + wm * 32 + mt * 16 + (lane >> 2) + half * 8;
                int n = n0 + wn * 32 + nt * 8 + (lane & 3) * 2;
                float2 v;
                v.x = acc[mt][nt][half*2+0] + bias[n];
                v.y = acc[mt][nt][half*2+1] + bias[n+1];
                if (RELU) { v.x = fmaxf(v.x, 0.f); v.y = fmaxf(v.y, 0.f); }
                size_t row = TRANS_OUT ? ((size_t)(m & (T_SZ-1)) * B_SZ + (m >> 8))
                                       : (size_t)m;
                *(float2*)(C + row * N + n) = v;
            }
}

// ---------------- fused tensor-core GRU step -------------------------------
// Grid (B/64=4, HID/32=32)=128 blocks, 256 thr (8 warps: 4m x 2j).
// Each block: gh = h[64 rows] @ w_hh^T for its 32-j tile x 3 gates, + update.
// gi_t points at gi[t] with layout [b][3H].
__global__ __launch_bounds__(256)
void gru_step_mma(const float* __restrict__ h_in, float* __restrict__ h_out,
                  const float* __restrict__ gi_t, const float* __restrict__ w_hh,
                  const float* __restrict__ b_hh)
{
    __shared__ unsigned hs[64][17];
    __shared__ unsigned ws[96][17];
    const int tid = threadIdx.x, wid = tid >> 5, lane = tid & 31;
    const int m0 = blockIdx.x * 64, j0 = blockIdx.y * 32;
    const int wm = wid & 3, wj = wid >> 2;

    float acc[3][2][4] = {};

    const int hrow = tid >> 2, hkc = (tid & 3) * 4;   // h: 1 float4/thread
    const float* Hp = h_in + (size_t)(m0 + hrow) * HID + hkc;

    for (int k0 = 0; k0 < HID; k0 += 16) {
        float4 hv = *(const float4*)(Hp + k0);
        hs[hrow][hkc+0] = f2tf(hv.x); hs[hrow][hkc+1] = f2tf(hv.y);
        hs[hrow][hkc+2] = f2tf(hv.z); hs[hrow][hkc+3] = f2tf(hv.w);
        #pragma unroll
        for (int i = 0; i < 2; i++) {
            int idx = tid + i * 256;
            if (idx < 384) {
                int row = idx >> 2, kc = (idx & 3) * 4;
                int g = row >> 5, jr = row & 31;
                float4 wv = *(const float4*)(w_hh + ((size_t)(g * HID + j0 + jr)) * HID + k0 + kc);
                ws[row][kc+0] = f2tf(wv.x); ws[row][kc+1] = f2tf(wv.y);
                ws[row][kc+2] = f2tf(wv.z); ws[row][kc+3] = f2tf(wv.w);
            }
        }
        __syncthreads();
        #pragma unroll
        for (int kk = 0; kk < 2; kk++) {
            const int kc = kk * 8 + (lane & 3);
            int r = wm * 16 + (lane >> 2);
            unsigned a[4] = { hs[r][kc], hs[r+8][kc], hs[r][kc+4], hs[r+8][kc+4] };
            #pragma unroll
            for (int g = 0; g < 3; g++)
                #pragma unroll
                for (int nt = 0; nt < 2; nt++) {
                    int bn = g * 32 + wj * 16 + nt * 8 + (lane >> 2);
                    unsigned b[2] = { ws[bn][kc], ws[bn][kc+4] };
                    mma8(acc[g][nt], a, b);
                }
        }
        __syncthreads();
    }

    // gates + state update
    #pragma unroll
    for (int nt = 0; nt < 2; nt++)
        #pragma unroll
        for (int half = 0; half < 2; half++) {
            int m = m0 + wm * 16 + (lane >> 2) + half * 8;
            int jb = j0 + wj * 16 + nt * 8 + (lane & 3) * 2;
            const float* gp = gi_t + (size_t)m * (3 * HID);
            #pragma unroll
            for (int c = 0; c < 2; c++) {
                int j = jb + c;
                float hr  = acc[0][nt][half*2+c] + b_hh[j];
                float hz  = acc[1][nt][half*2+c] + b_hh[HID + j];
                float hnn = acc[2][nt][half*2+c] + b_hh[2*HID + j];
                float r_ = 1.f / (1.f + expf(-(gp[j] + hr)));
                float z_ = 1.f / (1.f + expf(-(gp[HID + j] + hz)));
                float n_ = tanhf(gp[2*HID + j] + r_ * hnn);
                float hp = h_in[(size_t)m * HID + j];
                h_out[(size_t)m * HID + j] = (1.f - z_) * n_ + z_ * hp;
            }
        }
}

// ---------------- small helper kernels ------------------------------------
__global__ void copy_kernel(const float* __restrict__ src, float* __restrict__ dst, int n)
{
    int i = blockIdx.x * blockDim.x + threadIdx.x;
    if (i < n) dst[i] = src[i];
}

__global__ void finalize_h(const float* __restrict__ h, float* __restrict__ rh,
                           float* __restrict__ out_hn)
{
    int i = blockIdx.x * blockDim.x + threadIdx.x;
    if (i < B_SZ * HID) {
        float v = h[i];
        rh[i] = fmaxf(v, 0.f);
        out_hn[i] = v;
    }
}

__global__ __launch_bounds__(128)
void heads_kernel(const float* __restrict__ o3, const int* __restrict__ cult,
                  const float* __restrict__ hw, const float* __restrict__ hb,
                  float* __restrict__ outp)
{
    int b = blockIdx.x;
    int c = cult[b];
    __shared__ float sv[DIM2];
    for (int i = threadIdx.x; i < DIM2; i += blockDim.x)
        sv[i] = o3[(size_t)b * DIM2 + i];
    __syncthreads();
    int o = threadIdx.x >> 3, l = threadIdx.x & 7;
    const float* w = hw + ((size_t)c * OUT_DIM + o) * DIM2;
    float s = 0.f;
    for (int d = l; d < DIM2; d += 8) s += sv[d] * w[d];
    s += __shfl_down_sync(0xffffffffu, s, 4);
    s += __shfl_down_sync(0xffffffffu, s, 2);
    s += __shfl_down_sync(0xffffffffu, s, 1);
    if (l == 0) outp[b * OUT_DIM + o] = s + hb[c * OUT_DIM + o];
}

// ---------------- launch ---------------------------------------------------
extern "C" void kernel_launch(void* const* d_in, const int* in_sizes, int n_in,
                              void* d_out, int out_size)
{
    const float* input = (const float*)d_in[0];
    const float* hn    = (const float*)d_in[1];
    const int*   cult  = (const int*)  d_in[2];
    const float* fc1_w = (const float*)d_in[3];
    const float* fc1_b = (const float*)d_in[4];
    const float* fc2_w = (const float*)d_in[5];
    const float* fc2_b = (const float*)d_in[6];
    const float* w_ih  = (const float*)d_in[7];
    const float* w_hh  = (const float*)d_in[8];
    const float* b_ih  = (const float*)d_in[9];
    const float* b_hh  = (const float*)d_in[10];
    const float* fc3_w = (const float*)d_in[11];
    const float* fc3_b = (const float*)d_in[12];
    const float* hw    = (const float*)d_in[13];
    const float* hb    = (const float*)d_in[14];
    float* outp = (float*)d_out;

    float *x1, *x2, *gi, *h0, *h1, *rh, *o3;
    cudaGetSymbolAddress((void**)&x1, g_x1);
    cudaGetSymbolAddress((void**)&x2, g_x2);
    cudaGetSymbolAddress((void**)&gi, g_gi);
    cudaGetSymbolAddress((void**)&h0, g_h);
    h1 = h0 + (size_t)B_SZ * HID;
    cudaGetSymbolAddress((void**)&rh, g_rh);
    cudaGetSymbolAddress((void**)&o3, g_o3);

    // fc1: [65536,64] @ [512,64]^T
    gemm_mma<false,false><<<dim3(MT/128, DIM2/64), 256>>>(input, fc1_w, fc1_b, x1, MT, DIM2, IN_DIM);
    // fc2: x1 @ [1024,512]^T
    gemm_mma<false,false><<<dim3(MT/128, HID/64), 256>>>(x1, fc2_w, fc2_b, x2, MT, HID, DIM2);
    // gi_all: x2 @ [3072,1024]^T + b_ih, output transposed to [t][b][3H]
    gemm_mma<false,true><<<dim3(MT/128, (3*HID)/64), 256>>>(x2, w_ih, b_ih, gi, MT, 3*HID, HID);

    copy_kernel<<<(B_SZ*HID + 255)/256, 256>>>(hn, h0, B_SZ*HID);

    float* bufs[2] = {h0, h1};
    for (int t = 0; t < T_SZ; t++) {
        gru_step_mma<<<dim3(B_SZ/64, HID/32), 256>>>(
            bufs[t & 1], bufs[(t + 1) & 1],
            gi + (size_t)t * B_SZ * (3*HID), w_hh, b_hh);
    }
    float* hfin = bufs[T_SZ & 1];

    int hn_off = out_size - B_SZ * HID;
    finalize_h<<<(B_SZ*HID + 255)/256, 256>>>(hfin, rh, outp + hn_off);

    // fc3 (relu epilogue): relu(h) @ [512,1024]^T
    gemm_mma<true,false><<<dim3(B_SZ/128, DIM2/64), 256>>>(rh, fc3_w, fc3_b, o3, B_SZ, DIM2, HID);

    heads_kernel<<<B_SZ, 128>>>(o3, cult, hw, hb, outp);
}

// round 3
// speedup vs baseline: 2.4203x; 1.5141x over previous
#include <cuda_runtime.h>
#include <cuda_fp16.h>
#include <math.h>

#define B_SZ 256
#define T_SZ 256
#define IN_DIM 64
#define HID 1024
#define DIM2 512
#define OUT_DIM 16
#define MT (B_SZ*T_SZ)   // 65536
#define G3 (3*HID)       // 3072

// ---------------- scratch (device globals) ---------------------------------
__device__ float g_gi[(size_t)MT*G3];                 // 805 MB, layout [t][b][3H]
__device__ float g_hf[2][B_SZ*HID];
__device__ float g_o3[B_SZ*DIM2];

__device__ __align__(128) half g_in_h[(size_t)MT*IN_DIM];
__device__ __align__(128) half g_in_l[(size_t)MT*IN_DIM];
__device__ __align__(128) half g_x1h[(size_t)MT*DIM2];
__device__ __align__(128) half g_x1l[(size_t)MT*DIM2];
__device__ __align__(128) half g_x2h[(size_t)MT*HID];
__device__ __align__(128) half g_x2l[(size_t)MT*HID];
__device__ __align__(128) half g_hh[2][B_SZ*HID];
__device__ __align__(128) half g_hl[2][B_SZ*HID];
__device__ __align__(128) half g_rhh[B_SZ*HID];
__device__ __align__(128) half g_rhl[B_SZ*HID];
__device__ __align__(128) half g_w1h[DIM2*IN_DIM];
__device__ __align__(128) half g_w1l[DIM2*IN_DIM];
__device__ __align__(128) half g_w2h[HID*DIM2];
__device__ __align__(128) half g_w2l[HID*DIM2];
__device__ __align__(128) half g_w3h[DIM2*HID];
__device__ __align__(128) half g_w3l[DIM2*HID];
__device__ __align__(128) half g_wihh[(size_t)G3*HID];
__device__ __align__(128) half g_wihl[(size_t)G3*HID];
__device__ __align__(128) half g_whhh[(size_t)G3*HID];
__device__ __align__(128) half g_whhl[(size_t)G3*HID];

// ---------------- helpers ---------------------------------------------------
#define CP16(s,g) asm volatile("cp.async.ca.shared.global [%0], [%1], 16;\n" :: "r"(s), "l"(g))
#define CPCOMMIT  asm volatile("cp.async.commit_group;\n")
#define CPWAIT(n) asm volatile("cp.async.wait_group %0;\n" :: "n"(n))

__device__ __forceinline__ unsigned saddr(const void* p) {
    return (unsigned)__cvta_generic_to_shared(p);
}
__device__ __forceinline__ void mma16(float* c, const unsigned* a, const unsigned* b) {
    asm volatile("mma.sync.aligned.m16n8k16.row.col.f32.f16.f16.f32 "
        "{%0,%1,%2,%3}, {%4,%5,%6,%7}, {%8,%9}, {%0,%1,%2,%3};"
        : "+f"(c[0]), "+f"(c[1]), "+f"(c[2]), "+f"(c[3])
        : "r"(a[0]), "r"(a[1]), "r"(a[2]), "r"(a[3]), "r"(b[0]), "r"(b[1]));
}
__device__ __forceinline__ void split2(float x, half& hi, half& lo) {
    hi = __float2half_rn(x);
    lo = __float2half_rn(x - __half2float(hi));
}

// ---------------- split kernels --------------------------------------------
__global__ void split_kernel(const float* __restrict__ s, half* __restrict__ hi,
                             half* __restrict__ lo, int n)
{
    int i = (blockIdx.x * blockDim.x + threadIdx.x) * 4;
    if (i >= n) return;
    float4 v = *(const float4*)(s + i);
    half h0, h1, h2, h3, l0, l1, l2, l3;
    split2(v.x, h0, l0); split2(v.y, h1, l1);
    split2(v.z, h2, l2); split2(v.w, h3, l3);
    *(half2*)(hi + i)     = __halves2half2(h0, h1);
    *(half2*)(hi + i + 2) = __halves2half2(h2, h3);
    *(half2*)(lo + i)     = __halves2half2(l0, l1);
    *(half2*)(lo + i + 2) = __halves2half2(l2, l3);
}

// h0 init: copy f32 + split planes
__global__ void split_h0(const float* __restrict__ s, float* __restrict__ f,
                         half* __restrict__ hi, half* __restrict__ lo)
{
    int i = (blockIdx.x * blockDim.x + threadIdx.x) * 4;
    float4 v = *(const float4*)(s + i);
    *(float4*)(f + i) = v;
    half h0, h1, h2, h3, l0, l1, l2, l3;
    split2(v.x, h0, l0); split2(v.y, h1, l1);
    split2(v.z, h2, l2); split2(v.w, h3, l3);
    *(half2*)(hi + i)     = __halves2half2(h0, h1);
    *(half2*)(hi + i + 2) = __halves2half2(h2, h3);
    *(half2*)(lo + i)     = __halves2half2(l0, l1);
    *(half2*)(lo + i + 2) = __halves2half2(l2, l3);
}

// ---------------- fp16x3 pipelined GEMM ------------------------------------
// C[M,N] = (Ah+Al)[M,K] @ (Wh+Wl)[N,K]^T + bias, 3-term HMMA, fp32 acc.
// BM=128, BN=128, BK=32, 256 thr, 8 warps (4m x 2n), warp tile 32x64.
// TRANS_OUT remaps row m=b*T+t -> t*B+b (for gi).
template<bool RELU, bool TRANS_OUT, bool WRITE_F32, bool WRITE_SPLIT>
__global__ __launch_bounds__(256)
void gemm_h3(const half* __restrict__ Ah, const half* __restrict__ Al,
             const half* __restrict__ Wh, const half* __restrict__ Wl,
             const float* __restrict__ bias, float* __restrict__ C,
             half* __restrict__ Chi, half* __restrict__ Clo,
             int M, int N, int K)
{
    __shared__ __align__(16) half sA[2][2][128*40];   // [stage][plane][row*40+k]
    __shared__ __align__(16) half sW[2][2][128*40];
    const int tid = threadIdx.x, wid = tid >> 5, lane = tid & 31;
    const int m0 = blockIdx.x * 128, n0 = blockIdx.y * 128;
    const int wm = wid & 3, wn = wid >> 2;
    const int KT = K >> 5;

    float acc[2][8][4] = {};

    const int lr = tid >> 2;          // row for load task tid
    const int lc = (tid & 3) * 8;     // halves offset within BK=32

    // prologue load stage 0
    {
        const int k0 = 0;
        #pragma unroll
        for (int p = 0; p < 2; p++) {
            const half* gA = p ? Al : Ah;
            const half* gW = p ? Wl : Wh;
            #pragma unroll
            for (int i = 0; i < 2; i++) {
                int r = lr + i * 64;
                CP16(saddr(&sA[0][p][r*40 + lc]), gA + (size_t)(m0 + r) * K + k0 + lc);
                CP16(saddr(&sW[0][p][r*40 + lc]), gW + (size_t)(n0 + r) * K + k0 + lc);
            }
        }
        CPCOMMIT;
    }

    for (int kt = 0; kt < KT; kt++) {
        const int cur = kt & 1;
        if (kt + 1 < KT) {
            const int nxt = cur ^ 1, k0 = (kt + 1) << 5;
            #pragma unroll
            for (int p = 0; p < 2; p++) {
                const half* gA = p ? Al : Ah;
                const half* gW = p ? Wl : Wh;
                #pragma unroll
                for (int i = 0; i < 2; i++) {
                    int r = lr + i * 64;
                    CP16(saddr(&sA[nxt][p][r*40 + lc]), gA + (size_t)(m0 + r) * K + k0 + lc);
                    CP16(saddr(&sW[nxt][p][r*40 + lc]), gW + (size_t)(n0 + r) * K + k0 + lc);
                }
            }
            CPCOMMIT;
            CPWAIT(1);
        } else {
            CPWAIT(0);
        }
        __syncthreads();

        const unsigned* uAh = (const unsigned*)sA[cur][0];
        const unsigned* uAl = (const unsigned*)sA[cur][1];
        const unsigned* uWh = (const unsigned*)sW[cur][0];
        const unsigned* uWl = (const unsigned*)sW[cur][1];

        #pragma unroll
        for (int kk = 0; kk < 2; kk++) {
            unsigned ah[2][4], al[2][4];
            #pragma unroll
            for (int mt = 0; mt < 2; mt++) {
                int base = (wm*32 + mt*16 + (lane>>2)) * 20 + kk*8 + (lane & 3);
                ah[mt][0] = uAh[base];       ah[mt][1] = uAh[base + 160];
                ah[mt][2] = uAh[base + 4];   ah[mt][3] = uAh[base + 164];
                al[mt][0] = uAl[base];       al[mt][1] = uAl[base + 160];
                al[mt][2] = uAl[base + 4];   al[mt][3] = uAl[base + 164];
            }
            #pragma unroll
            for (int nt = 0; nt < 8; nt++) {
                int wb = (wn*64 + nt*8 + (lane>>2)) * 20 + kk*8 + (lane & 3);
                unsigned bh[2] = { uWh[wb], uWh[wb + 4] };
                unsigned bl[2] = { uWl[wb], uWl[wb + 4] };
                #pragma unroll
                for (int mt = 0; mt < 2; mt++) {
                    mma16(acc[mt][nt], ah[mt], bh);
                    mma16(acc[mt][nt], ah[mt], bl);
                    mma16(acc[mt][nt], al[mt], bh);
                }
            }
        }
        __syncthreads();
    }

    #pragma unroll
    for (int mt = 0; mt < 2; mt++)
        #pragma unroll
        for (int nt = 0; nt < 8; nt++) {
            int n = n0 + wn*64 + nt*8 + (lane & 3) * 2;
            float bx = bias[n], by = bias[n + 1];
            #pragma unroll
            for (int h2 = 0; h2 < 2; h2++) {
                int m = m0 + wm*32 + mt*16 + (lane>>2) + h2*8;
                float vx = acc[mt][nt][h2*2+0] + bx;
                float vy = acc[mt][nt][h2*2+1] + by;
                if (RELU) { vx = fmaxf(vx, 0.f); vy = fmaxf(vy, 0.f); }
                size_t row = TRANS_OUT ? ((size_t)(m & (T_SZ-1)) * B_SZ + (m >> 8))
                                       : (size_t)m;
                if (WRITE_F32) {
                    float2 v; v.x = vx; v.y = vy;
                    *(float2*)(C + row * N + n) = v;
                }
                if (WRITE_SPLIT) {
                    half hx, lx, hy, ly;
                    split2(vx, hx, lx); split2(vy, hy, ly);
                    *(half2*)(Chi + row * N + n) = __halves2half2(hx, hy);
                    *(half2*)(Clo + row * N + n) = __halves2half2(lx, ly);
                }
            }
        }
}

// ---------------- fused fp16x3 GRU step ------------------------------------
// Grid (B/64=4, HID/32=32)=128 blocks, 256 thr (8 warps: 4m x 2j).
// gh = h @ w_hh^T for a 64m x (3x32)j tile, then gate math + state update.
__global__ __launch_bounds__(256)
void gru_step_h3(const float* __restrict__ hf_in,
                 const half* __restrict__ hh_in, const half* __restrict__ hl_in,
                 float* __restrict__ hf_out,
                 half* __restrict__ hh_out, half* __restrict__ hl_out,
                 const float* __restrict__ gi_t,
                 const half* __restrict__ wh, const half* __restrict__ wl,
                 const float* __restrict__ b_hh)
{
    __shared__ __align__(16) half sH[2][2][64*40];
    __shared__ __align__(16) half sW[2][2][96*40];
    const int tid = threadIdx.x, wid = tid >> 5, lane = tid & 31;
    const int m0 = blockIdx.x * 64, j0 = blockIdx.y * 32;
    const int wm = wid & 3, wj = wid >> 2;

    float acc[6][4] = {};   // [g*2+nt8][frag]

    const int hr_ = tid >> 2, hc_ = (tid & 3) * 8;     // H task (256 tasks)
    const int wr0 = tid >> 2, wr1 = (tid + 256) >> 2;  // W tasks (384/plane)
    const int wc_ = (tid & 3) * 8;

    // prologue
    {
        const int k0 = 0;
        #pragma unroll
        for (int p = 0; p < 2; p++) {
            const half* gH = p ? hl_in : hh_in;
            const half* gW = p ? wl : wh;
            CP16(saddr(&sH[0][p][hr_*40 + hc_]), gH + (size_t)(m0 + hr_) * HID + k0 + hc_);
            {
                int g = wr0 >> 5, jr = wr0 & 31;
                CP16(saddr(&sW[0][p][wr0*40 + wc_]),
                     gW + (size_t)(g * HID + j0 + jr) * HID + k0 + wc_);
            }
            if (wr1 < 96) {
                int g = wr1 >> 5, jr = wr1 & 31;
                CP16(saddr(&sW[0][p][wr1*40 + wc_]),
                     gW + (size_t)(g * HID + j0 + jr) * HID + k0 + wc_);
            }
        }
        CPCOMMIT;
    }

    #pragma unroll 1
    for (int kt = 0; kt < 32; kt++) {
        const int cur = kt & 1;
        if (kt + 1 < 32) {
            const int nxt = cur ^ 1, k0 = (kt + 1) << 5;
            #pragma unroll
            for (int p = 0; p < 2; p++) {
                const half* gH = p ? hl_in : hh_in;
                const half* gW = p ? wl : wh;
                CP16(saddr(&sH[nxt][p][hr_*40 + hc_]), gH + (size_t)(m0 + hr_) * HID + k0 + hc_);
                {
                    int g = wr0 >> 5, jr = wr0 & 31;
                    CP16(saddr(&sW[nxt][p][wr0*40 + wc_]),
                         gW + (size_t)(g * HID + j0 + jr) * HID + k0 + wc_);
                }
                if (wr1 < 96) {
                    int g = wr1 >> 5, jr = wr1 & 31;
                    CP16(saddr(&sW[nxt][p][wr1*40 + wc_]),
                         gW + (size_t)(g * HID + j0 + jr) * HID + k0 + wc_);
                }
            }
            CPCOMMIT;
            CPWAIT(1);
        } else {
            CPWAIT(0);
        }
        __syncthreads();

        const unsigned* uHh = (const unsigned*)sH[cur][0];
        const unsigned* uHl = (const unsigned*)sH[cur][1];
        const unsigned* uWh = (const unsigned*)sW[cur][0];
        const unsigned* uWl = (const unsigned*)sW[cur][1];

        #pragma unroll
        for (int kk = 0; kk < 2; kk++) {
            int abase = (wm*16 + (lane>>2)) * 20 + kk*8 + (lane & 3);
            unsigned ah[4] = { uHh[abase], uHh[abase+160], uHh[abase+4], uHh[abase+164] };
            unsigned al[4] = { uHl[abase], uHl[abase+160], uHl[abase+4], uHl[abase+164] };
            #pragma unroll
            for (int nt = 0; nt < 6; nt++) {
                int g = nt >> 1, nt8 = nt & 1;
                int wb = (g*32 + wj*16 + nt8*8 + (lane>>2)) * 20 + kk*8 + (lane & 3);
                unsigned bh[2] = { uWh[wb], uWh[wb + 4] };
                unsigned bl[2] = { uWl[wb], uWl[wb + 4] };
                mma16(acc[nt], ah, bh);
                mma16(acc[nt], ah, bl);
                mma16(acc[nt], al, bh);
            }
        }
        __syncthreads();
    }

    // gates + state update
    #pragma unroll
    for (int h2 = 0; h2 < 2; h2++) {
        int m = m0 + wm*16 + (lane>>2) + h2*8;
        const float* gp = gi_t + (size_t)m * G3;
        #pragma unroll
        for (int nt8 = 0; nt8 < 2; nt8++)
            #pragma unroll
            for (int c = 0; c < 2; c++) {
                int j = j0 + wj*16 + nt8*8 + (lane & 3) * 2 + c;
                float hr  = acc[0*2+nt8][h2*2+c] + b_hh[j];
                float hz  = acc[1*2+nt8][h2*2+c] + b_hh[HID + j];
                float hnn = acc[2*2+nt8][h2*2+c] + b_hh[2*HID + j];
                float r_ = 1.f / (1.f + expf(-(gp[j] + hr)));
                float z_ = 1.f / (1.f + expf(-(gp[HID + j] + hz)));
                float n_ = tanhf(gp[2*HID + j] + r_ * hnn);
                float hp = hf_in[(size_t)m * HID + j];
                float hnew = (1.f - z_) * n_ + z_ * hp;
                hf_out[(size_t)m * HID + j] = hnew;
                half hi, lo; split2(hnew, hi, lo);
                hh_out[(size_t)m * HID + j] = hi;
                hl_out[(size_t)m * HID + j] = lo;
            }
    }
}

// ---------------- tail kernels ---------------------------------------------
__global__ void finalize_h(const float* __restrict__ h, float* __restrict__ out_hn,
                           half* __restrict__ rhh, half* __restrict__ rhl)
{
    int i = (blockIdx.x * blockDim.x + threadIdx.x) * 4;
    float4 v = *(const float4*)(h + i);
    *(float4*)(out_hn + i) = v;
    float r0 = fmaxf(v.x, 0.f), r1 = fmaxf(v.y, 0.f);
    float r2 = fmaxf(v.z, 0.f), r3 = fmaxf(v.w, 0.f);
    half h0, h1, h2, h3, l0, l1, l2, l3;
    split2(r0, h0, l0); split2(r1, h1, l1);
    split2(r2, h2, l2); split2(r3, h3, l3);
    *(half2*)(rhh + i)     = __halves2half2(h0, h1);
    *(half2*)(rhh + i + 2) = __halves2half2(h2, h3);
    *(half2*)(rhl + i)     = __halves2half2(l0, l1);
    *(half2*)(rhl + i + 2) = __halves2half2(l2, l3);
}

__global__ __launch_bounds__(128)
void heads_kernel(const float* __restrict__ o3, const int* __restrict__ cult,
                  const float* __restrict__ hw, const float* __restrict__ hb,
                  float* __restrict__ outp)
{
    int b = blockIdx.x;
    int c = cult[b];
    __shared__ float sv[DIM2];
    for (int i = threadIdx.x; i < DIM2; i += blockDim.x)
        sv[i] = o3[(size_t)b * DIM2 + i];
    __syncthreads();
    int o = threadIdx.x >> 3, l = threadIdx.x & 7;
    const float* w = hw + ((size_t)c * OUT_DIM + o) * DIM2;
    float s = 0.f;
    for (int d = l; d < DIM2; d += 8) s += sv[d] * w[d];
    s += __shfl_down_sync(0xffffffffu, s, 4);
    s += __shfl_down_sync(0xffffffffu, s, 2);
    s += __shfl_down_sync(0xffffffffu, s, 1);
    if (l == 0) outp[b * OUT_DIM + o] = s + hb[c * OUT_DIM + o];
}

// ---------------- launch ---------------------------------------------------
extern "C" void kernel_launch(void* const* d_in, const int* in_sizes, int n_in,
                              void* d_out, int out_size)
{
    const float* input = (const float*)d_in[0];
    const float* hn    = (const float*)d_in[1];
    const int*   cult  = (const int*)  d_in[2];
    const float* fc1_w = (const float*)d_in[3];
    const float* fc1_b = (const float*)d_in[4];
    const float* fc2_w = (const float*)d_in[5];
    const float* fc2_b = (const float*)d_in[6];
    const float* w_ih  = (const float*)d_in[7];
    const float* w_hh  = (const float*)d_in[8];
    const float* b_ih  = (const float*)d_in[9];
    const float* b_hh  = (const float*)d_in[10];
    const float* fc3_w = (const float*)d_in[11];
    const float* fc3_b = (const float*)d_in[12];
    const float* hw    = (const float*)d_in[13];
    const float* hb    = (const float*)d_in[14];
    float* outp = (float*)d_out;

    float *gi, *o3; float *hf;
    half *inh, *inl, *x1h, *x1l, *x2h, *x2l, *hh, *hl, *rhh, *rhl;
    half *w1h, *w1l, *w2h, *w2l, *w3h, *w3l, *wihh, *wihl, *whhh, *whhl;
    cudaGetSymbolAddress((void**)&gi, g_gi);
    cudaGetSymbolAddress((void**)&o3, g_o3);
    cudaGetSymbolAddress((void**)&hf, g_hf);
    cudaGetSymbolAddress((void**)&inh, g_in_h);  cudaGetSymbolAddress((void**)&inl, g_in_l);
    cudaGetSymbolAddress((void**)&x1h, g_x1h);   cudaGetSymbolAddress((void**)&x1l, g_x1l);
    cudaGetSymbolAddress((void**)&x2h, g_x2h);   cudaGetSymbolAddress((void**)&x2l, g_x2l);
    cudaGetSymbolAddress((void**)&hh, g_hh);     cudaGetSymbolAddress((void**)&hl, g_hl);
    cudaGetSymbolAddress((void**)&rhh, g_rhh);   cudaGetSymbolAddress((void**)&rhl, g_rhl);
    cudaGetSymbolAddress((void**)&w1h, g_w1h);   cudaGetSymbolAddress((void**)&w1l, g_w1l);
    cudaGetSymbolAddress((void**)&w2h, g_w2h);   cudaGetSymbolAddress((void**)&w2l, g_w2l);
    cudaGetSymbolAddress((void**)&w3h, g_w3h);   cudaGetSymbolAddress((void**)&w3l, g_w3l);
    cudaGetSymbolAddress((void**)&wihh, g_wihh); cudaGetSymbolAddress((void**)&wihl, g_wihl);
    cudaGetSymbolAddress((void**)&whhh, g_whhh); cudaGetSymbolAddress((void**)&whhl, g_whhl);

    // splits
    split_kernel<<<MT*IN_DIM/1024, 256>>>(input, inh, inl, MT*IN_DIM);
    split_kernel<<<DIM2*IN_DIM/1024, 256>>>(fc1_w, w1h, w1l, DIM2*IN_DIM);
    split_kernel<<<HID*DIM2/1024, 256>>>(fc2_w, w2h, w2l, HID*DIM2);
    split_kernel<<<DIM2*HID/1024, 256>>>(fc3_w, w3h, w3l, DIM2*HID);
    split_kernel<<<G3*HID/1024, 256>>>(w_ih, wihh, wihl, G3*HID);
    split_kernel<<<G3*HID/1024, 256>>>(w_hh, whhh, whhl, G3*HID);

    // fc1: in @ fc1_w^T -> x1 planes
    gemm_h3<false,false,false,true><<<dim3(MT/128, DIM2/128), 256>>>(
        inh, inl, w1h, w1l, fc1_b, nullptr, x1h, x1l, MT, DIM2, IN_DIM);
    // fc2: x1 @ fc2_w^T -> x2 planes
    gemm_h3<false,false,false,true><<<dim3(MT/128, HID/128), 256>>>(
        x1h, x1l, w2h, w2l, fc2_b, nullptr, x2h, x2l, MT, HID, DIM2);
    // gi: x2 @ w_ih^T + b_ih -> f32 [t][b][3H]
    gemm_h3<false,true,true,false><<<dim3(MT/128, G3/128), 256>>>(
        x2h, x2l, wihh, wihl, b_ih, gi, nullptr, nullptr, MT, G3, HID);

    // h0
    split_h0<<<B_SZ*HID/1024, 256>>>(hn, hf, hh, hl);

    const size_t HS = (size_t)B_SZ * HID;
    for (int t = 0; t < T_SZ; t++) {
        int a = t & 1, b = (t + 1) & 1;
        gru_step_h3<<<dim3(B_SZ/64, HID/32), 256>>>(
            hf + a*HS, hh + a*HS, hl + a*HS,
            hf + b*HS, hh + b*HS, hl + b*HS,
            gi + (size_t)t * B_SZ * G3, whhh, whhl, b_hh);
    }
    float* hfin = hf + (T_SZ & 1) * HS;   // T even -> buffer 0

    int hn_off = out_size - B_SZ * HID;
    finalize_h<<<B_SZ*HID/1024, 256>>>(hfin, outp + hn_off, rhh, rhl);

    // fc3: relu(h) @ fc3_w^T, relu epilogue -> o3 f32
    gemm_h3<true,false,true,false><<<dim3(B_SZ/128, DIM2/128), 256>>>(
        rhh, rhl, w3h, w3l, fc3_b, o3, nullptr, nullptr, B_SZ, DIM2, HID);

    heads_kernel<<<B_SZ, 128>>>(o3, cult, hw, hb, outp);
}

// round 4
// speedup vs baseline: 2.5322x; 1.0462x over previous
#include <cuda_runtime.h>
#include <cuda_fp16.h>
#include <math.h>

#define B_SZ 256
#define T_SZ 256
#define IN_DIM 64
#define HID 1024
#define DIM2 512
#define OUT_DIM 16
#define MT (B_SZ*T_SZ)   // 65536
#define G3 (3*HID)       // 3072

// ---------------- scratch (device globals) ---------------------------------
__device__ float g_gi[(size_t)MT*G3];                 // 805 MB, layout [t][b][3H]
__device__ float g_hf[2][B_SZ*HID];
__device__ float g_o3[B_SZ*DIM2];

__device__ __align__(128) half g_in_h[(size_t)MT*IN_DIM];
__device__ __align__(128) half g_in_l[(size_t)MT*IN_DIM];
__device__ __align__(128) half g_x1h[(size_t)MT*DIM2];
__device__ __align__(128) half g_x1l[(size_t)MT*DIM2];
__device__ __align__(128) half g_x2h[(size_t)MT*HID];
__device__ __align__(128) half g_x2l[(size_t)MT*HID];
__device__ __align__(128) half g_hh[2][B_SZ*HID];
__device__ __align__(128) half g_hl[2][B_SZ*HID];
__device__ __align__(128) half g_rhh[B_SZ*HID];
__device__ __align__(128) half g_rhl[B_SZ*HID];
__device__ __align__(128) half g_w1h[DIM2*IN_DIM];
__device__ __align__(128) half g_w1l[DIM2*IN_DIM];
__device__ __align__(128) half g_w2h[HID*DIM2];
__device__ __align__(128) half g_w2l[HID*DIM2];
__device__ __align__(128) half g_w3h[DIM2*HID];
__device__ __align__(128) half g_w3l[DIM2*HID];
__device__ __align__(128) half g_wihh[(size_t)G3*HID];
__device__ __align__(128) half g_wihl[(size_t)G3*HID];
__device__ __align__(128) half g_whhh[(size_t)G3*HID];
__device__ __align__(128) half g_whhl[(size_t)G3*HID];

// ---------------- helpers ---------------------------------------------------
#define CP16(s,g) asm volatile("cp.async.ca.shared.global [%0], [%1], 16;\n" :: "r"(s), "l"(g))
#define CPCOMMIT  asm volatile("cp.async.commit_group;\n")
#define CPWAIT(n) asm volatile("cp.async.wait_group %0;\n" :: "n"(n))

__device__ __forceinline__ unsigned saddr(const void* p) {
    return (unsigned)__cvta_generic_to_shared(p);
}
__device__ __forceinline__ void mma16(float* c, const unsigned* a, const unsigned* b) {
    asm volatile("mma.sync.aligned.m16n8k16.row.col.f32.f16.f16.f32 "
        "{%0,%1,%2,%3}, {%4,%5,%6,%7}, {%8,%9}, {%0,%1,%2,%3};"
        : "+f"(c[0]), "+f"(c[1]), "+f"(c[2]), "+f"(c[3])
        : "r"(a[0]), "r"(a[1]), "r"(a[2]), "r"(a[3]), "r"(b[0]), "r"(b[1]));
}
__device__ __forceinline__ void ldsm4(unsigned* r, unsigned addr) {
    asm volatile("ldmatrix.sync.aligned.m8n8.x4.shared.b16 {%0,%1,%2,%3}, [%4];"
        : "=r"(r[0]), "=r"(r[1]), "=r"(r[2]), "=r"(r[3]) : "r"(addr));
}
__device__ __forceinline__ void split2(float x, half& hi, half& lo) {
    hi = __float2half_rn(x);
    lo = __float2half_rn(x - __half2float(hi));
}

// ---------------- split kernels --------------------------------------------
__global__ void split_kernel(const float* __restrict__ s, half* __restrict__ hi,
                             half* __restrict__ lo, int n)
{
    int i = (blockIdx.x * blockDim.x + threadIdx.x) * 4;
    if (i >= n) return;
    float4 v = *(const float4*)(s + i);
    half h0, h1, h2, h3, l0, l1, l2, l3;
    split2(v.x, h0, l0); split2(v.y, h1, l1);
    split2(v.z, h2, l2); split2(v.w, h3, l3);
    *(half2*)(hi + i)     = __halves2half2(h0, h1);
    *(half2*)(hi + i + 2) = __halves2half2(h2, h3);
    *(half2*)(lo + i)     = __halves2half2(l0, l1);
    *(half2*)(lo + i + 2) = __halves2half2(l2, l3);
}

__global__ void split_h0(const float* __restrict__ s, float* __restrict__ f,
                         half* __restrict__ hi, half* __restrict__ lo)
{
    int i = (blockIdx.x * blockDim.x + threadIdx.x) * 4;
    float4 v = *(const float4*)(s + i);
    *(float4*)(f + i) = v;
    half h0, h1, h2, h3, l0, l1, l2, l3;
    split2(v.x, h0, l0); split2(v.y, h1, l1);
    split2(v.z, h2, l2); split2(v.w, h3, l3);
    *(half2*)(hi + i)     = __halves2half2(h0, h1);
    *(half2*)(hi + i + 2) = __halves2half2(h2, h3);
    *(half2*)(lo + i)     = __halves2half2(l0, l1);
    *(half2*)(lo + i + 2) = __halves2half2(l2, l3);
}

// ---------------- fp16x3 GEMM, 3-stage cp.async + ldmatrix -----------------
// C[M,N] = (Ah+Al)[M,K] @ (Wh+Wl)[N,K]^T + bias, 3-term HMMA, fp32 acc.
// BM=128, BN=128, BK=32, 256 thr (8 warps: 4m x 2n), warp tile 32x64.
// Grid: (N/128, M/128) — x = n-tile (fast) so concurrent blocks share A in L2.
template<bool RELU, bool TRANS_OUT, bool WRITE_F32, bool WRITE_SPLIT>
__global__ __launch_bounds__(256)
void gemm_h3(const half* __restrict__ Ah, const half* __restrict__ Al,
             const half* __restrict__ Wh, const half* __restrict__ Wl,
             const float* __restrict__ bias, float* __restrict__ C,
             half* __restrict__ Chi, half* __restrict__ Clo,
             int M, int N, int K)
{
    __shared__ __align__(16) half sA[3][2][128*40];   // [stage][plane]
    __shared__ __align__(16) half sW[3][2][128*40];
    const int tid = threadIdx.x, wid = tid >> 5, lane = tid & 31;
    const int m0 = blockIdx.y * 128, n0 = blockIdx.x * 128;
    const int wm = wid & 3, wn = wid >> 2;
    const int KT = K >> 5;

    float acc[2][8][4] = {};

    const int lr = tid >> 2, lc = (tid & 3) * 8;
    const half* gAp[2] = {Ah, Al};
    const half* gWp[2] = {Wh, Wl};

    auto load_stage = [&](int s, int k0) {
        #pragma unroll
        for (int p = 0; p < 2; p++) {
            const half* gA = gAp[p];
            const half* gW = gWp[p];
            #pragma unroll
            for (int i = 0; i < 2; i++) {
                int r = lr + i * 64;
                CP16(saddr(&sA[s][p][r*40 + lc]), gA + (size_t)(m0 + r) * K + k0 + lc);
                CP16(saddr(&sW[s][p][r*40 + lc]), gW + (size_t)(n0 + r) * K + k0 + lc);
            }
        }
    };

    // ldmatrix byte offsets within a stage-plane (row stride 80 B)
    const unsigned aOff = (unsigned)((wm*32 + (lane & 15)) * 80 + ((lane >> 4) & 1) * 16);
    const unsigned bOff = (unsigned)((wn*64 + (lane & 7) + ((lane >> 4) & 1) * 8) * 80
                                     + ((lane >> 3) & 1) * 16);

    // prologue: stages 0,1
    #pragma unroll
    for (int s = 0; s < 2; s++) { if (s < KT) load_stage(s, s * 32); CPCOMMIT; }

    for (int kt = 0; kt < KT; kt++) {
        CPWAIT(1);
        __syncthreads();
        {
            int ks = kt + 2;
            if (ks < KT) load_stage(ks % 3, ks * 32);
            CPCOMMIT;
        }
        const int cur = kt % 3;
        const unsigned baseAh = saddr(&sA[cur][0][0]);
        const unsigned baseAl = saddr(&sA[cur][1][0]);
        const unsigned baseWh = saddr(&sW[cur][0][0]);
        const unsigned baseWl = saddr(&sW[cur][1][0]);

        #pragma unroll
        for (int kk = 0; kk < 2; kk++) {
            unsigned ah[2][4], al[2][4];
            #pragma unroll
            for (int mt = 0; mt < 2; mt++) {
                unsigned off = aOff + mt * (16*80) + kk * 32;
                ldsm4(ah[mt], baseAh + off);
                ldsm4(al[mt], baseAl + off);
            }
            #pragma unroll
            for (int p = 0; p < 4; p++) {
                unsigned off = bOff + p * (16*80) + kk * 32;
                unsigned bh[4], bl[4];
                ldsm4(bh, baseWh + off);
                ldsm4(bl, baseWl + off);
                #pragma unroll
                for (int t2 = 0; t2 < 2; t2++) {
                    int nt = p * 2 + t2;
                    #pragma unroll
                    for (int mt = 0; mt < 2; mt++) {
                        mma16(acc[mt][nt], ah[mt], bh + t2*2);
                        mma16(acc[mt][nt], ah[mt], bl + t2*2);
                        mma16(acc[mt][nt], al[mt], bh + t2*2);
                    }
                }
            }
        }
    }

    #pragma unroll
    for (int mt = 0; mt < 2; mt++)
        #pragma unroll
        for (int nt = 0; nt < 8; nt++) {
            int n = n0 + wn*64 + nt*8 + (lane & 3) * 2;
            float bx = bias[n], by = bias[n + 1];
            #pragma unroll
            for (int h2 = 0; h2 < 2; h2++) {
                int m = m0 + wm*32 + mt*16 + (lane >> 2) + h2*8;
                float vx = acc[mt][nt][h2*2+0] + bx;
                float vy = acc[mt][nt][h2*2+1] + by;
                if (RELU) { vx = fmaxf(vx, 0.f); vy = fmaxf(vy, 0.f); }
                size_t row = TRANS_OUT ? ((size_t)(m & (T_SZ-1)) * B_SZ + (m >> 8))
                                       : (size_t)m;
                if (WRITE_F32) {
                    float2 v; v.x = vx; v.y = vy;
                    *(float2*)(C + row * N + n) = v;
                }
                if (WRITE_SPLIT) {
                    half hx, lx, hy, ly;
                    split2(vx, hx, lx); split2(vy, hy, ly);
                    *(half2*)(Chi + row * N + n) = __halves2half2(hx, hy);
                    *(half2*)(Clo + row * N + n) = __halves2half2(lx, ly);
                }
            }
        }
}

// ---------------- fused fp16x3 GRU step (ldmatrix + 3-stage) ----------------
// Grid (B/64=4, HID/32=32)=128 blocks, 256 thr (8 warps: 4m x 2j).
__global__ __launch_bounds__(256)
void gru_step_h3(const float* __restrict__ hf_in,
                 const half* __restrict__ hh_in, const half* __restrict__ hl_in,
                 float* __restrict__ hf_out,
                 half* __restrict__ hh_out, half* __restrict__ hl_out,
                 const float* __restrict__ gi_t,
                 const half* __restrict__ wh, const half* __restrict__ wl,
                 const float* __restrict__ b_hh)
{
    __shared__ __align__(16) half sH[3][2][64*40];
    __shared__ __align__(16) half sW[3][2][96*40];
    const int tid = threadIdx.x, wid = tid >> 5, lane = tid & 31;
    const int m0 = blockIdx.x * 64, j0 = blockIdx.y * 32;
    const int wm = wid & 3, wj = wid >> 2;

    float acc[6][4] = {};   // [g*2+t2][frag]

    const int lr = tid >> 2, lc = (tid & 3) * 8;

    auto load_stage = [&](int s, int k0) {
        #pragma unroll
        for (int p = 0; p < 2; p++) {
            const half* gH = p ? hl_in : hh_in;
            const half* gW = p ? wl : wh;
            CP16(saddr(&sH[s][p][lr*40 + lc]), gH + (size_t)(m0 + lr) * HID + k0 + lc);
            {
                int g = lr >> 5, jr = lr & 31;
                CP16(saddr(&sW[s][p][lr*40 + lc]),
                     gW + (size_t)(g * HID + j0 + jr) * HID + k0 + lc);
            }
            int r1 = lr + 64;
            if (r1 < 96) {
                int g = r1 >> 5, jr = r1 & 31;
                CP16(saddr(&sW[s][p][r1*40 + lc]),
                     gW + (size_t)(g * HID + j0 + jr) * HID + k0 + lc);
            }
        }
    };

    const unsigned aOff = (unsigned)((wm*16 + (lane & 15)) * 80 + ((lane >> 4) & 1) * 16);
    const unsigned bOff = (unsigned)((wj*16 + (lane & 7) + ((lane >> 4) & 1) * 8) * 80
                                     + ((lane >> 3) & 1) * 16);

    #pragma unroll
    for (int s = 0; s < 2; s++) { load_stage(s, s * 32); CPCOMMIT; }

    #pragma unroll 1
    for (int kt = 0; kt < 32; kt++) {
        CPWAIT(1);
        __syncthreads();
        {
            int ks = kt + 2;
            if (ks < 32) load_stage(ks % 3, ks * 32);
            CPCOMMIT;
        }
        const int cur = kt % 3;
        const unsigned baseHh = saddr(&sH[cur][0][0]);
        const unsigned baseHl = saddr(&sH[cur][1][0]);
        const unsigned baseWh = saddr(&sW[cur][0][0]);
        const unsigned baseWl = saddr(&sW[cur][1][0]);

        #pragma unroll
        for (int kk = 0; kk < 2; kk++) {
            unsigned ah[4], al[4];
            ldsm4(ah, baseHh + aOff + kk * 32);
            ldsm4(al, baseHl + aOff + kk * 32);
            #pragma unroll
            for (int g = 0; g < 3; g++) {
                unsigned off = bOff + g * (32*80) + kk * 32;
                unsigned bh[4], bl[4];
                ldsm4(bh, baseWh + off);
                ldsm4(bl, baseWl + off);
                #pragma unroll
                for (int t2 = 0; t2 < 2; t2++) {
                    int nt = g * 2 + t2;
                    mma16(acc[nt], ah, bh + t2*2);
                    mma16(acc[nt], ah, bl + t2*2);
                    mma16(acc[nt], al, bh + t2*2);
                }
            }
        }
    }

    // gates + state update
    #pragma unroll
    for (int h2 = 0; h2 < 2; h2++) {
        int m = m0 + wm*16 + (lane >> 2) + h2*8;
        const float* gp = gi_t + (size_t)m * G3;
        #pragma unroll
        for (int t2 = 0; t2 < 2; t2++)
            #pragma unroll
            for (int c = 0; c < 2; c++) {
                int j = j0 + wj*16 + t2*8 + (lane & 3) * 2 + c;
                float hr  = acc[0*2+t2][h2*2+c] + b_hh[j];
                float hz  = acc[1*2+t2][h2*2+c] + b_hh[HID + j];
                float hnn = acc[2*2+t2][h2*2+c] + b_hh[2*HID + j];
                float r_ = 1.f / (1.f + expf(-(gp[j] + hr)));
                float z_ = 1.f / (1.f + expf(-(gp[HID + j] + hz)));
                float n_ = tanhf(gp[2*HID + j] + r_ * hnn);
                float hp = hf_in[(size_t)m * HID + j];
                float hnew = (1.f - z_) * n_ + z_ * hp;
                hf_out[(size_t)m * HID + j] = hnew;
                half hi, lo; split2(hnew, hi, lo);
                hh_out[(size_t)m * HID + j] = hi;
                hl_out[(size_t)m * HID + j] = lo;
            }
    }
}

// ---------------- tail kernels ---------------------------------------------
__global__ void finalize_h(const float* __restrict__ h, float* __restrict__ out_hn,
                           half* __restrict__ rhh, half* __restrict__ rhl)
{
    int i = (blockIdx.x * blockDim.x + threadIdx.x) * 4;
    float4 v = *(const float4*)(h + i);
    *(float4*)(out_hn + i) = v;
    float r0 = fmaxf(v.x, 0.f), r1 = fmaxf(v.y, 0.f);
    float r2 = fmaxf(v.z, 0.f), r3 = fmaxf(v.w, 0.f);
    half h0, h1, h2, h3, l0, l1, l2, l3;
    split2(r0, h0, l0); split2(r1, h1, l1);
    split2(r2, h2, l2); split2(r3, h3, l3);
    *(half2*)(rhh + i)     = __halves2half2(h0, h1);
    *(half2*)(rhh + i + 2) = __halves2half2(h2, h3);
    *(half2*)(rhl + i)     = __halves2half2(l0, l1);
    *(half2*)(rhl + i + 2) = __halves2half2(l2, l3);
}

__global__ __launch_bounds__(128)
void heads_kernel(const float* __restrict__ o3, const int* __restrict__ cult,
                  const float* __restrict__ hw, const float* __restrict__ hb,
                  float* __restrict__ outp)
{
    int b = blockIdx.x;
    int c = cult[b];
    __shared__ float sv[DIM2];
    for (int i = threadIdx.x; i < DIM2; i += blockDim.x)
        sv[i] = o3[(size_t)b * DIM2 + i];
    __syncthreads();
    int o = threadIdx.x >> 3, l = threadIdx.x & 7;
    const float* w = hw + ((size_t)c * OUT_DIM + o) * DIM2;
    float s = 0.f;
    for (int d = l; d < DIM2; d += 8) s += sv[d] * w[d];
    s += __shfl_down_sync(0xffffffffu, s, 4);
    s += __shfl_down_sync(0xffffffffu, s, 2);
    s += __shfl_down_sync(0xffffffffu, s, 1);
    if (l == 0) outp[b * OUT_DIM + o] = s + hb[c * OUT_DIM + o];
}

// ---------------- launch ---------------------------------------------------
extern "C" void kernel_launch(void* const* d_in, const int* in_sizes, int n_in,
                              void* d_out, int out_size)
{
    const float* input = (const float*)d_in[0];
    const float* hn    = (const float*)d_in[1];
    const int*   cult  = (const int*)  d_in[2];
    const float* fc1_w = (const float*)d_in[3];
    const float* fc1_b = (const float*)d_in[4];
    const float* fc2_w = (const float*)d_in[5];
    const float* fc2_b = (const float*)d_in[6];
    const float* w_ih  = (const float*)d_in[7];
    const float* w_hh  = (const float*)d_in[8];
    const float* b_ih  = (const float*)d_in[9];
    const float* b_hh  = (const float*)d_in[10];
    const float* fc3_w = (const float*)d_in[11];
    const float* fc3_b = (const float*)d_in[12];
    const float* hw    = (const float*)d_in[13];
    const float* hb    = (const float*)d_in[14];
    float* outp = (float*)d_out;

    float *gi, *o3, *hf;
    half *inh, *inl, *x1h, *x1l, *x2h, *x2l, *hh, *hl, *rhh, *rhl;
    half *w1h, *w1l, *w2h, *w2l, *w3h, *w3l, *wihh, *wihl, *whhh, *whhl;
    cudaGetSymbolAddress((void**)&gi, g_gi);
    cudaGetSymbolAddress((void**)&o3, g_o3);
    cudaGetSymbolAddress((void**)&hf, g_hf);
    cudaGetSymbolAddress((void**)&inh, g_in_h);  cudaGetSymbolAddress((void**)&inl, g_in_l);
    cudaGetSymbolAddress((void**)&x1h, g_x1h);   cudaGetSymbolAddress((void**)&x1l, g_x1l);
    cudaGetSymbolAddress((void**)&x2h, g_x2h);   cudaGetSymbolAddress((void**)&x2l, g_x2l);
    cudaGetSymbolAddress((void**)&hh, g_hh);     cudaGetSymbolAddress((void**)&hl, g_hl);
    cudaGetSymbolAddress((void**)&rhh, g_rhh);   cudaGetSymbolAddress((void**)&rhl, g_rhl);
    cudaGetSymbolAddress((void**)&w1h, g_w1h);   cudaGetSymbolAddress((void**)&w1l, g_w1l);
    cudaGetSymbolAddress((void**)&w2h, g_w2h);   cudaGetSymbolAddress((void**)&w2l, g_w2l);
    cudaGetSymbolAddress((void**)&w3h, g_w3h);   cudaGetSymbolAddress((void**)&w3l, g_w3l);
    cudaGetSymbolAddress((void**)&wihh, g_wihh); cudaGetSymbolAddress((void**)&wihl, g_wihl);
    cudaGetSymbolAddress((void**)&whhh, g_whhh); cudaGetSymbolAddress((void**)&whhl, g_whhl);

    // splits
    split_kernel<<<MT*IN_DIM/1024, 256>>>(input, inh, inl, MT*IN_DIM);
    split_kernel<<<DIM2*IN_DIM/1024, 256>>>(fc1_w, w1h, w1l, DIM2*IN_DIM);
    split_kernel<<<HID*DIM2/1024, 256>>>(fc2_w, w2h, w2l, HID*DIM2);
    split_kernel<<<DIM2*HID/1024, 256>>>(fc3_w, w3h, w3l, DIM2*HID);
    split_kernel<<<G3*HID/1024, 256>>>(w_ih, wihh, wihl, G3*HID);
    split_kernel<<<G3*HID/1024, 256>>>(w_hh, whhh, whhl, G3*HID);

    // fc1: in @ fc1_w^T -> x1 planes       grid (N/128, M/128)
    gemm_h3<false,false,false,true><<<dim3(DIM2/128, MT/128), 256>>>(
        inh, inl, w1h, w1l, fc1_b, nullptr, x1h, x1l, MT, DIM2, IN_DIM);
    // fc2: x1 @ fc2_w^T -> x2 planes
    gemm_h3<false,false,false,true><<<dim3(HID/128, MT/128), 256>>>(
        x1h, x1l, w2h, w2l, fc2_b, nullptr, x2h, x2l, MT, HID, DIM2);
    // gi: x2 @ w_ih^T + b_ih -> f32 [t][b][3H]
    gemm_h3<false,true,true,false><<<dim3(G3/128, MT/128), 256>>>(
        x2h, x2l, wihh, wihl, b_ih, gi, nullptr, nullptr, MT, G3, HID);

    split_h0<<<B_SZ*HID/1024, 256>>>(hn, hf, hh, hl);

    const size_t HS = (size_t)B_SZ * HID;
    for (int t = 0; t < T_SZ; t++) {
        int a = t & 1, b = (t + 1) & 1;
        gru_step_h3<<<dim3(B_SZ/64, HID/32), 256>>>(
            hf + a*HS, hh + a*HS, hl + a*HS,
            hf + b*HS, hh + b*HS, hl + b*HS,
            gi + (size_t)t * B_SZ * G3, whhh, whhl, b_hh);
    }
    float* hfin = hf + (T_SZ & 1) * HS;

    int hn_off = out_size - B_SZ * HID;
    finalize_h<<<B_SZ*HID/1024, 256>>>(hfin, outp + hn_off, rhh, rhl);

    // fc3: relu(h) @ fc3_w^T, relu epilogue
    gemm_h3<true,false,true,false><<<dim3(DIM2/128, B_SZ/128), 256>>>(
        rhh, rhl, w3h, w3l, fc3_b, o3, nullptr, nullptr, B_SZ, DIM2, HID);

    heads_kernel<<<B_SZ, 128>>>(o3, cult, hw, hb, outp);
}

// round 5
// speedup vs baseline: 3.4898x; 1.3782x over previous
#include <cuda_runtime.h>
#include <cuda_fp16.h>
#include <math.h>

#define B_SZ 256
#define T_SZ 256
#define IN_DIM 64
#define HID 1024
#define DIM2 512
#define OUT_DIM 16
#define MT (B_SZ*T_SZ)   // 65536
#define G3 (3*HID)       // 3072

// ======================= tiled global scratch ==============================
// GEMM operand tiles: [tile(128 rows)][stage(k/32)][plane(2)][128][40] halves
//   stage chunk = 2*128*40 = 10240 halves = 20480 B (both planes, contiguous)
// GRU W tiles:  [jtile(32)][stage(32)][plane(2)][96][40]  -> 7680 halves/stage
// GRU H tiles:  [mtile(4)][stage(32)][plane(2)][64][40]   -> 5120 halves/stage
__device__ float g_gi[(size_t)MT*G3];                 // 805 MB [t][b][3H]
__device__ float g_hf[2][B_SZ*HID];
__device__ float g_o3[B_SZ*DIM2];

__device__ __align__(128) half g_int [(size_t)512*2*10240];    // input tiled (K=64)
__device__ __align__(128) half g_x1t [(size_t)512*16*10240];   // x1 tiled (K=512)
__device__ __align__(128) half g_x2t [(size_t)512*32*10240];   // x2 tiled (K=1024)
__device__ __align__(128) half g_rht [(size_t)2*32*10240];     // relu(h) tiled
__device__ __align__(128) half g_w1t [(size_t)4*2*10240];
__device__ __align__(128) half g_w2t [(size_t)8*16*10240];
__device__ __align__(128) half g_w3t [(size_t)4*32*10240];
__device__ __align__(128) half g_wiht[(size_t)24*32*10240];
__device__ __align__(128) half g_whht[(size_t)32*32*7680];     // GRU-geom w_hh
__device__ __align__(128) half g_ht  [2][(size_t)4*32*5120];   // GRU-geom h ping-pong
// dummy-profile sinks
__device__ float g_dummy_hf[B_SZ*HID];
__device__ __align__(128) half g_dummy_ht[(size_t)4*32*5120];

// ======================= PTX helpers =======================================
__device__ __forceinline__ unsigned saddr(const void* p) {
    return (unsigned)__cvta_generic_to_shared(p);
}
#define MBAR_INIT(mb, cnt) \
    asm volatile("mbarrier.init.shared.b64 [%0], %1;" :: "r"(mb), "r"(cnt) : "memory")
#define EXPECT_TX(mb, bytes) \
    asm volatile("mbarrier.arrive.expect_tx.shared.b64 _, [%0], %1;" :: "r"(mb), "r"(bytes) : "memory")
#define BULK_G2S(dst, src, bytes, mb) \
    asm volatile("cp.async.bulk.shared::cluster.global.mbarrier::complete_tx::bytes [%0], [%1], %2, [%3];" \
        :: "r"(dst), "l"(src), "r"(bytes), "r"(mb) : "memory")
#define MBWAIT(mb, ph) do { unsigned _d = 0; while (!_d) { \
    asm volatile("{\n\t.reg .pred p;\n\t" \
        "mbarrier.try_wait.parity.acquire.cta.shared::cta.b64 p, [%1], %2, 0x989680;\n\t" \
        "selp.b32 %0, 1, 0, p;\n\t}" \
        : "=r"(_d) : "r"(mb), "r"(ph)); } } while (0)

__device__ __forceinline__ void mma16(float* c, const unsigned* a, const unsigned* b) {
    asm volatile("mma.sync.aligned.m16n8k16.row.col.f32.f16.f16.f32 "
        "{%0,%1,%2,%3}, {%4,%5,%6,%7}, {%8,%9}, {%0,%1,%2,%3};"
        : "+f"(c[0]), "+f"(c[1]), "+f"(c[2]), "+f"(c[3])
        : "r"(a[0]), "r"(a[1]), "r"(a[2]), "r"(a[3]), "r"(b[0]), "r"(b[1]));
}
__device__ __forceinline__ void ldsm4(unsigned* r, unsigned addr) {
    asm volatile("ldmatrix.sync.aligned.m8n8.x4.shared.b16 {%0,%1,%2,%3}, [%4];"
        : "=r"(r[0]), "=r"(r[1]), "=r"(r[2]), "=r"(r[3]) : "r"(addr));
}
__device__ __forceinline__ void split2(float x, half& hi, half& lo) {
    hi = __float2half_rn(x);
    lo = __float2half_rn(x - __half2float(hi));
}

// ======================= split / re-layout kernels =========================
// GEMM-A/W geometry: 128-row tiles, row r, col c
__global__ void split_tiled(const float* __restrict__ s, half* __restrict__ dst,
                            int K, int n)
{
    int i = (blockIdx.x * blockDim.x + threadIdx.x) * 4;
    if (i >= n) return;
    int r = i / K, c = i % K;
    float4 v = *(const float4*)(s + i);
    half h[4], l[4];
    split2(v.x, h[0], l[0]); split2(v.y, h[1], l[1]);
    split2(v.z, h[2], l[2]); split2(v.w, h[3], l[3]);
    size_t base = (((size_t)(r >> 7) * (K >> 5) + (c >> 5)) * 2) * 5120
                + (size_t)(r & 127) * 40 + (c & 31);
    *(half2*)(dst + base)        = __halves2half2(h[0], h[1]);
    *(half2*)(dst + base + 2)    = __halves2half2(h[2], h[3]);
    *(half2*)(dst + base + 5120) = __halves2half2(l[0], l[1]);
    *(half2*)(dst + base + 5122) = __halves2half2(l[2], l[3]);
}

// w_hh -> GRU geometry (96-row tiles: g*32+jr)
__global__ void split_whh_t(const float* __restrict__ s, half* __restrict__ dst)
{
    int i = (blockIdx.x * blockDim.x + threadIdx.x) * 4;   // < 3072*1024
    int rw = i >> 10, c = i & 1023;
    int g = rw >> 10, j = rw & 1023;
    float4 v = *(const float4*)(s + i);
    half h[4], l[4];
    split2(v.x, h[0], l[0]); split2(v.y, h[1], l[1]);
    split2(v.z, h[2], l[2]); split2(v.w, h[3], l[3]);
    size_t base = (((size_t)(j >> 5) * 32 + (c >> 5)) * 2) * 3840
                + (size_t)(g * 32 + (j & 31)) * 40 + (c & 31);
    *(half2*)(dst + base)        = __halves2half2(h[0], h[1]);
    *(half2*)(dst + base + 2)    = __halves2half2(h[2], h[3]);
    *(half2*)(dst + base + 3840) = __halves2half2(l[0], l[1]);
    *(half2*)(dst + base + 3842) = __halves2half2(l[2], l[3]);
}

// h0 -> f32 buffer + GRU-geom tiled planes (64-row tiles)
__global__ void split_h0_t(const float* __restrict__ s, float* __restrict__ f,
                           half* __restrict__ dst)
{
    int i = (blockIdx.x * blockDim.x + threadIdx.x) * 4;   // < 256*1024
    int r = i >> 10, c = i & 1023;
    float4 v = *(const float4*)(s + i);
    *(float4*)(f + i) = v;
    half h[4], l[4];
    split2(v.x, h[0], l[0]); split2(v.y, h[1], l[1]);
    split2(v.z, h[2], l[2]); split2(v.w, h[3], l[3]);
    size_t base = (((size_t)(r >> 6) * 32 + (c >> 5)) * 2) * 2560
                + (size_t)(r & 63) * 40 + (c & 31);
    *(half2*)(dst + base)        = __halves2half2(h[0], h[1]);
    *(half2*)(dst + base + 2)    = __halves2half2(h[2], h[3]);
    *(half2*)(dst + base + 2560) = __halves2half2(l[0], l[1]);
    *(half2*)(dst + base + 2562) = __halves2half2(l[2], l[3]);
}

// final h -> hn_out f32 + relu(h) tiled (GEMM-A geometry for fc3)
__global__ void finalize_h(const float* __restrict__ hsrc, float* __restrict__ out_hn,
                           half* __restrict__ rht)
{
    int i = (blockIdx.x * blockDim.x + threadIdx.x) * 4;
    int r = i >> 10, c = i & 1023;
    float4 v = *(const float4*)(hsrc + i);
    *(float4*)(out_hn + i) = v;
    float rv[4] = { fmaxf(v.x,0.f), fmaxf(v.y,0.f), fmaxf(v.z,0.f), fmaxf(v.w,0.f) };
    half h[4], l[4];
    #pragma unroll
    for (int k = 0; k < 4; k++) split2(rv[k], h[k], l[k]);
    size_t base = (((size_t)(r >> 7) * 32 + (c >> 5)) * 2) * 5120
                + (size_t)(r & 127) * 40 + (c & 31);
    *(half2*)(rht + base)        = __halves2half2(h[0], h[1]);
    *(half2*)(rht + base + 2)    = __halves2half2(h[2], h[3]);
    *(half2*)(rht + base + 5120) = __halves2half2(l[0], l[1]);
    *(half2*)(rht + base + 5122) = __halves2half2(l[2], l[3]);
}

// ======================= bulk-pipelined fp16x3 GEMM ========================
// C[M,N] = (Ah+Al) @ (Wh+Wl)^T + bias. BM=BN=128, BK=32, 256 thr, 3-stage.
// Operands pre-tiled; one 20480B bulk copy per operand per stage.
template<bool RELU, bool TRANS_OUT, bool WRITE_F32, bool WRITE_SPLIT>
__global__ __launch_bounds__(256)
void gemm_h3b(const half* __restrict__ At, const half* __restrict__ Wt,
              const float* __restrict__ bias, float* __restrict__ C,
              half* __restrict__ Ct, int N, int KT)
{
    extern __shared__ __align__(16) half smem[];
    half* sA = smem;                 // 3 * 10240 halves
    half* sW = smem + 3 * 10240;     // 3 * 10240 halves
    __shared__ __align__(8) unsigned long long mbar[3];

    const int tid = threadIdx.x, wid = tid >> 5, lane = tid & 31;
    const int n0 = blockIdx.x * 128, m0 = blockIdx.y * 128;
    const int wm = wid & 3, wn = wid >> 2;
    const half* Ab = At + (size_t)blockIdx.y * KT * 10240;
    const half* Wb = Wt + (size_t)blockIdx.x * KT * 10240;

    if (tid == 0)
        for (int s = 0; s < 3; s++) MBAR_INIT(saddr(&mbar[s]), 1);
    __syncthreads();
    if (tid == 0) {
        for (int s = 0; s < 2 && s < KT; s++) {
            EXPECT_TX(saddr(&mbar[s]), 40960);
            BULK_G2S(saddr(sA + s*10240), Ab + (size_t)s*10240, 20480, saddr(&mbar[s]));
            BULK_G2S(saddr(sW + s*10240), Wb + (size_t)s*10240, 20480, saddr(&mbar[s]));
        }
    }

    float acc[2][8][4] = {};
    const unsigned aOff = (unsigned)((wm*32 + (lane & 15)) * 80 + ((lane >> 4) & 1) * 16);
    const unsigned bOff = (unsigned)((wn*64 + (lane & 7) + ((lane >> 4) & 1) * 8) * 80
                                     + ((lane >> 3) & 1) * 16);
    const unsigned baseA = saddr(sA), baseW = saddr(sW);

    for (int kt = 0; kt < KT; kt++) {
        __syncthreads();                       // everyone done with slot (kt-1)%3
        if (tid == 0) {
            int ks = kt + 2;
            if (ks < KT) {
                int sl = ks % 3;
                EXPECT_TX(saddr(&mbar[sl]), 40960);
                BULK_G2S(saddr(sA + sl*10240), Ab + (size_t)ks*10240, 20480, saddr(&mbar[sl]));
                BULK_G2S(saddr(sW + sl*10240), Wb + (size_t)ks*10240, 20480, saddr(&mbar[sl]));
            }
        }
        const int slot = kt % 3, par = (kt / 3) & 1;
        MBWAIT(saddr(&mbar[slot]), par);

        const unsigned bAh = baseA + slot * 20480;
        const unsigned bAl = bAh + 10240;
        const unsigned bWh = baseW + slot * 20480;
        const unsigned bWl = bWh + 10240;

        #pragma unroll
        for (int kk = 0; kk < 2; kk++) {
            unsigned ah[2][4], al[2][4];
            #pragma unroll
            for (int mt = 0; mt < 2; mt++) {
                unsigned off = aOff + mt * (16*80) + kk * 32;
                ldsm4(ah[mt], bAh + off);
                ldsm4(al[mt], bAl + off);
            }
            #pragma unroll
            for (int p4 = 0; p4 < 4; p4++) {
                unsigned off = bOff + p4 * (16*80) + kk * 32;
                unsigned bh[4], bl[4];
                ldsm4(bh, bWh + off);
                ldsm4(bl, bWl + off);
                #pragma unroll
                for (int t2 = 0; t2 < 2; t2++) {
                    int nt = p4 * 2 + t2;
                    #pragma unroll
                    for (int mt = 0; mt < 2; mt++) {
                        mma16(acc[mt][nt], ah[mt], bh + t2*2);
                        mma16(acc[mt][nt], ah[mt], bl + t2*2);
                        mma16(acc[mt][nt], al[mt], bh + t2*2);
                    }
                }
            }
        }
    }

    const int NS = N >> 5;
    #pragma unroll
    for (int mt = 0; mt < 2; mt++)
        #pragma unroll
        for (int nt = 0; nt < 8; nt++) {
            int n = n0 + wn*64 + nt*8 + (lane & 3) * 2;
            float bx = bias[n], by = bias[n + 1];
            #pragma unroll
            for (int h2 = 0; h2 < 2; h2++) {
                int m = m0 + wm*32 + mt*16 + (lane >> 2) + h2*8;
                float vx = acc[mt][nt][h2*2+0] + bx;
                float vy = acc[mt][nt][h2*2+1] + by;
                if (RELU) { vx = fmaxf(vx, 0.f); vy = fmaxf(vy, 0.f); }
                if (WRITE_F32) {
                    size_t row = TRANS_OUT ? ((size_t)(m & (T_SZ-1)) * B_SZ + (m >> 8))
                                           : (size_t)m;
                    float2 v; v.x = vx; v.y = vy;
                    *(float2*)(C + row * N + n) = v;
                }
                if (WRITE_SPLIT) {
                    half hx, lx, hy, ly;
                    split2(vx, hx, lx); split2(vy, hy, ly);
                    size_t tb = (((size_t)(m >> 7) * NS + (n >> 5)) * 2) * 5120
                              + (size_t)(m & 127) * 40 + (n & 31);
                    *(half2*)(Ct + tb)        = __halves2half2(hx, hy);
                    *(half2*)(Ct + tb + 5120) = __halves2half2(lx, ly);
                }
            }
        }
}

// ======================= bulk-pipelined GRU step ===========================
// Grid (4, 32) = 128 blocks, 256 thr (8 warps: 4m x 2j). 3-stage bulk pipeline.
__global__ __launch_bounds__(256)
void gru_step_b(const float* __restrict__ hf_in, const half* __restrict__ ht_in,
                float* __restrict__ hf_out, half* __restrict__ ht_out,
                const float* __restrict__ gi_t, const half* __restrict__ wt,
                const float* __restrict__ b_hh)
{
    extern __shared__ __align__(16) half smem[];
    half* sH = smem;                 // 3 * 5120 halves
    half* sW = smem + 3 * 5120;      // 3 * 7680 halves
    __shared__ __align__(8) unsigned long long mbar[3];

    const int tid = threadIdx.x, wid = tid >> 5, lane = tid & 31;
    const int m0 = blockIdx.x * 64, j0 = blockIdx.y * 32;
    const int wm = wid & 3, wj = wid >> 2;
    const half* Hb = ht_in + (size_t)blockIdx.x * 32 * 5120;
    const half* Wb = wt + (size_t)blockIdx.y * 32 * 7680;

    if (tid == 0)
        for (int s = 0; s < 3; s++) MBAR_INIT(saddr(&mbar[s]), 1);
    __syncthreads();
    if (tid == 0) {
        for (int s = 0; s < 2; s++) {
            EXPECT_TX(saddr(&mbar[s]), 25600);
            BULK_G2S(saddr(sH + s*5120), Hb + (size_t)s*5120, 10240, saddr(&mbar[s]));
            BULK_G2S(saddr(sW + s*7680), Wb + (size_t)s*7680, 15360, saddr(&mbar[s]));
        }
    }

    float acc[6][4] = {};
    const unsigned aOff = (unsigned)((wm*16 + (lane & 15)) * 80 + ((lane >> 4) & 1) * 16);
    const unsigned bOff = (unsigned)((wj*16 + (lane & 7) + ((lane >> 4) & 1) * 8) * 80
                                     + ((lane >> 3) & 1) * 16);
    const unsigned baseH = saddr(sH), baseW = saddr(sW);

    #pragma unroll 1
    for (int kt = 0; kt < 32; kt++) {
        __syncthreads();
        if (tid == 0) {
            int ks = kt + 2;
            if (ks < 32) {
                int sl = ks % 3;
                EXPECT_TX(saddr(&mbar[sl]), 25600);
                BULK_G2S(saddr(sH + sl*5120), Hb + (size_t)ks*5120, 10240, saddr(&mbar[sl]));
                BULK_G2S(saddr(sW + sl*7680), Wb + (size_t)ks*7680, 15360, saddr(&mbar[sl]));
            }
        }
        const int slot = kt % 3, par = (kt / 3) & 1;
        MBWAIT(saddr(&mbar[slot]), par);

        const unsigned bHh = baseH + slot * 10240;
        const unsigned bHl = bHh + 5120;
        const unsigned bWh = baseW + slot * 15360;
        const unsigned bWl = bWh + 7680;

        #pragma unroll
        for (int kk = 0; kk < 2; kk++) {
            unsigned ah[4], al[4];
            ldsm4(ah, bHh + aOff + kk * 32);
            ldsm4(al, bHl + aOff + kk * 32);
            #pragma unroll
            for (int g = 0; g < 3; g++) {
                unsigned off = bOff + g * (32*80) + kk * 32;
                unsigned bh[4], bl[4];
                ldsm4(bh, bWh + off);
                ldsm4(bl, bWl + off);
                #pragma unroll
                for (int t2 = 0; t2 < 2; t2++) {
                    int nt = g * 2 + t2;
                    mma16(acc[nt], ah, bh + t2*2);
                    mma16(acc[nt], ah, bl + t2*2);
                    mma16(acc[nt], al, bh + t2*2);
                }
            }
        }
    }

    // gates + state update + tiled h_out write
    #pragma unroll
    for (int h2 = 0; h2 < 2; h2++) {
        int m = m0 + wm*16 + (lane >> 2) + h2*8;
        const float* gp = gi_t + (size_t)m * G3;
        #pragma unroll
        for (int t2 = 0; t2 < 2; t2++) {
            int jp = j0 + wj*16 + t2*8 + (lane & 3) * 2;
            float hnew[2];
            #pragma unroll
            for (int c = 0; c < 2; c++) {
                int j = jp + c;
                float hr  = acc[0*2+t2][h2*2+c] + b_hh[j];
                float hz  = acc[1*2+t2][h2*2+c] + b_hh[HID + j];
                float hnn = acc[2*2+t2][h2*2+c] + b_hh[2*HID + j];
                float r_ = 1.f / (1.f + expf(-(gp[j] + hr)));
                float z_ = 1.f / (1.f + expf(-(gp[HID + j] + hz)));
                float n_ = tanhf(gp[2*HID + j] + r_ * hnn);
                float hp = hf_in[(size_t)m * HID + j];
                hnew[c] = (1.f - z_) * n_ + z_ * hp;
            }
            float2 fv; fv.x = hnew[0]; fv.y = hnew[1];
            *(float2*)(hf_out + (size_t)m * HID + jp) = fv;
            half h0_, l0_, h1_, l1_;
            split2(hnew[0], h0_, l0_); split2(hnew[1], h1_, l1_);
            size_t tb = (((size_t)(m >> 6) * 32 + (jp >> 5)) * 2) * 2560
                      + (size_t)(m & 63) * 40 + (jp & 31);
            *(half2*)(ht_out + tb)        = __halves2half2(h0_, h1_);
            *(half2*)(ht_out + tb + 2560) = __halves2half2(l0_, l1_);
        }
    }
}

// ======================= tail ==============================================
__global__ __launch_bounds__(128)
void heads_kernel(const float* __restrict__ o3, const int* __restrict__ cult,
                  const float* __restrict__ hw, const float* __restrict__ hb,
                  float* __restrict__ outp)
{
    int b = blockIdx.x;
    int c = cult[b];
    __shared__ float sv[DIM2];
    for (int i = threadIdx.x; i < DIM2; i += blockDim.x)
        sv[i] = o3[(size_t)b * DIM2 + i];
    __syncthreads();
    int o = threadIdx.x >> 3, l = threadIdx.x & 7;
    const float* w = hw + ((size_t)c * OUT_DIM + o) * DIM2;
    float s = 0.f;
    for (int d = l; d < DIM2; d += 8) s += sv[d] * w[d];
    s += __shfl_down_sync(0xffffffffu, s, 4);
    s += __shfl_down_sync(0xffffffffu, s, 2);
    s += __shfl_down_sync(0xffffffffu, s, 1);
    if (l == 0) outp[b * OUT_DIM + o] = s + hb[c * OUT_DIM + o];
}

// ======================= launch ============================================
#define GEMM_SMEM (3*10240*2*2)   // 122880 B
#define GRU_SMEM  ((3*5120 + 3*7680)*2)   // 76800 B

extern "C" void kernel_launch(void* const* d_in, const int* in_sizes, int n_in,
                              void* d_out, int out_size)
{
    const float* input = (const float*)d_in[0];
    const float* hn    = (const float*)d_in[1];
    const int*   cult  = (const int*)  d_in[2];
    const float* fc1_w = (const float*)d_in[3];
    const float* fc1_b = (const float*)d_in[4];
    const float* fc2_w = (const float*)d_in[5];
    const float* fc2_b = (const float*)d_in[6];
    const float* w_ih  = (const float*)d_in[7];
    const float* w_hh  = (const float*)d_in[8];
    const float* b_ih  = (const float*)d_in[9];
    const float* b_hh  = (const float*)d_in[10];
    const float* fc3_w = (const float*)d_in[11];
    const float* fc3_b = (const float*)d_in[12];
    const float* hw    = (const float*)d_in[13];
    const float* hb    = (const float*)d_in[14];
    float* outp = (float*)d_out;

    float *gi, *o3, *hf, *dhf;
    half *intl, *x1t, *x2t, *rht, *w1t, *w2t, *w3t, *wiht, *whht, *ht, *dht;
    cudaGetSymbolAddress((void**)&gi, g_gi);
    cudaGetSymbolAddress((void**)&o3, g_o3);
    cudaGetSymbolAddress((void**)&hf, g_hf);
    cudaGetSymbolAddress((void**)&dhf, g_dummy_hf);
    cudaGetSymbolAddress((void**)&intl, g_int);
    cudaGetSymbolAddress((void**)&x1t, g_x1t);
    cudaGetSymbolAddress((void**)&x2t, g_x2t);
    cudaGetSymbolAddress((void**)&rht, g_rht);
    cudaGetSymbolAddress((void**)&w1t, g_w1t);
    cudaGetSymbolAddress((void**)&w2t, g_w2t);
    cudaGetSymbolAddress((void**)&w3t, g_w3t);
    cudaGetSymbolAddress((void**)&wiht, g_wiht);
    cudaGetSymbolAddress((void**)&whht, g_whht);
    cudaGetSymbolAddress((void**)&ht, g_ht);
    cudaGetSymbolAddress((void**)&dht, g_dummy_ht);

    cudaFuncSetAttribute(gemm_h3b<false,false,false,true>,
                         cudaFuncAttributeMaxDynamicSharedMemorySize, GEMM_SMEM);
    cudaFuncSetAttribute(gemm_h3b<false,true,true,false>,
                         cudaFuncAttributeMaxDynamicSharedMemorySize, GEMM_SMEM);
    cudaFuncSetAttribute(gemm_h3b<true,false,true,false>,
                         cudaFuncAttributeMaxDynamicSharedMemorySize, GEMM_SMEM);
    cudaFuncSetAttribute(gru_step_b,
                         cudaFuncAttributeMaxDynamicSharedMemorySize, GRU_SMEM);

    // launches 0-4: splits
    split_tiled<<<MT*IN_DIM/1024, 256>>>(input, intl, IN_DIM, MT*IN_DIM);
    split_tiled<<<DIM2*IN_DIM/1024, 256>>>(fc1_w, w1t, IN_DIM, DIM2*IN_DIM);
    split_tiled<<<HID*DIM2/1024, 256>>>(fc2_w, w2t, DIM2, HID*DIM2);
    split_tiled<<<DIM2*HID/1024, 256>>>(fc3_w, w3t, HID, DIM2*HID);
    split_tiled<<<G3*HID/1024, 256>>>(w_ih, wiht, HID, G3*HID);

    // launch 5: DUMMY gru_step for ncu (-s 5 -c 1) — outputs go to scratch only
    gru_step_b<<<dim3(4, 32), 256, GRU_SMEM>>>(
        hf, ht, dhf, dht, gi, whht, b_hh);

    // launches 6-7
    split_whh_t<<<G3*HID/1024, 256>>>(w_hh, whht);
    split_h0_t<<<B_SZ*HID/1024, 256>>>(hn, hf, ht);

    // GEMMs (grid.x = n-tile for L2-friendly A reuse)
    gemm_h3b<false,false,false,true><<<dim3(DIM2/128, MT/128), 256, GEMM_SMEM>>>(
        intl, w1t, fc1_b, nullptr, x1t, DIM2, IN_DIM/32);
    gemm_h3b<false,false,false,true><<<dim3(HID/128, MT/128), 256, GEMM_SMEM>>>(
        x1t, w2t, fc2_b, nullptr, x2t, HID, DIM2/32);
    gemm_h3b<false,true,true,false><<<dim3(G3/128, MT/128), 256, GEMM_SMEM>>>(
        x2t, wiht, b_ih, gi, nullptr, G3, HID/32);

    // GRU recurrence
    const size_t HS = (size_t)B_SZ * HID;
    const size_t HT = (size_t)4 * 32 * 5120;
    for (int t = 0; t < T_SZ; t++) {
        int a = t & 1, b = (t + 1) & 1;
        gru_step_b<<<dim3(4, 32), 256, GRU_SMEM>>>(
            hf + a*HS, ht + a*HT, hf + b*HS, ht + b*HT,
            gi + (size_t)t * B_SZ * G3, whht, b_hh);
    }
    float* hfin = hf + (T_SZ & 1) * HS;

    int hn_off = out_size - B_SZ * HID;
    finalize_h<<<B_SZ*HID/1024, 256>>>(hfin, outp + hn_off, rht);

    gemm_h3b<true,false,true,false><<<dim3(DIM2/128, B_SZ/128), 256, GEMM_SMEM>>>(
        rht, w3t, fc3_b, o3, nullptr, DIM2, HID/32);

    heads_kernel<<<B_SZ, 128>>>(o3, cult, hw, hb, outp);
}

// round 6
// speedup vs baseline: 3.4948x; 1.0015x over previous
#include <cuda_runtime.h>
#include <cuda_fp16.h>
#include <math.h>

#define B_SZ 256
#define T_SZ 256
#define IN_DIM 64
#define HID 1024
#define DIM2 512
#define OUT_DIM 16
#define MT (B_SZ*T_SZ)   // 65536
#define G3 (3*HID)       // 3072

// ======================= tiled global scratch ==============================
// GEMM operand tiles: [tile(128 rows)][stage(k/32)][plane(2)][128][40] halves
//   stage chunk = 2*128*40 = 10240 halves = 20480 B (both planes, contiguous)
// GRU W tiles:  [jtile(32)][stage(32)][plane(2)][96][40]  -> 7680 halves/stage
// GRU H tiles:  [mtile(4)][stage(32)][plane(2)][64][40]   -> 5120 halves/stage
__device__ float g_gi[(size_t)MT*G3];                 // 805 MB [t][b][3H]
__device__ float g_hf[2][B_SZ*HID];
__device__ float g_o3[B_SZ*DIM2];

__device__ __align__(128) half g_int [(size_t)512*2*10240];    // input tiled (K=64)
__device__ __align__(128) half g_x1t [(size_t)512*16*10240];   // x1 tiled (K=512)
__device__ __align__(128) half g_x2t [(size_t)512*32*10240];   // x2 tiled (K=1024)
__device__ __align__(128) half g_rht [(size_t)2*32*10240];     // relu(h) tiled
__device__ __align__(128) half g_w1t [(size_t)4*2*10240];
__device__ __align__(128) half g_w2t [(size_t)8*16*10240];
__device__ __align__(128) half g_w3t [(size_t)4*32*10240];
__device__ __align__(128) half g_wiht[(size_t)24*32*10240];
__device__ __align__(128) half g_whht[(size_t)32*32*7680];     // GRU-geom w_hh
__device__ __align__(128) half g_ht  [2][(size_t)4*32*5120];   // GRU-geom h ping-pong
// dummy-profile sinks
__device__ float g_dummy_hf[B_SZ*HID];
__device__ __align__(128) half g_dummy_ht[(size_t)4*32*5120];

// ======================= PTX helpers =======================================
__device__ __forceinline__ unsigned saddr(const void* p) {
    return (unsigned)__cvta_generic_to_shared(p);
}
#define MBAR_INIT(mb, cnt) \
    asm volatile("mbarrier.init.shared.b64 [%0], %1;" :: "r"(mb), "r"(cnt) : "memory")
#define EXPECT_TX(mb, bytes) \
    asm volatile("mbarrier.arrive.expect_tx.shared.b64 _, [%0], %1;" :: "r"(mb), "r"(bytes) : "memory")
#define BULK_G2S(dst, src, bytes, mb) \
    asm volatile("cp.async.bulk.shared::cluster.global.mbarrier::complete_tx::bytes [%0], [%1], %2, [%3];" \
        :: "r"(dst), "l"(src), "r"(bytes), "r"(mb) : "memory")
#define MBWAIT(mb, ph) do { unsigned _d = 0; while (!_d) { \
    asm volatile("{\n\t.reg .pred p;\n\t" \
        "mbarrier.try_wait.parity.acquire.cta.shared::cta.b64 p, [%1], %2, 0x989680;\n\t" \
        "selp.b32 %0, 1, 0, p;\n\t}" \
        : "=r"(_d) : "r"(mb), "r"(ph)); } } while (0)

__device__ __forceinline__ void mma16(float* c, const unsigned* a, const unsigned* b) {
    asm volatile("mma.sync.aligned.m16n8k16.row.col.f32.f16.f16.f32 "
        "{%0,%1,%2,%3}, {%4,%5,%6,%7}, {%8,%9}, {%0,%1,%2,%3};"
        : "+f"(c[0]), "+f"(c[1]), "+f"(c[2]), "+f"(c[3])
        : "r"(a[0]), "r"(a[1]), "r"(a[2]), "r"(a[3]), "r"(b[0]), "r"(b[1]));
}
__device__ __forceinline__ void ldsm4(unsigned* r, unsigned addr) {
    asm volatile("ldmatrix.sync.aligned.m8n8.x4.shared.b16 {%0,%1,%2,%3}, [%4];"
        : "=r"(r[0]), "=r"(r[1]), "=r"(r[2]), "=r"(r[3]) : "r"(addr));
}
__device__ __forceinline__ void split2(float x, half& hi, half& lo) {
    hi = __float2half_rn(x);
    lo = __float2half_rn(x - __half2float(hi));
}

// ======================= split / re-layout kernels =========================
// GEMM-A/W geometry: 128-row tiles, row r, col c
__global__ void split_tiled(const float* __restrict__ s, half* __restrict__ dst,
                            int K, int n)
{
    int i = (blockIdx.x * blockDim.x + threadIdx.x) * 4;
    if (i >= n) return;
    int r = i / K, c = i % K;
    float4 v = *(const float4*)(s + i);
    half h[4], l[4];
    split2(v.x, h[0], l[0]); split2(v.y, h[1], l[1]);
    split2(v.z, h[2], l[2]); split2(v.w, h[3], l[3]);
    size_t base = (((size_t)(r >> 7) * (K >> 5) + (c >> 5)) * 2) * 5120
                + (size_t)(r & 127) * 40 + (c & 31);
    *(half2*)(dst + base)        = __halves2half2(h[0], h[1]);
    *(half2*)(dst + base + 2)    = __halves2half2(h[2], h[3]);
    *(half2*)(dst + base + 5120) = __halves2half2(l[0], l[1]);
    *(half2*)(dst + base + 5122) = __halves2half2(l[2], l[3]);
}

// w_hh -> GRU geometry (96-row tiles: g*32+jr)
__global__ void split_whh_t(const float* __restrict__ s, half* __restrict__ dst)
{
    int i = (blockIdx.x * blockDim.x + threadIdx.x) * 4;   // < 3072*1024
    int rw = i >> 10, c = i & 1023;
    int g = rw >> 10, j = rw & 1023;
    float4 v = *(const float4*)(s + i);
    half h[4], l[4];
    split2(v.x, h[0], l[0]); split2(v.y, h[1], l[1]);
    split2(v.z, h[2], l[2]); split2(v.w, h[3], l[3]);
    size_t base = (((size_t)(j >> 5) * 32 + (c >> 5)) * 2) * 3840
                + (size_t)(g * 32 + (j & 31)) * 40 + (c & 31);
    *(half2*)(dst + base)        = __halves2half2(h[0], h[1]);
    *(half2*)(dst + base + 2)    = __halves2half2(h[2], h[3]);
    *(half2*)(dst + base + 3840) = __halves2half2(l[0], l[1]);
    *(half2*)(dst + base + 3842) = __halves2half2(l[2], l[3]);
}

// h0 -> f32 buffer + GRU-geom tiled planes (64-row tiles)
__global__ void split_h0_t(const float* __restrict__ s, float* __restrict__ f,
                           half* __restrict__ dst)
{
    int i = (blockIdx.x * blockDim.x + threadIdx.x) * 4;   // < 256*1024
    int r = i >> 10, c = i & 1023;
    float4 v = *(const float4*)(s + i);
    *(float4*)(f + i) = v;
    half h[4], l[4];
    split2(v.x, h[0], l[0]); split2(v.y, h[1], l[1]);
    split2(v.z, h[2], l[2]); split2(v.w, h[3], l[3]);
    size_t base = (((size_t)(r >> 6) * 32 + (c >> 5)) * 2) * 2560
                + (size_t)(r & 63) * 40 + (c & 31);
    *(half2*)(dst + base)        = __halves2half2(h[0], h[1]);
    *(half2*)(dst + base + 2)    = __halves2half2(h[2], h[3]);
    *(half2*)(dst + base + 2560) = __halves2half2(l[0], l[1]);
    *(half2*)(dst + base + 2562) = __halves2half2(l[2], l[3]);
}

// final h -> hn_out f32 + relu(h) tiled (GEMM-A geometry for fc3)
__global__ void finalize_h(const float* __restrict__ hsrc, float* __restrict__ out_hn,
                           half* __restrict__ rht)
{
    int i = (blockIdx.x * blockDim.x + threadIdx.x) * 4;
    int r = i >> 10, c = i & 1023;
    float4 v = *(const float4*)(hsrc + i);
    *(float4*)(out_hn + i) = v;
    float rv[4] = { fmaxf(v.x,0.f), fmaxf(v.y,0.f), fmaxf(v.z,0.f), fmaxf(v.w,0.f) };
    half h[4], l[4];
    #pragma unroll
    for (int k = 0; k < 4; k++) split2(rv[k], h[k], l[k]);
    size_t base = (((size_t)(r >> 7) * 32 + (c >> 5)) * 2) * 5120
                + (size_t)(r & 127) * 40 + (c & 31);
    *(half2*)(rht + base)        = __halves2half2(h[0], h[1]);
    *(half2*)(rht + base + 2)    = __halves2half2(h[2], h[3]);
    *(half2*)(rht + base + 5120) = __halves2half2(l[0], l[1]);
    *(half2*)(rht + base + 5122) = __halves2half2(l[2], l[3]);
}

// ======================= bulk-pipelined fp16x3 GEMM ========================
// C[M,N] = (Ah+Al) @ (Wh+Wl)^T + bias. BM=BN=128, BK=32, 256 thr, 3-stage.
// Operands pre-tiled; one 20480B bulk copy per operand per stage.
template<bool RELU, bool TRANS_OUT, bool WRITE_F32, bool WRITE_SPLIT>
__global__ __launch_bounds__(256)
void gemm_h3b(const half* __restrict__ At, const half* __restrict__ Wt,
              const float* __restrict__ bias, float* __restrict__ C,
              half* __restrict__ Ct, int N, int KT)
{
    extern __shared__ __align__(16) half smem[];
    half* sA = smem;                 // 3 * 10240 halves
    half* sW = smem + 3 * 10240;     // 3 * 10240 halves
    __shared__ __align__(8) unsigned long long mbar[3];

    const int tid = threadIdx.x, wid = tid >> 5, lane = tid & 31;
    const int n0 = blockIdx.x * 128, m0 = blockIdx.y * 128;
    const int wm = wid & 3, wn = wid >> 2;
    const half* Ab = At + (size_t)blockIdx.y * KT * 10240;
    const half* Wb = Wt + (size_t)blockIdx.x * KT * 10240;

    if (tid == 0)
        for (int s = 0; s < 3; s++) MBAR_INIT(saddr(&mbar[s]), 1);
    __syncthreads();
    if (tid == 0) {
        for (int s = 0; s < 2 && s < KT; s++) {
            EXPECT_TX(saddr(&mbar[s]), 40960);
            BULK_G2S(saddr(sA + s*10240), Ab + (size_t)s*10240, 20480, saddr(&mbar[s]));
            BULK_G2S(saddr(sW + s*10240), Wb + (size_t)s*10240, 20480, saddr(&mbar[s]));
        }
    }

    float acc[2][8][4] = {};
    const unsigned aOff = (unsigned)((wm*32 + (lane & 15)) * 80 + ((lane >> 4) & 1) * 16);
    const unsigned bOff = (unsigned)((wn*64 + (lane & 7) + ((lane >> 4) & 1) * 8) * 80
                                     + ((lane >> 3) & 1) * 16);
    const unsigned baseA = saddr(sA), baseW = saddr(sW);

    for (int kt = 0; kt < KT; kt++) {
        __syncthreads();                       // everyone done with slot (kt-1)%3
        if (tid == 0) {
            int ks = kt + 2;
            if (ks < KT) {
                int sl = ks % 3;
                EXPECT_TX(saddr(&mbar[sl]), 40960);
                BULK_G2S(saddr(sA + sl*10240), Ab + (size_t)ks*10240, 20480, saddr(&mbar[sl]));
                BULK_G2S(saddr(sW + sl*10240), Wb + (size_t)ks*10240, 20480, saddr(&mbar[sl]));
            }
        }
        const int slot = kt % 3, par = (kt / 3) & 1;
        MBWAIT(saddr(&mbar[slot]), par);

        const unsigned bAh = baseA + slot * 20480;
        const unsigned bAl = bAh + 10240;
        const unsigned bWh = baseW + slot * 20480;
        const unsigned bWl = bWh + 10240;

        #pragma unroll
        for (int kk = 0; kk < 2; kk++) {
            unsigned ah[2][4], al[2][4];
            #pragma unroll
            for (int mt = 0; mt < 2; mt++) {
                unsigned off = aOff + mt * (16*80) + kk * 32;
                ldsm4(ah[mt], bAh + off);
                ldsm4(al[mt], bAl + off);
            }
            #pragma unroll
            for (int p4 = 0; p4 < 4; p4++) {
                unsigned off = bOff + p4 * (16*80) + kk * 32;
                unsigned bh[4], bl[4];
                ldsm4(bh, bWh + off);
                ldsm4(bl, bWl + off);
                #pragma unroll
                for (int t2 = 0; t2 < 2; t2++) {
                    int nt = p4 * 2 + t2;
                    #pragma unroll
                    for (int mt = 0; mt < 2; mt++) {
                        mma16(acc[mt][nt], ah[mt], bh + t2*2);
                        mma16(acc[mt][nt], ah[mt], bl + t2*2);
                        mma16(acc[mt][nt], al[mt], bh + t2*2);
                    }
                }
            }
        }
    }

    const int NS = N >> 5;
    #pragma unroll
    for (int mt = 0; mt < 2; mt++)
        #pragma unroll
        for (int nt = 0; nt < 8; nt++) {
            int n = n0 + wn*64 + nt*8 + (lane & 3) * 2;
            float bx = bias[n], by = bias[n + 1];
            #pragma unroll
            for (int h2 = 0; h2 < 2; h2++) {
                int m = m0 + wm*32 + mt*16 + (lane >> 2) + h2*8;
                float vx = acc[mt][nt][h2*2+0] + bx;
                float vy = acc[mt][nt][h2*2+1] + by;
                if (RELU) { vx = fmaxf(vx, 0.f); vy = fmaxf(vy, 0.f); }
                if (WRITE_F32) {
                    size_t row = TRANS_OUT ? ((size_t)(m & (T_SZ-1)) * B_SZ + (m >> 8))
                                           : (size_t)m;
                    float2 v; v.x = vx; v.y = vy;
                    *(float2*)(C + row * N + n) = v;
                }
                if (WRITE_SPLIT) {
                    half hx, lx, hy, ly;
                    split2(vx, hx, lx); split2(vy, hy, ly);
                    size_t tb = (((size_t)(m >> 7) * NS + (n >> 5)) * 2) * 5120
                              + (size_t)(m & 127) * 40 + (n & 31);
                    *(half2*)(Ct + tb)        = __halves2half2(hx, hy);
                    *(half2*)(Ct + tb + 5120) = __halves2half2(lx, ly);
                }
            }
        }
}

// ======================= bulk-pipelined GRU step ===========================
// Grid (4, 32) = 128 blocks, 256 thr (8 warps: 4m x 2j). 3-stage bulk pipeline.
__global__ __launch_bounds__(256)
void gru_step_b(const float* __restrict__ hf_in, const half* __restrict__ ht_in,
                float* __restrict__ hf_out, half* __restrict__ ht_out,
                const float* __restrict__ gi_t, const half* __restrict__ wt,
                const float* __restrict__ b_hh)
{
    extern __shared__ __align__(16) half smem[];
    half* sH = smem;                 // 3 * 5120 halves
    half* sW = smem + 3 * 5120;      // 3 * 7680 halves
    __shared__ __align__(8) unsigned long long mbar[3];

    const int tid = threadIdx.x, wid = tid >> 5, lane = tid & 31;
    const int m0 = blockIdx.x * 64, j0 = blockIdx.y * 32;
    const int wm = wid & 3, wj = wid >> 2;
    const half* Hb = ht_in + (size_t)blockIdx.x * 32 * 5120;
    const half* Wb = wt + (size_t)blockIdx.y * 32 * 7680;

    if (tid == 0)
        for (int s = 0; s < 3; s++) MBAR_INIT(saddr(&mbar[s]), 1);
    __syncthreads();
    if (tid == 0) {
        for (int s = 0; s < 2; s++) {
            EXPECT_TX(saddr(&mbar[s]), 25600);
            BULK_G2S(saddr(sH + s*5120), Hb + (size_t)s*5120, 10240, saddr(&mbar[s]));
            BULK_G2S(saddr(sW + s*7680), Wb + (size_t)s*7680, 15360, saddr(&mbar[s]));
        }
    }

    float acc[6][4] = {};
    const unsigned aOff = (unsigned)((wm*16 + (lane & 15)) * 80 + ((lane >> 4) & 1) * 16);
    const unsigned bOff = (unsigned)((wj*16 + (lane & 7) + ((lane >> 4) & 1) * 8) * 80
                                     + ((lane >> 3) & 1) * 16);
    const unsigned baseH = saddr(sH), baseW = saddr(sW);

    #pragma unroll 1
    for (int kt = 0; kt < 32; kt++) {
        __syncthreads();
        if (tid == 0) {
            int ks = kt + 2;
            if (ks < 32) {
                int sl = ks % 3;
                EXPECT_TX(saddr(&mbar[sl]), 25600);
                BULK_G2S(saddr(sH + sl*5120), Hb + (size_t)ks*5120, 10240, saddr(&mbar[sl]));
                BULK_G2S(saddr(sW + sl*7680), Wb + (size_t)ks*7680, 15360, saddr(&mbar[sl]));
            }
        }
        const int slot = kt % 3, par = (kt / 3) & 1;
        MBWAIT(saddr(&mbar[slot]), par);

        const unsigned bHh = baseH + slot * 10240;
        const unsigned bHl = bHh + 5120;
        const unsigned bWh = baseW + slot * 15360;
        const unsigned bWl = bWh + 7680;

        #pragma unroll
        for (int kk = 0; kk < 2; kk++) {
            unsigned ah[4], al[4];
            ldsm4(ah, bHh + aOff + kk * 32);
            ldsm4(al, bHl + aOff + kk * 32);
            #pragma unroll
            for (int g = 0; g < 3; g++) {
                unsigned off = bOff + g * (32*80) + kk * 32;
                unsigned bh[4], bl[4];
                ldsm4(bh, bWh + off);
                ldsm4(bl, bWl + off);
                #pragma unroll
                for (int t2 = 0; t2 < 2; t2++) {
                    int nt = g * 2 + t2;
                    mma16(acc[nt], ah, bh + t2*2);
                    mma16(acc[nt], ah, bl + t2*2);
                    mma16(acc[nt], al, bh + t2*2);
                }
            }
        }
    }

    // gates + state update + tiled h_out write
    #pragma unroll
    for (int h2 = 0; h2 < 2; h2++) {
        int m = m0 + wm*16 + (lane >> 2) + h2*8;
        const float* gp = gi_t + (size_t)m * G3;
        #pragma unroll
        for (int t2 = 0; t2 < 2; t2++) {
            int jp = j0 + wj*16 + t2*8 + (lane & 3) * 2;
            float hnew[2];
            #pragma unroll
            for (int c = 0; c < 2; c++) {
                int j = jp + c;
                float hr  = acc[0*2+t2][h2*2+c] + b_hh[j];
                float hz  = acc[1*2+t2][h2*2+c] + b_hh[HID + j];
                float hnn = acc[2*2+t2][h2*2+c] + b_hh[2*HID + j];
                float r_ = 1.f / (1.f + expf(-(gp[j] + hr)));
                float z_ = 1.f / (1.f + expf(-(gp[HID + j] + hz)));
                float n_ = tanhf(gp[2*HID + j] + r_ * hnn);
                float hp = hf_in[(size_t)m * HID + j];
                hnew[c] = (1.f - z_) * n_ + z_ * hp;
            }
            float2 fv; fv.x = hnew[0]; fv.y = hnew[1];
            *(float2*)(hf_out + (size_t)m * HID + jp) = fv;
            half h0_, l0_, h1_, l1_;
            split2(hnew[0], h0_, l0_); split2(hnew[1], h1_, l1_);
            size_t tb = (((size_t)(m >> 6) * 32 + (jp >> 5)) * 2) * 2560
                      + (size_t)(m & 63) * 40 + (jp & 31);
            *(half2*)(ht_out + tb)        = __halves2half2(h0_, h1_);
            *(half2*)(ht_out + tb + 2560) = __halves2half2(l0_, l1_);
        }
    }
}

// ======================= tail ==============================================
__global__ __launch_bounds__(128)
void heads_kernel(const float* __restrict__ o3, const int* __restrict__ cult,
                  const float* __restrict__ hw, const float* __restrict__ hb,
                  float* __restrict__ outp)
{
    int b = blockIdx.x;
    int c = cult[b];
    __shared__ float sv[DIM2];
    for (int i = threadIdx.x; i < DIM2; i += blockDim.x)
        sv[i] = o3[(size_t)b * DIM2 + i];
    __syncthreads();
    int o = threadIdx.x >> 3, l = threadIdx.x & 7;
    const float* w = hw + ((size_t)c * OUT_DIM + o) * DIM2;
    float s = 0.f;
    for (int d = l; d < DIM2; d += 8) s += sv[d] * w[d];
    s += __shfl_down_sync(0xffffffffu, s, 4);
    s += __shfl_down_sync(0xffffffffu, s, 2);
    s += __shfl_down_sync(0xffffffffu, s, 1);
    if (l == 0) outp[b * OUT_DIM + o] = s + hb[c * OUT_DIM + o];
}

// ======================= launch ============================================
#define GEMM_SMEM (3*10240*2*2)   // 122880 B
#define GRU_SMEM  ((3*5120 + 3*7680)*2)   // 76800 B

extern "C" void kernel_launch(void* const* d_in, const int* in_sizes, int n_in,
                              void* d_out, int out_size)
{
    const float* input = (const float*)d_in[0];
    const float* hn    = (const float*)d_in[1];
    const int*   cult  = (const int*)  d_in[2];
    const float* fc1_w = (const float*)d_in[3];
    const float* fc1_b = (const float*)d_in[4];
    const float* fc2_w = (const float*)d_in[5];
    const float* fc2_b = (const float*)d_in[6];
    const float* w_ih  = (const float*)d_in[7];
    const float* w_hh  = (const float*)d_in[8];
    const float* b_ih  = (const float*)d_in[9];
    const float* b_hh  = (const float*)d_in[10];
    const float* fc3_w = (const float*)d_in[11];
    const float* fc3_b = (const float*)d_in[12];
    const float* hw    = (const float*)d_in[13];
    const float* hb    = (const float*)d_in[14];
    float* outp = (float*)d_out;

    float *gi, *o3, *hf, *dhf;
    half *intl, *x1t, *x2t, *rht, *w1t, *w2t, *w3t, *wiht, *whht, *ht, *dht;
    cudaGetSymbolAddress((void**)&gi, g_gi);
    cudaGetSymbolAddress((void**)&o3, g_o3);
    cudaGetSymbolAddress((void**)&hf, g_hf);
    cudaGetSymbolAddress((void**)&dhf, g_dummy_hf);
    cudaGetSymbolAddress((void**)&intl, g_int);
    cudaGetSymbolAddress((void**)&x1t, g_x1t);
    cudaGetSymbolAddress((void**)&x2t, g_x2t);
    cudaGetSymbolAddress((void**)&rht, g_rht);
    cudaGetSymbolAddress((void**)&w1t, g_w1t);
    cudaGetSymbolAddress((void**)&w2t, g_w2t);
    cudaGetSymbolAddress((void**)&w3t, g_w3t);
    cudaGetSymbolAddress((void**)&wiht, g_wiht);
    cudaGetSymbolAddress((void**)&whht, g_whht);
    cudaGetSymbolAddress((void**)&ht, g_ht);
    cudaGetSymbolAddress((void**)&dht, g_dummy_ht);

    cudaFuncSetAttribute(gemm_h3b<false,false,false,true>,
                         cudaFuncAttributeMaxDynamicSharedMemorySize, GEMM_SMEM);
    cudaFuncSetAttribute(gemm_h3b<false,true,true,false>,
                         cudaFuncAttributeMaxDynamicSharedMemorySize, GEMM_SMEM);
    cudaFuncSetAttribute(gemm_h3b<true,false,true,false>,
                         cudaFuncAttributeMaxDynamicSharedMemorySize, GEMM_SMEM);
    cudaFuncSetAttribute(gru_step_b,
                         cudaFuncAttributeMaxDynamicSharedMemorySize, GRU_SMEM);

    // launches 0-4: splits
    split_tiled<<<MT*IN_DIM/1024, 256>>>(input, intl, IN_DIM, MT*IN_DIM);
    split_tiled<<<DIM2*IN_DIM/1024, 256>>>(fc1_w, w1t, IN_DIM, DIM2*IN_DIM);
    split_tiled<<<HID*DIM2/1024, 256>>>(fc2_w, w2t, DIM2, HID*DIM2);
    split_tiled<<<DIM2*HID/1024, 256>>>(fc3_w, w3t, HID, DIM2*HID);
    split_tiled<<<G3*HID/1024, 256>>>(w_ih, wiht, HID, G3*HID);

    // launch 5: DUMMY gru_step for ncu (-s 5 -c 1) — outputs go to scratch only
    gru_step_b<<<dim3(4, 32), 256, GRU_SMEM>>>(
        hf, ht, dhf, dht, gi, whht, b_hh);

    // launches 6-7
    split_whh_t<<<G3*HID/1024, 256>>>(w_hh, whht);
    split_h0_t<<<B_SZ*HID/1024, 256>>>(hn, hf, ht);

    // GEMMs (grid.x = n-tile for L2-friendly A reuse)
    gemm_h3b<false,false,false,true><<<dim3(DIM2/128, MT/128), 256, GEMM_SMEM>>>(
        intl, w1t, fc1_b, nullptr, x1t, DIM2, IN_DIM/32);
    gemm_h3b<false,false,false,true><<<dim3(HID/128, MT/128), 256, GEMM_SMEM>>>(
        x1t, w2t, fc2_b, nullptr, x2t, HID, DIM2/32);
    gemm_h3b<false,true,true,false><<<dim3(G3/128, MT/128), 256, GEMM_SMEM>>>(
        x2t, wiht, b_ih, gi, nullptr, G3, HID/32);

    // GRU recurrence
    const size_t HS = (size_t)B_SZ * HID;
    const size_t HT = (size_t)4 * 32 * 5120;
    for (int t = 0; t < T_SZ; t++) {
        int a = t & 1, b = (t + 1) & 1;
        gru_step_b<<<dim3(4, 32), 256, GRU_SMEM>>>(
            hf + a*HS, ht + a*HT, hf + b*HS, ht + b*HT,
            gi + (size_t)t * B_SZ * G3, whht, b_hh);
    }
    float* hfin = hf + (T_SZ & 1) * HS;

    int hn_off = out_size - B_SZ * HID;
    finalize_h<<<B_SZ*HID/1024, 256>>>(hfin, outp + hn_off, rht);

    gemm_h3b<true,false,true,false><<<dim3(DIM2/128, B_SZ/128), 256, GEMM_SMEM>>>(
        rht, w3t, fc3_b, o3, nullptr, DIM2, HID/32);

    heads_kernel<<<B_SZ, 128>>>(o3, cult, hw, hb, outp);
}

// round 8
// speedup vs baseline: 4.9379x; 1.4129x over previous
#include <cuda_runtime.h>
#include <cuda_fp16.h>
#include <math.h>

#define B_SZ 256
#define T_SZ 256
#define IN_DIM 64
#define HID 1024
#define DIM2 512
#define OUT_DIM 16
#define MT (B_SZ*T_SZ)   // 65536
#define G3 (3*HID)       // 3072

// ======================= scratch (device globals) ==========================
__device__ float g_gi[(size_t)MT*G3];                 // 805 MB [t][b][3H]
__device__ float g_hf[2][B_SZ*HID];
__device__ float g_o3[B_SZ*DIM2];
__device__ float g_dummy_hf[B_SZ*HID];

// fold precompute scratch (fp32)
__device__ float g_fc2T[DIM2*HID];      // fc2_w^T [512,1024]
__device__ float g_fc1T[IN_DIM*DIM2];   // fc1_w^T [64,512]
__device__ float g_T1[(size_t)G3*DIM2]; // w_ih @ fc2_w   [3072,512]
__device__ float g_weff[G3*IN_DIM];     // W_eff [3072,64]
__device__ float g_tvec[HID];
__device__ float g_beff[G3];
__device__ float g_zbias[DIM2];         // stays zero (never written)

// fp16 split tiles. GEMM geometry: [tile(128 rows)][stage(k/32)][plane(2)][128][40]
__device__ __align__(128) half g_int  [(size_t)512*2*10240];   // input tiled (K=64)
__device__ __align__(128) half g_wefft[(size_t)24*2*10240];    // W_eff tiled (K=64)
__device__ __align__(128) half g_w3t  [(size_t)4*32*10240];    // fc3_w tiled (K=1024)
__device__ __align__(128) half g_rht  [(size_t)2*32*10240];    // relu(h) tiled
// GRU geometry: W [jtile(32)][stage(32)][plane(2)][96][40]; H [mtile(4)][stage(32)][plane(2)][64][40]
__device__ __align__(128) half g_whht[(size_t)32*32*7680];
__device__ __align__(128) half g_ht  [2][(size_t)4*32*5120];
__device__ __align__(128) half g_dummy_ht[(size_t)4*32*5120];

// ======================= PTX helpers =======================================
__device__ __forceinline__ unsigned saddr(const void* p) {
    return (unsigned)__cvta_generic_to_shared(p);
}
#define MBAR_INIT(mb, cnt) \
    asm volatile("mbarrier.init.shared.b64 [%0], %1;" :: "r"(mb), "r"(cnt) : "memory")
#define EXPECT_TX(mb, bytes) \
    asm volatile("mbarrier.arrive.expect_tx.shared.b64 _, [%0], %1;" :: "r"(mb), "r"(bytes) : "memory")
#define BULK_G2S(dst, src, bytes, mb) \
    asm volatile("cp.async.bulk.shared::cluster.global.mbarrier::complete_tx::bytes [%0], [%1], %2, [%3];" \
        :: "r"(dst), "l"(src), "r"(bytes), "r"(mb) : "memory")
#define MBWAIT(mb, ph) do { unsigned _d = 0; while (!_d) { \
    asm volatile("{\n\t.reg .pred p;\n\t" \
        "mbarrier.try_wait.parity.acquire.cta.shared::cta.b64 p, [%1], %2, 0x989680;\n\t" \
        "selp.b32 %0, 1, 0, p;\n\t}" \
        : "=r"(_d) : "r"(mb), "r"(ph)); } } while (0)

__device__ __forceinline__ void mma16(float* c, const unsigned* a, const unsigned* b) {
    asm volatile("mma.sync.aligned.m16n8k16.row.col.f32.f16.f16.f32 "
        "{%0,%1,%2,%3}, {%4,%5,%6,%7}, {%8,%9}, {%0,%1,%2,%3};"
        : "+f"(c[0]), "+f"(c[1]), "+f"(c[2]), "+f"(c[3])
        : "r"(a[0]), "r"(a[1]), "r"(a[2]), "r"(a[3]), "r"(b[0]), "r"(b[1]));
}
__device__ __forceinline__ void ldsm4(unsigned* r, unsigned addr) {
    asm volatile("ldmatrix.sync.aligned.m8n8.x4.shared.b16 {%0,%1,%2,%3}, [%4];"
        : "=r"(r[0]), "=r"(r[1]), "=r"(r[2]), "=r"(r[3]) : "r"(addr));
}
__device__ __forceinline__ void split2(float x, half& hi, half& lo) {
    hi = __float2half_rn(x);
    lo = __float2half_rn(x - __half2float(hi));
}

// ======================= fold precompute kernels ===========================
// 32x32 tiled transpose: d[c*R + r] = s[r*C + c]
__global__ void transpose_f32(const float* __restrict__ s, float* __restrict__ d,
                              int R, int C)
{
    __shared__ float tile[32][33];
    int c0 = blockIdx.x * 32, r0 = blockIdx.y * 32;
    int x = threadIdx.x, y = threadIdx.y;   // block (32,8)
    #pragma unroll
    for (int i = y; i < 32; i += 8)
        tile[i][x] = s[(size_t)(r0 + i) * C + c0 + x];
    __syncthreads();
    #pragma unroll
    for (int i = y; i < 32; i += 8)
        d[(size_t)(c0 + i) * R + r0 + x] = tile[x][i];
}

// fp32 SIMT NT GEMM (R1-proven): C[M,N] = A[M,K] @ W[N,K]^T + bias
__global__ __launch_bounds__(256)
void gemm_nt(const float* __restrict__ A, const float* __restrict__ W,
             const float* __restrict__ bias, float* __restrict__ C,
             int M, int N, int K)
{
    __shared__ float As[16][68];
    __shared__ float Ws[16][68];
    const int tid = threadIdx.x;
    const int m0 = blockIdx.x * 64, n0 = blockIdx.y * 64;
    const int tx = tid & 15, ty = tid >> 4;
    float acc[4][4] = {};
    const int ar = tid >> 2;
    const int ak = (tid & 3) * 4;
    const float* Aptr = A + (size_t)(m0 + ar) * K + ak;
    const float* Wptr = W + (size_t)(n0 + ar) * K + ak;
    for (int k0 = 0; k0 < K; k0 += 16) {
        float4 av = *(const float4*)(Aptr + k0);
        float4 wv = *(const float4*)(Wptr + k0);
        As[ak+0][ar] = av.x; As[ak+1][ar] = av.y; As[ak+2][ar] = av.z; As[ak+3][ar] = av.w;
        Ws[ak+0][ar] = wv.x; Ws[ak+1][ar] = wv.y; Ws[ak+2][ar] = wv.z; Ws[ak+3][ar] = wv.w;
        __syncthreads();
        #pragma unroll
        for (int k = 0; k < 16; k++) {
            float4 a = *(const float4*)&As[k][ty*4];
            float4 w = *(const float4*)&Ws[k][tx*4];
            float avv[4] = {a.x, a.y, a.z, a.w};
            float wvv[4] = {w.x, w.y, w.z, w.w};
            #pragma unroll
            for (int i = 0; i < 4; i++)
                #pragma unroll
                for (int j = 0; j < 4; j++)
                    acc[i][j] += avv[i] * wvv[j];
        }
        __syncthreads();
    }
    #pragma unroll
    for (int i = 0; i < 4; i++) {
        int m = m0 + ty*4 + i;
        #pragma unroll
        for (int j = 0; j < 4; j++) {
            int n = n0 + tx*4 + j;
            C[(size_t)m * N + n] = acc[i][j] + bias[n];
        }
    }
}

// tvec[g] = dot(fc2_w[g,:], fc1_b) + fc2_b[g]
__global__ void compute_tvec(const float* __restrict__ fc2_w, const float* __restrict__ fc1_b,
                             const float* __restrict__ fc2_b, float* __restrict__ tvec)
{
    int g = (blockIdx.x * blockDim.x + threadIdx.x) >> 5;
    int lane = threadIdx.x & 31;
    if (g >= HID) return;
    const float* w = fc2_w + (size_t)g * DIM2;
    float s = 0.f;
    for (int d = lane; d < DIM2; d += 32) s += w[d] * fc1_b[d];
    #pragma unroll
    for (int o = 16; o; o >>= 1) s += __shfl_down_sync(0xffffffffu, s, o);
    if (!lane) tvec[g] = s + fc2_b[g];
}

// beff[g] = dot(w_ih[g,:], tvec) + b_ih[g]
__global__ void compute_beff(const float* __restrict__ w_ih, const float* __restrict__ tvec,
                             const float* __restrict__ b_ih, float* __restrict__ beff)
{
    int g = (blockIdx.x * blockDim.x + threadIdx.x) >> 5;
    int lane = threadIdx.x & 31;
    if (g >= G3) return;
    const float* w = w_ih + (size_t)g * HID;
    float s = 0.f;
    for (int d = lane; d < HID; d += 32) s += w[d] * tvec[d];
    #pragma unroll
    for (int o = 16; o; o >>= 1) s += __shfl_down_sync(0xffffffffu, s, o);
    if (!lane) beff[g] = s + b_ih[g];
}

// ======================= split / re-layout kernels =========================
__global__ void split_tiled(const float* __restrict__ s, half* __restrict__ dst,
                            int K, int n)
{
    int i = (blockIdx.x * blockDim.x + threadIdx.x) * 4;
    if (i >= n) return;
    int r = i / K, c = i % K;
    float4 v = *(const float4*)(s + i);
    half h[4], l[4];
    split2(v.x, h[0], l[0]); split2(v.y, h[1], l[1]);
    split2(v.z, h[2], l[2]); split2(v.w, h[3], l[3]);
    size_t base = (((size_t)(r >> 7) * (K >> 5) + (c >> 5)) * 2) * 5120
                + (size_t)(r & 127) * 40 + (c & 31);
    *(half2*)(dst + base)        = __halves2half2(h[0], h[1]);
    *(half2*)(dst + base + 2)    = __halves2half2(h[2], h[3]);
    *(half2*)(dst + base + 5120) = __halves2half2(l[0], l[1]);
    *(half2*)(dst + base + 5122) = __halves2half2(l[2], l[3]);
}

__global__ void split_whh_t(const float* __restrict__ s, half* __restrict__ dst)
{
    int i = (blockIdx.x * blockDim.x + threadIdx.x) * 4;
    int rw = i >> 10, c = i & 1023;
    int g = rw >> 10, j = rw & 1023;
    float4 v = *(const float4*)(s + i);
    half h[4], l[4];
    split2(v.x, h[0], l[0]); split2(v.y, h[1], l[1]);
    split2(v.z, h[2], l[2]); split2(v.w, h[3], l[3]);
    size_t base = (((size_t)(j >> 5) * 32 + (c >> 5)) * 2) * 3840
                + (size_t)(g * 32 + (j & 31)) * 40 + (c & 31);
    *(half2*)(dst + base)        = __halves2half2(h[0], h[1]);
    *(half2*)(dst + base + 2)    = __halves2half2(h[2], h[3]);
    *(half2*)(dst + base + 3840) = __halves2half2(l[0], l[1]);
    *(half2*)(dst + base + 3842) = __halves2half2(l[2], l[3]);
}

__global__ void split_h0_t(const float* __restrict__ s, float* __restrict__ f,
                           half* __restrict__ dst)
{
    int i = (blockIdx.x * blockDim.x + threadIdx.x) * 4;
    int r = i >> 10, c = i & 1023;
    float4 v = *(const float4*)(s + i);
    *(float4*)(f + i) = v;
    half h[4], l[4];
    split2(v.x, h[0], l[0]); split2(v.y, h[1], l[1]);
    split2(v.z, h[2], l[2]); split2(v.w, h[3], l[3]);
    size_t base = (((size_t)(r >> 6) * 32 + (c >> 5)) * 2) * 2560
                + (size_t)(r & 63) * 40 + (c & 31);
    *(half2*)(dst + base)        = __halves2half2(h[0], h[1]);
    *(half2*)(dst + base + 2)    = __halves2half2(h[2], h[3]);
    *(half2*)(dst + base + 2560) = __halves2half2(l[0], l[1]);
    *(half2*)(dst + base + 2562) = __halves2half2(l[2], l[3]);
}

__global__ void finalize_h(const float* __restrict__ hsrc, float* __restrict__ out_hn,
                           half* __restrict__ rht)
{
    int i = (blockIdx.x * blockDim.x + threadIdx.x) * 4;
    int r = i >> 10, c = i & 1023;
    float4 v = *(const float4*)(hsrc + i);
    *(float4*)(out_hn + i) = v;
    float rv[4] = { fmaxf(v.x,0.f), fmaxf(v.y,0.f), fmaxf(v.z,0.f), fmaxf(v.w,0.f) };
    half h[4], l[4];
    #pragma unroll
    for (int k = 0; k < 4; k++) split2(rv[k], h[k], l[k]);
    size_t base = (((size_t)(r >> 7) * 32 + (c >> 5)) * 2) * 5120
                + (size_t)(r & 127) * 40 + (c & 31);
    *(half2*)(rht + base)        = __halves2half2(h[0], h[1]);
    *(half2*)(rht + base + 2)    = __halves2half2(h[2], h[3]);
    *(half2*)(rht + base + 5120) = __halves2half2(l[0], l[1]);
    *(half2*)(rht + base + 5122) = __halves2half2(l[2], l[3]);
}

// ======================= bulk-pipelined fp16x3 GEMM ========================
// C[M,N] = (Ah+Al) @ (Wh+Wl)^T + bias. BM=BN=128, BK=32, 256 thr, 3-stage.
template<bool RELU, bool TRANS_OUT>
__global__ __launch_bounds__(256)
void gemm_h3b(const half* __restrict__ At, const half* __restrict__ Wt,
              const float* __restrict__ bias, float* __restrict__ C,
              int N, int KT)
{
    extern __shared__ __align__(16) half smem[];
    half* sA = smem;
    half* sW = smem + 3 * 10240;
    __shared__ __align__(8) unsigned long long mbar[3];

    const int tid = threadIdx.x, wid = tid >> 5, lane = tid & 31;
    const int n0 = blockIdx.x * 128, m0 = blockIdx.y * 128;
    const int wm = wid & 3, wn = wid >> 2;
    const half* Ab = At + (size_t)blockIdx.y * KT * 10240;
    const half* Wb = Wt + (size_t)blockIdx.x * KT * 10240;

    if (tid == 0)
        for (int s = 0; s < 3; s++) MBAR_INIT(saddr(&mbar[s]), 1);
    __syncthreads();
    if (tid == 0) {
        for (int s = 0; s < 2 && s < KT; s++) {
            EXPECT_TX(saddr(&mbar[s]), 40960);
            BULK_G2S(saddr(sA + s*10240), Ab + (size_t)s*10240, 20480, saddr(&mbar[s]));
            BULK_G2S(saddr(sW + s*10240), Wb + (size_t)s*10240, 20480, saddr(&mbar[s]));
        }
    }

    float acc[2][8][4] = {};
    const unsigned aOff = (unsigned)((wm*32 + (lane & 15)) * 80 + ((lane >> 4) & 1) * 16);
    const unsigned bOff = (unsigned)((wn*64 + (lane & 7) + ((lane >> 4) & 1) * 8) * 80
                                     + ((lane >> 3) & 1) * 16);
    const unsigned baseA = saddr(sA), baseW = saddr(sW);

    for (int kt = 0; kt < KT; kt++) {
        __syncthreads();
        if (tid == 0) {
            int ks = kt + 2;
            if (ks < KT) {
                int sl = ks % 3;
                EXPECT_TX(saddr(&mbar[sl]), 40960);
                BULK_G2S(saddr(sA + sl*10240), Ab + (size_t)ks*10240, 20480, saddr(&mbar[sl]));
                BULK_G2S(saddr(sW + sl*10240), Wb + (size_t)ks*10240, 20480, saddr(&mbar[sl]));
            }
        }
        const int slot = kt % 3, par = (kt / 3) & 1;
        MBWAIT(saddr(&mbar[slot]), par);

        const unsigned bAh = baseA + slot * 20480;
        const unsigned bAl = bAh + 10240;
        const unsigned bWh = baseW + slot * 20480;
        const unsigned bWl = bWh + 10240;

        #pragma unroll
        for (int kk = 0; kk < 2; kk++) {
            unsigned ah[2][4], al[2][4];
            #pragma unroll
            for (int mt = 0; mt < 2; mt++) {
                unsigned off = aOff + mt * (16*80) + kk * 32;
                ldsm4(ah[mt], bAh + off);
                ldsm4(al[mt], bAl + off);
            }
            #pragma unroll
            for (int p4 = 0; p4 < 4; p4++) {
                unsigned off = bOff + p4 * (16*80) + kk * 32;
                unsigned bh[4], bl[4];
                ldsm4(bh, bWh + off);
                ldsm4(bl, bWl + off);
                #pragma unroll
                for (int t2 = 0; t2 < 2; t2++) {
                    int nt = p4 * 2 + t2;
                    #pragma unroll
                    for (int mt = 0; mt < 2; mt++) {
                        mma16(acc[mt][nt], ah[mt], bh + t2*2);
                        mma16(acc[mt][nt], ah[mt], bl + t2*2);
                        mma16(acc[mt][nt], al[mt], bh + t2*2);
                    }
                }
            }
        }
    }

    #pragma unroll
    for (int mt = 0; mt < 2; mt++)
        #pragma unroll
        for (int nt = 0; nt < 8; nt++) {
            int n = n0 + wn*64 + nt*8 + (lane & 3) * 2;
            float bx = bias[n], by = bias[n + 1];
            #pragma unroll
            for (int h2 = 0; h2 < 2; h2++) {
                int m = m0 + wm*32 + mt*16 + (lane >> 2) + h2*8;
                float vx = acc[mt][nt][h2*2+0] + bx;
                float vy = acc[mt][nt][h2*2+1] + by;
                if (RELU) { vx = fmaxf(vx, 0.f); vy = fmaxf(vy, 0.f); }
                size_t row = TRANS_OUT ? ((size_t)(m & (T_SZ-1)) * B_SZ + (m >> 8))
                                       : (size_t)m;
                float2 v; v.x = vx; v.y = vy;
                *(float2*)(C + row * N + n) = v;
            }
        }
}

// ======================= bulk-pipelined GRU step (4-stage) ==================
// Grid (4, 32) = 128 blocks, 256 thr (8 warps: 4m x 2j).
__global__ __launch_bounds__(256)
void gru_step_b(const float* __restrict__ hf_in, const half* __restrict__ ht_in,
                float* __restrict__ hf_out, half* __restrict__ ht_out,
                const float* __restrict__ gi_t, const half* __restrict__ wt,
                const float* __restrict__ b_hh)
{
    extern __shared__ __align__(16) half smem[];
    half* sH = smem;                 // 4 * 5120 halves
    half* sW = smem + 4 * 5120;      // 4 * 7680 halves
    __shared__ __align__(8) unsigned long long mbar[4];

    const int tid = threadIdx.x, wid = tid >> 5, lane = tid & 31;
    const int m0 = blockIdx.x * 64, j0 = blockIdx.y * 32;
    const int wm = wid & 3, wj = wid >> 2;
    const half* Hb = ht_in + (size_t)blockIdx.x * 32 * 5120;
    const half* Wb = wt + (size_t)blockIdx.y * 32 * 7680;

    if (tid == 0)
        for (int s = 0; s < 4; s++) MBAR_INIT(saddr(&mbar[s]), 1);
    __syncthreads();
    if (tid == 0) {
        for (int s = 0; s < 3; s++) {
            EXPECT_TX(saddr(&mbar[s]), 25600);
            BULK_G2S(saddr(sH + s*5120), Hb + (size_t)s*5120, 10240, saddr(&mbar[s]));
            BULK_G2S(saddr(sW + s*7680), Wb + (size_t)s*7680, 15360, saddr(&mbar[s]));
        }
    }

    float acc[6][4] = {};
    const unsigned aOff = (unsigned)((wm*16 + (lane & 15)) * 80 + ((lane >> 4) & 1) * 16);
    const unsigned bOff = (unsigned)((wj*16 + (lane & 7) + ((lane >> 4) & 1) * 8) * 80
                                     + ((lane >> 3) & 1) * 16);
    const unsigned baseH = saddr(sH), baseW = saddr(sW);

    #pragma unroll 1
    for (int kt = 0; kt < 32; kt++) {
        __syncthreads();                 // all warps done with slot (kt-1)&3
        if (tid == 0) {
            int ks = kt + 3;
            if (ks < 32) {
                int sl = ks & 3;
                EXPECT_TX(saddr(&mbar[sl]), 25600);
                BULK_G2S(saddr(sH + sl*5120), Hb + (size_t)ks*5120, 10240, saddr(&mbar[sl]));
                BULK_G2S(saddr(sW + sl*7680), Wb + (size_t)ks*7680, 15360, saddr(&mbar[sl]));
            }
        }
        const int slot = kt & 3, par = (kt >> 2) & 1;
        MBWAIT(saddr(&mbar[slot]), par);

        const unsigned bHh = baseH + slot * 10240;
        const unsigned bHl = bHh + 5120;
        const unsigned bWh = baseW + slot * 15360;
        const unsigned bWl = bWh + 7680;

        #pragma unroll
        for (int kk = 0; kk < 2; kk++) {
            unsigned ah[4], al[4];
            ldsm4(ah, bHh + aOff + kk * 32);
            ldsm4(al, bHl + aOff + kk * 32);
            #pragma unroll
            for (int g = 0; g < 3; g++) {
                unsigned off = bOff + g * (32*80) + kk * 32;
                unsigned bh[4], bl[4];
                ldsm4(bh, bWh + off);
                ldsm4(bl, bWl + off);
                #pragma unroll
                for (int t2 = 0; t2 < 2; t2++) {
                    int nt = g * 2 + t2;
                    mma16(acc[nt], ah, bh + t2*2);
                    mma16(acc[nt], ah, bl + t2*2);
                    mma16(acc[nt], al, bh + t2*2);
                }
            }
        }
    }

    // gates + state update + tiled h_out write
    #pragma unroll
    for (int h2 = 0; h2 < 2; h2++) {
        int m = m0 + wm*16 + (lane >> 2) + h2*8;
        const float* gp = gi_t + (size_t)m * G3;
        #pragma unroll
        for (int t2 = 0; t2 < 2; t2++) {
            int jp = j0 + wj*16 + t2*8 + (lane & 3) * 2;
            float hnew[2];
            #pragma unroll
            for (int c = 0; c < 2; c++) {
                int j = jp + c;
                float hr  = acc[0*2+t2][h2*2+c] + b_hh[j];
                float hz  = acc[1*2+t2][h2*2+c] + b_hh[HID + j];
                float hnn = acc[2*2+t2][h2*2+c] + b_hh[2*HID + j];
                float r_ = 1.f / (1.f + expf(-(gp[j] + hr)));
                float z_ = 1.f / (1.f + expf(-(gp[HID + j] + hz)));
                float n_ = tanhf(gp[2*HID + j] + r_ * hnn);
                float hp = hf_in[(size_t)m * HID + j];
                hnew[c] = (1.f - z_) * n_ + z_ * hp;
            }
            float2 fv; fv.x = hnew[0]; fv.y = hnew[1];
            *(float2*)(hf_out + (size_t)m * HID + jp) = fv;
            half h0_, l0_, h1_, l1_;
            split2(hnew[0], h0_, l0_); split2(hnew[1], h1_, l1_);
            size_t tb = (((size_t)(m >> 6) * 32 + (jp >> 5)) * 2) * 2560
                      + (size_t)(m & 63) * 40 + (jp & 31);
            *(half2*)(ht_out + tb)        = __halves2half2(h0_, h1_);
            *(half2*)(ht_out + tb + 2560) = __halves2half2(l0_, l1_);
        }
    }
}

// ======================= tail ==============================================
__global__ __launch_bounds__(128)
void heads_kernel(const float* __restrict__ o3, const int* __restrict__ cult,
                  const float* __restrict__ hw, const float* __restrict__ hb,
                  float* __restrict__ outp)
{
    int b = blockIdx.x;
    int c = cult[b];
    __shared__ float sv[DIM2];
    for (int i = threadIdx.x; i < DIM2; i += blockDim.x)
        sv[i] = o3[(size_t)b * DIM2 + i];
    __syncthreads();
    int o = threadIdx.x >> 3, l = threadIdx.x & 7;
    const float* w = hw + ((size_t)c * OUT_DIM + o) * DIM2;
    float s = 0.f;
    for (int d = l; d < DIM2; d += 8) s += sv[d] * w[d];
    s += __shfl_down_sync(0xffffffffu, s, 4);
    s += __shfl_down_sync(0xffffffffu, s, 2);
    s += __shfl_down_sync(0xffffffffu, s, 1);
    if (l == 0) outp[b * OUT_DIM + o] = s + hb[c * OUT_DIM + o];
}

// ======================= launch ============================================
#define GEMM_SMEM (3*10240*2*2)            // 122880 B
#define GRU_SMEM  ((4*5120 + 4*7680)*2)    // 102400 B

extern "C" void kernel_launch(void* const* d_in, const int* in_sizes, int n_in,
                              void* d_out, int out_size)
{
    const float* input = (const float*)d_in[0];
    const float* hn    = (const float*)d_in[1];
    const int*   cult  = (const int*)  d_in[2];
    const float* fc1_w = (const float*)d_in[3];
    const float* fc1_b = (const float*)d_in[4];
    const float* fc2_w = (const float*)d_in[5];
    const float* fc2_b = (const float*)d_in[6];
    const float* w_ih  = (const float*)d_in[7];
    const float* w_hh  = (const float*)d_in[8];
    const float* b_ih  = (const float*)d_in[9];
    const float* b_hh  = (const float*)d_in[10];
    const float* fc3_w = (const float*)d_in[11];
    const float* fc3_b = (const float*)d_in[12];
    const float* hw    = (const float*)d_in[13];
    const float* hb    = (const float*)d_in[14];
    float* outp = (float*)d_out;

    float *gi, *o3, *hf, *dhf, *fc2T, *fc1T, *T1, *weff, *tvec, *beff, *zb;
    half *intl, *wefft, *w3t, *rht, *whht, *ht, *dht;
    cudaGetSymbolAddress((void**)&gi, g_gi);
    cudaGetSymbolAddress((void**)&o3, g_o3);
    cudaGetSymbolAddress((void**)&hf, g_hf);
    cudaGetSymbolAddress((void**)&dhf, g_dummy_hf);
    cudaGetSymbolAddress((void**)&fc2T, g_fc2T);
    cudaGetSymbolAddress((void**)&fc1T, g_fc1T);
    cudaGetSymbolAddress((void**)&T1, g_T1);
    cudaGetSymbolAddress((void**)&weff, g_weff);
    cudaGetSymbolAddress((void**)&tvec, g_tvec);
    cudaGetSymbolAddress((void**)&beff, g_beff);
    cudaGetSymbolAddress((void**)&zb, g_zbias);
    cudaGetSymbolAddress((void**)&intl, g_int);
    cudaGetSymbolAddress((void**)&wefft, g_wefft);
    cudaGetSymbolAddress((void**)&w3t, g_w3t);
    cudaGetSymbolAddress((void**)&rht, g_rht);
    cudaGetSymbolAddress((void**)&whht, g_whht);
    cudaGetSymbolAddress((void**)&ht, g_ht);
    cudaGetSymbolAddress((void**)&dht, g_dummy_ht);

    cudaFuncSetAttribute(gemm_h3b<false,true>,
                         cudaFuncAttributeMaxDynamicSharedMemorySize, GEMM_SMEM);
    cudaFuncSetAttribute(gemm_h3b<true,false>,
                         cudaFuncAttributeMaxDynamicSharedMemorySize, GEMM_SMEM);
    cudaFuncSetAttribute(gru_step_b,
                         cudaFuncAttributeMaxDynamicSharedMemorySize, GRU_SMEM);

    // ---- fold precompute: W_eff = w_ih @ fc2_w @ fc1_w, b_eff ----
    // launches 0-4
    transpose_f32<<<dim3(DIM2/32, HID/32), dim3(32,8)>>>(fc2_w, fc2T, HID, DIM2);
    transpose_f32<<<dim3(IN_DIM/32, DIM2/32), dim3(32,8)>>>(fc1_w, fc1T, DIM2, IN_DIM);
    gemm_nt<<<dim3(G3/64, DIM2/64), 256>>>(w_ih, fc2T, zb, T1, G3, DIM2, HID);
    gemm_nt<<<dim3(G3/64, IN_DIM/64), 256>>>(T1, fc1T, zb, weff, G3, IN_DIM, DIM2);
    compute_tvec<<<HID*32/256, 256>>>(fc2_w, fc1_b, fc2_b, tvec);

    // launch 5: DUMMY gru step for ncu (-s 5 -c 1); writes only to scratch
    gru_step_b<<<dim3(4, 32), 256, GRU_SMEM>>>(hf, ht, dhf, dht, gi, whht, b_hh);

    compute_beff<<<G3*32/256, 256>>>(w_ih, tvec, b_ih, beff);

    // splits
    split_tiled<<<MT*IN_DIM/1024, 256>>>(input, intl, IN_DIM, MT*IN_DIM);
    split_tiled<<<G3*IN_DIM/1024, 256>>>(weff, wefft, IN_DIM, G3*IN_DIM);
    split_tiled<<<DIM2*HID/1024, 256>>>(fc3_w, w3t, HID, DIM2*HID);
    split_whh_t<<<G3*HID/1024, 256>>>(w_hh, whht);
    split_h0_t<<<B_SZ*HID/1024, 256>>>(hn, hf, ht);

    // gi = input @ W_eff^T + b_eff, K=64 (KT=2), output [t][b][3H]
    gemm_h3b<false,true><<<dim3(G3/128, MT/128), 256, GEMM_SMEM>>>(
        intl, wefft, beff, gi, G3, IN_DIM/32);

    // GRU recurrence
    const size_t HS = (size_t)B_SZ * HID;
    const size_t HT = (size_t)4 * 32 * 5120;
    for (int t = 0; t < T_SZ; t++) {
        int a = t & 1, b = (t + 1) & 1;
        gru_step_b<<<dim3(4, 32), 256, GRU_SMEM>>>(
            hf + a*HS, ht + a*HT, hf + b*HS, ht + b*HT,
            gi + (size_t)t * B_SZ * G3, whht, b_hh);
    }
    float* hfin = hf + (T_SZ & 1) * HS;

    int hn_off = out_size - B_SZ * HID;
    finalize_h<<<B_SZ*HID/1024, 256>>>(hfin, outp + hn_off, rht);

    // fc3: relu(h) @ fc3_w^T, relu epilogue
    gemm_h3b<true,false><<<dim3(DIM2/128, B_SZ/128), 256, GEMM_SMEM>>>(
        rht, w3t, fc3_b, o3, DIM2, HID/32);

    heads_kernel<<<B_SZ, 128>>>(o3, cult, hw, hb, outp);
}

// round 10
// speedup vs baseline: 6.0552x; 1.2263x over previous
#include <cuda_runtime.h>
#include <cuda_fp16.h>
#include <math.h>

#define B_SZ 256
#define T_SZ 256
#define IN_DIM 64
#define HID 1024
#define DIM2 512
#define OUT_DIM 16
#define MT (B_SZ*T_SZ)   // 65536
#define G3 (3*HID)       // 3072

// ======================= scratch (device globals) ==========================
__device__ float g_gi[(size_t)MT*G3];       // 805 MB, layout [t][jt(64)][b(256)][48]
__device__ float g_hf[B_SZ*HID];            // final h (f32)
__device__ float g_o3[B_SZ*DIM2];
__device__ int   g_bar[2*T_SZ];             // per-(mt,step) barrier counters

// fold precompute scratch (fp32)
__device__ float g_fc2T[DIM2*HID];
__device__ float g_fc1T[IN_DIM*DIM2];
__device__ float g_T1[(size_t)G3*DIM2];
__device__ float g_weff[G3*IN_DIM];
__device__ float g_tvec[HID];
__device__ float g_beff[G3];
__device__ float g_zbias[DIM2];             // stays zero

// GEMM-geometry split tiles: [tile(128 rows)][stage(k/32)][plane(2)][128][40]
__device__ __align__(128) half g_int  [(size_t)512*2*10240];   // input (K=64)
__device__ __align__(128) half g_wefft[(size_t)24*2*10240];    // W_eff (K=64)
__device__ __align__(128) half g_w3t  [(size_t)4*32*10240];    // fc3_w (K=1024)
__device__ __align__(128) half g_rht  [(size_t)2*32*10240];    // relu(h)
// persistent-GRU weight layouts
__device__ __align__(128) half g_whhH[(size_t)64*32*1920];     // [jt][kt][48][40] hi
__device__ __align__(128) half g_whhL[(size_t)64*32*1280];     // [jt][kt][32][40] lo (z,n gates)
// h split-plane ping-pong: [buf(2)][mt(2)][kt(32)][plane(2)][128][40]
__device__ __align__(128) half g_hbuf[(size_t)2*2*32*2*128*40];

// ======================= PTX helpers =======================================
__device__ __forceinline__ unsigned saddr(const void* p) {
    return (unsigned)__cvta_generic_to_shared(p);
}
#define MBAR_INIT(mb, cnt) \
    asm volatile("mbarrier.init.shared.b64 [%0], %1;" :: "r"(mb), "r"(cnt) : "memory")
#define EXPECT_TX(mb, bytes) \
    asm volatile("mbarrier.arrive.expect_tx.shared.b64 _, [%0], %1;" :: "r"(mb), "r"(bytes) : "memory")
#define BULK_G2S(dst, src, bytes, mb) \
    asm volatile("cp.async.bulk.shared::cluster.global.mbarrier::complete_tx::bytes [%0], [%1], %2, [%3];" \
        :: "r"(dst), "l"(src), "r"(bytes), "r"(mb) : "memory")
#define MBWAIT(mb, ph) do { unsigned _d = 0; while (!_d) { \
    asm volatile("{\n\t.reg .pred p;\n\t" \
        "mbarrier.try_wait.parity.acquire.cta.shared::cta.b64 p, [%1], %2, 0x989680;\n\t" \
        "selp.b32 %0, 1, 0, p;\n\t}" \
        : "=r"(_d) : "r"(mb), "r"(ph)); } } while (0)

__device__ __forceinline__ void mma16(float* c, const unsigned* a, const unsigned* b) {
    asm volatile("mma.sync.aligned.m16n8k16.row.col.f32.f16.f16.f32 "
        "{%0,%1,%2,%3}, {%4,%5,%6,%7}, {%8,%9}, {%0,%1,%2,%3};"
        : "+f"(c[0]), "+f"(c[1]), "+f"(c[2]), "+f"(c[3])
        : "r"(a[0]), "r"(a[1]), "r"(a[2]), "r"(a[3]), "r"(b[0]), "r"(b[1]));
}
__device__ __forceinline__ void ldsm4(unsigned* r, unsigned addr) {
    asm volatile("ldmatrix.sync.aligned.m8n8.x4.shared.b16 {%0,%1,%2,%3}, [%4];"
        : "=r"(r[0]), "=r"(r[1]), "=r"(r[2]), "=r"(r[3]) : "r"(addr));
}
__device__ __forceinline__ void split2(float x, half& hi, half& lo) {
    hi = __float2half_rn(x);
    lo = __float2half_rn(x - __half2float(hi));
}

// ======================= fold precompute kernels ===========================
__global__ void transpose_f32(const float* __restrict__ s, float* __restrict__ d,
                              int R, int C)
{
    __shared__ float tile[32][33];
    int c0 = blockIdx.x * 32, r0 = blockIdx.y * 32;
    int x = threadIdx.x, y = threadIdx.y;
    #pragma unroll
    for (int i = y; i < 32; i += 8)
        tile[i][x] = s[(size_t)(r0 + i) * C + c0 + x];
    __syncthreads();
    #pragma unroll
    for (int i = y; i < 32; i += 8)
        d[(size_t)(c0 + i) * R + r0 + x] = tile[x][i];
}

__global__ __launch_bounds__(256)
void gemm_nt(const float* __restrict__ A, const float* __restrict__ W,
             const float* __restrict__ bias, float* __restrict__ C,
             int M, int N, int K)
{
    __shared__ float As[16][68];
    __shared__ float Ws[16][68];
    const int tid = threadIdx.x;
    const int m0 = blockIdx.x * 64, n0 = blockIdx.y * 64;
    const int tx = tid & 15, ty = tid >> 4;
    float acc[4][4] = {};
    const int ar = tid >> 2;
    const int ak = (tid & 3) * 4;
    const float* Aptr = A + (size_t)(m0 + ar) * K + ak;
    const float* Wptr = W + (size_t)(n0 + ar) * K + ak;
    for (int k0 = 0; k0 < K; k0 += 16) {
        float4 av = *(const float4*)(Aptr + k0);
        float4 wv = *(const float4*)(Wptr + k0);
        As[ak+0][ar] = av.x; As[ak+1][ar] = av.y; As[ak+2][ar] = av.z; As[ak+3][ar] = av.w;
        Ws[ak+0][ar] = wv.x; Ws[ak+1][ar] = wv.y; Ws[ak+2][ar] = wv.z; Ws[ak+3][ar] = wv.w;
        __syncthreads();
        #pragma unroll
        for (int k = 0; k < 16; k++) {
            float4 a = *(const float4*)&As[k][ty*4];
            float4 w = *(const float4*)&Ws[k][tx*4];
            float avv[4] = {a.x, a.y, a.z, a.w};
            float wvv[4] = {w.x, w.y, w.z, w.w};
            #pragma unroll
            for (int i = 0; i < 4; i++)
                #pragma unroll
                for (int j = 0; j < 4; j++)
                    acc[i][j] += avv[i] * wvv[j];
        }
        __syncthreads();
    }
    #pragma unroll
    for (int i = 0; i < 4; i++) {
        int m = m0 + ty*4 + i;
        #pragma unroll
        for (int j = 0; j < 4; j++) {
            int n = n0 + tx*4 + j;
            C[(size_t)m * N + n] = acc[i][j] + bias[n];
        }
    }
}

__global__ void compute_tvec(const float* __restrict__ fc2_w, const float* __restrict__ fc1_b,
                             const float* __restrict__ fc2_b, float* __restrict__ tvec)
{
    int g = (blockIdx.x * blockDim.x + threadIdx.x) >> 5;
    int lane = threadIdx.x & 31;
    if (g >= HID) return;
    const float* w = fc2_w + (size_t)g * DIM2;
    float s = 0.f;
    for (int d = lane; d < DIM2; d += 32) s += w[d] * fc1_b[d];
    #pragma unroll
    for (int o = 16; o; o >>= 1) s += __shfl_down_sync(0xffffffffu, s, o);
    if (!lane) tvec[g] = s + fc2_b[g];
}

__global__ void compute_beff(const float* __restrict__ w_ih, const float* __restrict__ tvec,
                             const float* __restrict__ b_ih, float* __restrict__ beff)
{
    int g = (blockIdx.x * blockDim.x + threadIdx.x) >> 5;
    int lane = threadIdx.x & 31;
    if (g >= G3) return;
    const float* w = w_ih + (size_t)g * HID;
    float s = 0.f;
    for (int d = lane; d < HID; d += 32) s += w[d] * tvec[d];
    #pragma unroll
    for (int o = 16; o; o >>= 1) s += __shfl_down_sync(0xffffffffu, s, o);
    if (!lane) beff[g] = s + b_ih[g];
}

__global__ void zero_bar(int* __restrict__ bar)
{
    bar[threadIdx.x] = 0;
}

// ======================= split / re-layout kernels =========================
__global__ void split_tiled(const float* __restrict__ s, half* __restrict__ dst,
                            int K, int n)
{
    int i = (blockIdx.x * blockDim.x + threadIdx.x) * 4;
    if (i >= n) return;
    int r = i / K, c = i % K;
    float4 v = *(const float4*)(s + i);
    half h[4], l[4];
    split2(v.x, h[0], l[0]); split2(v.y, h[1], l[1]);
    split2(v.z, h[2], l[2]); split2(v.w, h[3], l[3]);
    size_t base = (((size_t)(r >> 7) * (K >> 5) + (c >> 5)) * 2) * 5120
                + (size_t)(r & 127) * 40 + (c & 31);
    *(half2*)(dst + base)        = __halves2half2(h[0], h[1]);
    *(half2*)(dst + base + 2)    = __halves2half2(h[2], h[3]);
    *(half2*)(dst + base + 5120) = __halves2half2(l[0], l[1]);
    *(half2*)(dst + base + 5122) = __halves2half2(l[2], l[3]);
}

// w_hh -> persistent layouts: hi [jt][kt][48][40]; lo (z,n) [jt][kt][32][40]
__global__ void split_whh_hl(const float* __restrict__ s, half* __restrict__ dh,
                             half* __restrict__ dl)
{
    int i = (blockIdx.x * blockDim.x + threadIdx.x) * 4;
    int rw = i >> 10, c = i & 1023;
    int g = rw >> 10, j = rw & 1023;
    int jt = j >> 4, jr = j & 15, kt = c >> 5, kc = c & 31;
    float4 v = *(const float4*)(s + i);
    half h[4], l[4];
    split2(v.x, h[0], l[0]); split2(v.y, h[1], l[1]);
    split2(v.z, h[2], l[2]); split2(v.w, h[3], l[3]);
    size_t hb = ((size_t)jt * 32 + kt) * 1920 + (size_t)(g * 16 + jr) * 40 + kc;
    *(half2*)(dh + hb)     = __halves2half2(h[0], h[1]);
    *(half2*)(dh + hb + 2) = __halves2half2(h[2], h[3]);
    if (g >= 1) {
        size_t lb = ((size_t)jt * 32 + kt) * 1280 + (size_t)((g - 1) * 16 + jr) * 40 + kc;
        *(half2*)(dl + lb)     = __halves2half2(l[0], l[1]);
        *(half2*)(dl + lb + 2) = __halves2half2(l[2], l[3]);
    }
}

// h0 -> g_hbuf buffer 0: [mt][kt][plane][128][40]
__global__ void split_h0_b(const float* __restrict__ s, half* __restrict__ hbuf)
{
    int i = (blockIdx.x * blockDim.x + threadIdx.x) * 4;
    int r = i >> 10, c = i & 1023;
    int mt = r >> 7, rl = r & 127, kt = c >> 5, kc = c & 31;
    float4 v = *(const float4*)(s + i);
    half h[4], l[4];
    split2(v.x, h[0], l[0]); split2(v.y, h[1], l[1]);
    split2(v.z, h[2], l[2]); split2(v.w, h[3], l[3]);
    size_t base = (((size_t)mt * 32 + kt) * 2) * 5120 + (size_t)rl * 40 + kc;
    *(half2*)(hbuf + base)        = __halves2half2(h[0], h[1]);
    *(half2*)(hbuf + base + 2)    = __halves2half2(h[2], h[3]);
    *(half2*)(hbuf + base + 5120) = __halves2half2(l[0], l[1]);
    *(half2*)(hbuf + base + 5122) = __halves2half2(l[2], l[3]);
}

// final h -> hn_out f32 + relu(h) GEMM-A tiled (K=1024)
__global__ void finalize_h(const float* __restrict__ hsrc, float* __restrict__ out_hn,
                           half* __restrict__ rht)
{
    int i = (blockIdx.x * blockDim.x + threadIdx.x) * 4;
    int r = i >> 10, c = i & 1023;
    float4 v = *(const float4*)(hsrc + i);
    *(float4*)(out_hn + i) = v;
    float rv[4] = { fmaxf(v.x,0.f), fmaxf(v.y,0.f), fmaxf(v.z,0.f), fmaxf(v.w,0.f) };
    half h[4], l[4];
    #pragma unroll
    for (int k = 0; k < 4; k++) split2(rv[k], h[k], l[k]);
    size_t base = (((size_t)(r >> 7) * 32 + (c >> 5)) * 2) * 5120
                + (size_t)(r & 127) * 40 + (c & 31);
    *(half2*)(rht + base)        = __halves2half2(h[0], h[1]);
    *(half2*)(rht + base + 2)    = __halves2half2(h[2], h[3]);
    *(half2*)(rht + base + 5120) = __halves2half2(l[0], l[1]);
    *(half2*)(rht + base + 5122) = __halves2half2(l[2], l[3]);
}

// single extern dynamic-smem declaration for ALL kernels
extern __shared__ __align__(16) unsigned char dynsmem[];

// ======================= bulk-pipelined fp16x3 GEMM ========================
// C = (Ah+Al)@(Wh+Wl)^T + bias. BM=BN=128, BK=32, 256 thr, 3-stage.
// GILAYOUT: write to gi layout [t][jt][b][48] (m = b*256+t, n = g*1024+j).
template<bool RELU, bool GILAYOUT>
__global__ __launch_bounds__(256)
void gemm_h3b(const half* __restrict__ At, const half* __restrict__ Wt,
              const float* __restrict__ bias, float* __restrict__ C,
              int N, int KT)
{
    half* sA = (half*)dynsmem;
    half* sW = (half*)dynsmem + 3 * 10240;
    __shared__ __align__(8) unsigned long long mbar[3];

    const int tid = threadIdx.x, wid = tid >> 5, lane = tid & 31;
    const int n0 = blockIdx.x * 128, m0 = blockIdx.y * 128;
    const int wm = wid & 3, wn = wid >> 2;
    const half* Ab = At + (size_t)blockIdx.y * KT * 10240;
    const half* Wb = Wt + (size_t)blockIdx.x * KT * 10240;

    if (tid == 0)
        for (int s = 0; s < 3; s++) MBAR_INIT(saddr(&mbar[s]), 1);
    __syncthreads();
    if (tid == 0) {
        for (int s = 0; s < 2 && s < KT; s++) {
            EXPECT_TX(saddr(&mbar[s]), 40960);
            BULK_G2S(saddr(sA + s*10240), Ab + (size_t)s*10240, 20480, saddr(&mbar[s]));
            BULK_G2S(saddr(sW + s*10240), Wb + (size_t)s*10240, 20480, saddr(&mbar[s]));
        }
    }

    float acc[2][8][4] = {};
    const unsigned aOff = (unsigned)((wm*32 + (lane & 15)) * 80 + ((lane >> 4) & 1) * 16);
    const unsigned bOff = (unsigned)((wn*64 + (lane & 7) + ((lane >> 4) & 1) * 8) * 80
                                     + ((lane >> 3) & 1) * 16);
    const unsigned baseA = saddr(sA), baseW = saddr(sW);

    for (int kt = 0; kt < KT; kt++) {
        __syncthreads();
        if (tid == 0) {
            int ks = kt + 2;
            if (ks < KT) {
                int sl = ks % 3;
                EXPECT_TX(saddr(&mbar[sl]), 40960);
                BULK_G2S(saddr(sA + sl*10240), Ab + (size_t)ks*10240, 20480, saddr(&mbar[sl]));
                BULK_G2S(saddr(sW + sl*10240), Wb + (size_t)ks*10240, 20480, saddr(&mbar[sl]));
            }
        }
        const int slot = kt % 3, par = (kt / 3) & 1;
        MBWAIT(saddr(&mbar[slot]), par);

        const unsigned bAh = baseA + slot * 20480;
        const unsigned bAl = bAh + 10240;
        const unsigned bWh = baseW + slot * 20480;
        const unsigned bWl = bWh + 10240;

        #pragma unroll
        for (int kk = 0; kk < 2; kk++) {
            unsigned ah[2][4], al[2][4];
            #pragma unroll
            for (int mt = 0; mt < 2; mt++) {
                unsigned off = aOff + mt * (16*80) + kk * 32;
                ldsm4(ah[mt], bAh + off);
                ldsm4(al[mt], bAl + off);
            }
            #pragma unroll
            for (int p4 = 0; p4 < 4; p4++) {
                unsigned off = bOff + p4 * (16*80) + kk * 32;
                unsigned bh[4], bl[4];
                ldsm4(bh, bWh + off);
                ldsm4(bl, bWl + off);
                #pragma unroll
                for (int t2 = 0; t2 < 2; t2++) {
                    int nt = p4 * 2 + t2;
                    #pragma unroll
                    for (int mt = 0; mt < 2; mt++) {
                        mma16(acc[mt][nt], ah[mt], bh + t2*2);
                        mma16(acc[mt][nt], ah[mt], bl + t2*2);
                        mma16(acc[mt][nt], al[mt], bh + t2*2);
                    }
                }
            }
        }
    }

    #pragma unroll
    for (int mt = 0; mt < 2; mt++)
        #pragma unroll
        for (int nt = 0; nt < 8; nt++) {
            int n = n0 + wn*64 + nt*8 + (lane & 3) * 2;
            float bx = bias[n], by = bias[n + 1];
            #pragma unroll
            for (int h2 = 0; h2 < 2; h2++) {
                int m = m0 + wm*32 + mt*16 + (lane >> 2) + h2*8;
                float vx = acc[mt][nt][h2*2+0] + bx;
                float vy = acc[mt][nt][h2*2+1] + by;
                if (RELU) { vx = fmaxf(vx, 0.f); vy = fmaxf(vy, 0.f); }
                float2 v; v.x = vx; v.y = vy;
                if (GILAYOUT) {
                    int b = m >> 8, tt = m & 255;
                    int g = n >> 10, j = n & 1023;
                    size_t addr = (((size_t)tt * 64 + (j >> 4)) * 256 + b) * 48
                                + g * 16 + (j & 15);
                    *(float2*)(C + addr) = v;
                } else {
                    *(float2*)(C + (size_t)m * N + n) = v;
                }
            }
        }
}

// ======================= persistent GRU kernel ==============================
// Grid (jt=64, mt=2) = 128 blocks, 256 thr (8 warps; warp w = m rows w*16..+16,
// all 48 gate-cols of this block's 16-j tile). One launch covers all 256 steps.
// SMEM: W_hi resident [kt32][48][40] (122880B) | 3 stages (H 20480 + Wlo(z,n) 2560)
//       | gi chunk [128][48] f32 (24576B).
#define STG_SZ   23040
#define OFF_STG  122880
#define OFF_GI   (122880 + 3*STG_SZ)        // 192000
#define PERS_SMEM (OFF_GI + 24576)          // 216576

__global__ __launch_bounds__(256)
void gru_persist(const float* __restrict__ hn,
                 const half* __restrict__ whhH, const half* __restrict__ whhL,
                 const float* __restrict__ gi2, const float* __restrict__ b_hh,
                 half* __restrict__ hbuf, float* __restrict__ hf_final,
                 int* __restrict__ bar)
{
    __shared__ __align__(8) unsigned long long mbar[5];
    const unsigned sb = saddr(dynsmem);
    const int tid = threadIdx.x, w = tid >> 5, lane = tid & 31;
    const int jt = blockIdx.x, mt = blockIdx.y;

    if (tid == 0)
        for (int i = 0; i < 5; i++) MBAR_INIT(saddr(&mbar[i]), 1);
    __syncthreads();
    const unsigned mbW = saddr(&mbar[0]);
    const unsigned mbS = saddr(&mbar[1]);   // +8*s
    const unsigned mbG = saddr(&mbar[4]);

    // resident W_hi load (once)
    if (tid == 0) {
        EXPECT_TX(mbW, 122880);
        BULK_G2S(sb, (const char*)whhH + (size_t)jt * 122880, 122880, mbW);
    }

    // per-thread output coordinates
    const int mrow = w * 16 + (lane >> 2);        // + h2*8
    const int jl0  = (lane & 3) * 2;              // + t2*8 (+c)
    float hprev[8];
    float bb[12];
    #pragma unroll
    for (int h2 = 0; h2 < 2; h2++)
        #pragma unroll
        for (int t2 = 0; t2 < 2; t2++) {
            int m = mt*128 + mrow + h2*8;
            int j = jt*16 + t2*8 + jl0;
            float2 hv = *(const float2*)(hn + (size_t)m * HID + j);
            hprev[h2*4 + t2*2 + 0] = hv.x;
            hprev[h2*4 + t2*2 + 1] = hv.y;
        }
    #pragma unroll
    for (int g = 0; g < 3; g++)
        #pragma unroll
        for (int t2 = 0; t2 < 2; t2++) {
            float2 bv = *(const float2*)(b_hh + g*HID + jt*16 + t2*8 + jl0);
            bb[g*4 + t2*2 + 0] = bv.x;
            bb[g*4 + t2*2 + 1] = bv.y;
        }

    const unsigned aOff = (unsigned)((w*16 + (lane & 15)) * 80 + ((lane >> 4) & 1) * 16);
    const unsigned bOff = (unsigned)(((lane & 7) + ((lane >> 4) & 1) * 8) * 80
                                     + ((lane >> 3) & 1) * 16);

    int us0 = 0, us1 = 0, us2 = 0;   // per-slot use counters (parity)
    MBWAIT(mbW, 0);

    for (int t = 0; t < T_SZ; t++) {
        const char* Hb = (const char*)hbuf
            + (((size_t)(t & 1) * 2 + mt) * 32) * 20480;
        const char* Lb = (const char*)whhL + (size_t)jt * 32 * 2560;
        if (tid == 0) {
            EXPECT_TX(mbG, 24576);
            BULK_G2S(sb + OFF_GI,
                     (const char*)gi2 + ((((size_t)t * 64 + jt) * 256 + mt*128) * 48) * 4,
                     24576, mbG);
            #pragma unroll
            for (int s = 0; s < 3; s++) {
                EXPECT_TX(mbS + 8*s, STG_SZ);
                BULK_G2S(sb + OFF_STG + s*STG_SZ,         Hb + (size_t)s*20480, 20480, mbS + 8*s);
                BULK_G2S(sb + OFF_STG + s*STG_SZ + 20480, Lb + (size_t)s*2560,  2560,  mbS + 8*s);
            }
        }

        float acc[6][4] = {};
        int slot = 0;
        for (int kt = 0; kt < 32; kt++) {
            int par;
            if (slot == 0)      { par = us0 & 1; us0++; }
            else if (slot == 1) { par = us1 & 1; us1++; }
            else                { par = us2 & 1; us2++; }
            MBWAIT(mbS + 8*slot, par);

            const unsigned hHi = sb + OFF_STG + slot*STG_SZ;
            const unsigned hLo = hHi + 10240;
            const unsigned wLo = hHi + 20480;
            const unsigned wHi = sb + kt * 3840;

            #pragma unroll
            for (int kk = 0; kk < 2; kk++) {
                unsigned ah[4], al[4];
                ldsm4(ah, hHi + aOff + kk*32);
                ldsm4(al, hLo + aOff + kk*32);
                unsigned br[4], bz[4], bn[4], blz[4], bln[4];
                ldsm4(br,  wHi + bOff + kk*32);
                ldsm4(bz,  wHi + bOff + 16*80 + kk*32);
                ldsm4(bn,  wHi + bOff + 32*80 + kk*32);
                ldsm4(blz, wLo + bOff + kk*32);
                ldsm4(bln, wLo + bOff + 16*80 + kk*32);
                #pragma unroll
                for (int t2 = 0; t2 < 2; t2++) {
                    // r gate: 2-term (W hi only)
                    mma16(acc[0+t2], ah, br + t2*2);
                    mma16(acc[0+t2], al, br + t2*2);
                    // z gate: 3-term
                    mma16(acc[2+t2], ah, bz + t2*2);
                    mma16(acc[2+t2], al, bz + t2*2);
                    mma16(acc[2+t2], ah, blz + t2*2);
                    // n gate: 3-term
                    mma16(acc[4+t2], ah, bn + t2*2);
                    mma16(acc[4+t2], al, bn + t2*2);
                    mma16(acc[4+t2], ah, bln + t2*2);
                }
            }
            __syncthreads();
            if (tid == 0 && kt + 3 < 32) {
                int ks = kt + 3;
                EXPECT_TX(mbS + 8*slot, STG_SZ);
                BULK_G2S(sb + OFF_STG + slot*STG_SZ,         Hb + (size_t)ks*20480, 20480, mbS + 8*slot);
                BULK_G2S(sb + OFF_STG + slot*STG_SZ + 20480, Lb + (size_t)ks*2560,  2560,  mbS + 8*slot);
            }
            slot = (slot == 2) ? 0 : slot + 1;
        }

        // epilogue: gates + state update
        MBWAIT(mbG, t & 1);
        const float* gis = (const float*)(dynsmem + OFF_GI);
        char* ob = (char*)hbuf
            + ((((size_t)((t+1) & 1) * 2 + mt) * 32 + (jt >> 1))) * 20480;
        const int kc0 = (jt & 1) * 16;

        #pragma unroll
        for (int h2 = 0; h2 < 2; h2++) {
            int ml = mrow + h2*8;
            #pragma unroll
            for (int t2 = 0; t2 < 2; t2++) {
                float hh[2];
                #pragma unroll
                for (int c = 0; c < 2; c++) {
                    int fi = h2*2 + c;
                    int jl = t2*8 + jl0 + c;
                    float rpre = acc[0+t2][fi] + bb[0 + t2*2 + c] + gis[ml*48 + jl];
                    float zpre = acc[2+t2][fi] + bb[4 + t2*2 + c] + gis[ml*48 + 16 + jl];
                    float hnn  = acc[4+t2][fi] + bb[8 + t2*2 + c];
                    float r_ = 1.f / (1.f + expf(-rpre));
                    float z_ = 1.f / (1.f + expf(-zpre));
                    float n_ = tanhf(gis[ml*48 + 32 + jl] + r_ * hnn);
                    int pi = h2*4 + t2*2 + c;
                    float hv = (1.f - z_) * n_ + z_ * hprev[pi];
                    hprev[pi] = hv;
                    hh[c] = hv;
                }
                half a0, b0, a1, b1;
                split2(hh[0], a0, b0);
                split2(hh[1], a1, b1);
                int kc = kc0 + t2*8 + jl0;
                *(half2*)(ob + (size_t)ml*80 + kc*2)         = __halves2half2(a0, a1);
                *(half2*)(ob + 10240 + (size_t)ml*80 + kc*2) = __halves2half2(b0, b1);
                if (t == T_SZ - 1) {
                    float2 fv; fv.x = hh[0]; fv.y = hh[1];
                    *(float2*)(hf_final + (size_t)(mt*128 + ml) * HID
                               + jt*16 + t2*8 + jl0) = fv;
                }
            }
        }

        // inter-step barrier (per m-group of 64 blocks)
        if (t < T_SZ - 1) {
            __threadfence();
            __syncthreads();
            if (tid == 0) {
                int* cnt = bar + mt * T_SZ + t;
                atomicAdd(cnt, 1);
                while (atomicAdd(cnt, 0) < 64) { }
            }
            __syncthreads();
        }
    }
}

// ======================= tail ==============================================
__global__ __launch_bounds__(128)
void heads_kernel(const float* __restrict__ o3, const int* __restrict__ cult,
                  const float* __restrict__ hw, const float* __restrict__ hb,
                  float* __restrict__ outp)
{
    int b = blockIdx.x;
    int c = cult[b];
    __shared__ float sv[DIM2];
    for (int i = threadIdx.x; i < DIM2; i += blockDim.x)
        sv[i] = o3[(size_t)b * DIM2 + i];
    __syncthreads();
    int o = threadIdx.x >> 3, l = threadIdx.x & 7;
    const float* w = hw + ((size_t)c * OUT_DIM + o) * DIM2;
    float s = 0.f;
    for (int d = l; d < DIM2; d += 8) s += sv[d] * w[d];
    s += __shfl_down_sync(0xffffffffu, s, 4);
    s += __shfl_down_sync(0xffffffffu, s, 2);
    s += __shfl_down_sync(0xffffffffu, s, 1);
    if (l == 0) outp[b * OUT_DIM + o] = s + hb[c * OUT_DIM + o];
}

// ======================= launch ============================================
#define GEMM_SMEM (3*10240*2*2)   // 122880 B

extern "C" void kernel_launch(void* const* d_in, const int* in_sizes, int n_in,
                              void* d_out, int out_size)
{
    const float* input = (const float*)d_in[0];
    const float* hn    = (const float*)d_in[1];
    const int*   cult  = (const int*)  d_in[2];
    const float* fc1_w = (const float*)d_in[3];
    const float* fc1_b = (const float*)d_in[4];
    const float* fc2_w = (const float*)d_in[5];
    const float* fc2_b = (const float*)d_in[6];
    const float* w_ih  = (const float*)d_in[7];
    const float* w_hh  = (const float*)d_in[8];
    const float* b_ih  = (const float*)d_in[9];
    const float* b_hh  = (const float*)d_in[10];
    const float* fc3_w = (const float*)d_in[11];
    const float* fc3_b = (const float*)d_in[12];
    const float* hw    = (const float*)d_in[13];
    const float* hb    = (const float*)d_in[14];
    float* outp = (float*)d_out;

    float *gi, *o3, *hf, *fc2T, *fc1T, *T1, *weff, *tvec, *beff, *zb;
    int* bar;
    half *intl, *wefft, *w3t, *rht, *whhH, *whhL, *hbuf;
    cudaGetSymbolAddress((void**)&gi, g_gi);
    cudaGetSymbolAddress((void**)&o3, g_o3);
    cudaGetSymbolAddress((void**)&hf, g_hf);
    cudaGetSymbolAddress((void**)&bar, g_bar);
    cudaGetSymbolAddress((void**)&fc2T, g_fc2T);
    cudaGetSymbolAddress((void**)&fc1T, g_fc1T);
    cudaGetSymbolAddress((void**)&T1, g_T1);
    cudaGetSymbolAddress((void**)&weff, g_weff);
    cudaGetSymbolAddress((void**)&tvec, g_tvec);
    cudaGetSymbolAddress((void**)&beff, g_beff);
    cudaGetSymbolAddress((void**)&zb, g_zbias);
    cudaGetSymbolAddress((void**)&intl, g_int);
    cudaGetSymbolAddress((void**)&wefft, g_wefft);
    cudaGetSymbolAddress((void**)&w3t, g_w3t);
    cudaGetSymbolAddress((void**)&rht, g_rht);
    cudaGetSymbolAddress((void**)&whhH, g_whhH);
    cudaGetSymbolAddress((void**)&whhL, g_whhL);
    cudaGetSymbolAddress((void**)&hbuf, g_hbuf);

    cudaFuncSetAttribute(gemm_h3b<false,true>,
                         cudaFuncAttributeMaxDynamicSharedMemorySize, GEMM_SMEM);
    cudaFuncSetAttribute(gemm_h3b<true,false>,
                         cudaFuncAttributeMaxDynamicSharedMemorySize, GEMM_SMEM);
    cudaFuncSetAttribute(gru_persist,
                         cudaFuncAttributeMaxDynamicSharedMemorySize, PERS_SMEM);

    // fold precompute: W_eff = w_ih @ fc2_w @ fc1_w, b_eff
    transpose_f32<<<dim3(DIM2/32, HID/32), dim3(32,8)>>>(fc2_w, fc2T, HID, DIM2);
    transpose_f32<<<dim3(IN_DIM/32, DIM2/32), dim3(32,8)>>>(fc1_w, fc1T, DIM2, IN_DIM);
    gemm_nt<<<dim3(G3/64, DIM2/64), 256>>>(w_ih, fc2T, zb, T1, G3, DIM2, HID);
    gemm_nt<<<dim3(G3/64, IN_DIM/64), 256>>>(T1, fc1T, zb, weff, G3, IN_DIM, DIM2);
    compute_tvec<<<HID*32/256, 256>>>(fc2_w, fc1_b, fc2_b, tvec);
    compute_beff<<<G3*32/256, 256>>>(w_ih, tvec, b_ih, beff);
    zero_bar<<<1, 2*T_SZ>>>(bar);

    // splits
    split_tiled<<<MT*IN_DIM/1024, 256>>>(input, intl, IN_DIM, MT*IN_DIM);
    split_tiled<<<G3*IN_DIM/1024, 256>>>(weff, wefft, IN_DIM, G3*IN_DIM);
    split_tiled<<<DIM2*HID/1024, 256>>>(fc3_w, w3t, HID, DIM2*HID);
    split_whh_hl<<<G3*HID/1024, 256>>>(w_hh, whhH, whhL);
    split_h0_b<<<B_SZ*HID/1024, 256>>>(hn, hbuf);

    // gi = input @ W_eff^T + b_eff, K=64, layout [t][jt][b][48]
    gemm_h3b<false,true><<<dim3(G3/128, MT/128), 256, GEMM_SMEM>>>(
        intl, wefft, beff, gi, G3, IN_DIM/32);

    // persistent GRU: one launch, 256 steps
    gru_persist<<<dim3(64, 2), 256, PERS_SMEM>>>(
        hn, whhH, whhL, gi, b_hh, hbuf, hf, bar);

    int hn_off = out_size - B_SZ * HID;
    finalize_h<<<B_SZ*HID/1024, 256>>>(hf, outp + hn_off, rht);

    // fc3: relu(h) @ fc3_w^T, relu epilogue
    gemm_h3b<true,false><<<dim3(DIM2/128, B_SZ/128), 256, GEMM_SMEM>>>(
        rht, w3t, fc3_b, o3, DIM2, HID/32);

    heads_kernel<<<B_SZ, 128>>>(o3, cult, hw, hb, outp);
}

// round 11
// speedup vs baseline: 6.0818x; 1.0044x over previous
#include <cuda_runtime.h>
#include <cuda_fp16.h>
#include <math.h>

#define B_SZ 256
#define T_SZ 256
#define IN_DIM 64
#define HID 1024
#define DIM2 512
#define OUT_DIM 16
#define MT (B_SZ*T_SZ)   // 65536
#define G3 (3*HID)       // 3072

// ======================= scratch (device globals) ==========================
__device__ float g_gi[(size_t)MT*G3];       // 805 MB, layout [t][jt(64)][b(256)][48]
__device__ float g_hf[B_SZ*HID];            // final h (f32)
__device__ float g_o3[B_SZ*DIM2];
__device__ int   g_bar[2*T_SZ];             // per-(mt,step) barrier counters

// fold precompute scratch (fp32)
__device__ float g_fc2T[DIM2*HID];
__device__ float g_fc1T[IN_DIM*DIM2];
__device__ float g_T1[(size_t)G3*DIM2];
__device__ float g_weff[G3*IN_DIM];
__device__ float g_tvec[HID];
__device__ float g_beff[G3];
__device__ float g_zbias[DIM2];             // stays zero

// GEMM-geometry split tiles: [tile(128 rows)][stage(k/32)][plane(2)][128][40]
__device__ __align__(128) half g_int  [(size_t)512*2*10240];   // input (K=64)
__device__ __align__(128) half g_wefft[(size_t)24*2*10240];    // W_eff (K=64)
__device__ __align__(128) half g_w3t  [(size_t)4*32*10240];    // fc3_w (K=1024)
__device__ __align__(128) half g_rht  [(size_t)2*32*10240];    // relu(h)
// persistent-GRU weight layouts
__device__ __align__(128) half g_whhH[(size_t)64*32*1920];     // [jt][kt][48][40] hi
__device__ __align__(128) half g_whhL[(size_t)64*32*1280];     // [jt][kt][32][40] lo (z,n gates)
// h split-plane ping-pong: [buf(2)][mt(2)][kt(32)][plane(2)][128][40]
__device__ __align__(128) half g_hbuf[(size_t)2*2*32*2*128*40];

// ======================= PTX helpers =======================================
__device__ __forceinline__ unsigned saddr(const void* p) {
    return (unsigned)__cvta_generic_to_shared(p);
}
#define MBAR_INIT(mb, cnt) \
    asm volatile("mbarrier.init.shared.b64 [%0], %1;" :: "r"(mb), "r"(cnt) : "memory")
#define EXPECT_TX(mb, bytes) \
    asm volatile("mbarrier.arrive.expect_tx.shared.b64 _, [%0], %1;" :: "r"(mb), "r"(bytes) : "memory")
#define BULK_G2S(dst, src, bytes, mb) \
    asm volatile("cp.async.bulk.shared::cluster.global.mbarrier::complete_tx::bytes [%0], [%1], %2, [%3];" \
        :: "r"(dst), "l"(src), "r"(bytes), "r"(mb) : "memory")
#define MBWAIT(mb, ph) do { unsigned _d = 0; while (!_d) { \
    asm volatile("{\n\t.reg .pred p;\n\t" \
        "mbarrier.try_wait.parity.acquire.cta.shared::cta.b64 p, [%1], %2, 0x989680;\n\t" \
        "selp.b32 %0, 1, 0, p;\n\t}" \
        : "=r"(_d) : "r"(mb), "r"(ph)); } } while (0)

__device__ __forceinline__ void mma16(float* c, const unsigned* a, const unsigned* b) {
    asm volatile("mma.sync.aligned.m16n8k16.row.col.f32.f16.f16.f32 "
        "{%0,%1,%2,%3}, {%4,%5,%6,%7}, {%8,%9}, {%0,%1,%2,%3};"
        : "+f"(c[0]), "+f"(c[1]), "+f"(c[2]), "+f"(c[3])
        : "r"(a[0]), "r"(a[1]), "r"(a[2]), "r"(a[3]), "r"(b[0]), "r"(b[1]));
}
__device__ __forceinline__ void ldsm4(unsigned* r, unsigned addr) {
    asm volatile("ldmatrix.sync.aligned.m8n8.x4.shared.b16 {%0,%1,%2,%3}, [%4];"
        : "=r"(r[0]), "=r"(r[1]), "=r"(r[2]), "=r"(r[3]) : "r"(addr));
}
__device__ __forceinline__ void split2(float x, half& hi, half& lo) {
    hi = __float2half_rn(x);
    lo = __float2half_rn(x - __half2float(hi));
}

// ======================= fold precompute kernels ===========================
__global__ void transpose_f32(const float* __restrict__ s, float* __restrict__ d,
                              int R, int C)
{
    __shared__ float tile[32][33];
    int c0 = blockIdx.x * 32, r0 = blockIdx.y * 32;
    int x = threadIdx.x, y = threadIdx.y;
    #pragma unroll
    for (int i = y; i < 32; i += 8)
        tile[i][x] = s[(size_t)(r0 + i) * C + c0 + x];
    __syncthreads();
    #pragma unroll
    for (int i = y; i < 32; i += 8)
        d[(size_t)(c0 + i) * R + r0 + x] = tile[x][i];
}

__global__ __launch_bounds__(256)
void gemm_nt(const float* __restrict__ A, const float* __restrict__ W,
             const float* __restrict__ bias, float* __restrict__ C,
             int M, int N, int K)
{
    __shared__ float As[16][68];
    __shared__ float Ws[16][68];
    const int tid = threadIdx.x;
    const int m0 = blockIdx.x * 64, n0 = blockIdx.y * 64;
    const int tx = tid & 15, ty = tid >> 4;
    float acc[4][4] = {};
    const int ar = tid >> 2;
    const int ak = (tid & 3) * 4;
    const float* Aptr = A + (size_t)(m0 + ar) * K + ak;
    const float* Wptr = W + (size_t)(n0 + ar) * K + ak;
    for (int k0 = 0; k0 < K; k0 += 16) {
        float4 av = *(const float4*)(Aptr + k0);
        float4 wv = *(const float4*)(Wptr + k0);
        As[ak+0][ar] = av.x; As[ak+1][ar] = av.y; As[ak+2][ar] = av.z; As[ak+3][ar] = av.w;
        Ws[ak+0][ar] = wv.x; Ws[ak+1][ar] = wv.y; Ws[ak+2][ar] = wv.z; Ws[ak+3][ar] = wv.w;
        __syncthreads();
        #pragma unroll
        for (int k = 0; k < 16; k++) {
            float4 a = *(const float4*)&As[k][ty*4];
            float4 w = *(const float4*)&Ws[k][tx*4];
            float avv[4] = {a.x, a.y, a.z, a.w};
            float wvv[4] = {w.x, w.y, w.z, w.w};
            #pragma unroll
            for (int i = 0; i < 4; i++)
                #pragma unroll
                for (int j = 0; j < 4; j++)
                    acc[i][j] += avv[i] * wvv[j];
        }
        __syncthreads();
    }
    #pragma unroll
    for (int i = 0; i < 4; i++) {
        int m = m0 + ty*4 + i;
        #pragma unroll
        for (int j = 0; j < 4; j++) {
            int n = n0 + tx*4 + j;
            C[(size_t)m * N + n] = acc[i][j] + bias[n];
        }
    }
}

__global__ void compute_tvec(const float* __restrict__ fc2_w, const float* __restrict__ fc1_b,
                             const float* __restrict__ fc2_b, float* __restrict__ tvec)
{
    int g = (blockIdx.x * blockDim.x + threadIdx.x) >> 5;
    int lane = threadIdx.x & 31;
    if (g >= HID) return;
    const float* w = fc2_w + (size_t)g * DIM2;
    float s = 0.f;
    for (int d = lane; d < DIM2; d += 32) s += w[d] * fc1_b[d];
    #pragma unroll
    for (int o = 16; o; o >>= 1) s += __shfl_down_sync(0xffffffffu, s, o);
    if (!lane) tvec[g] = s + fc2_b[g];
}

__global__ void compute_beff(const float* __restrict__ w_ih, const float* __restrict__ tvec,
                             const float* __restrict__ b_ih, float* __restrict__ beff)
{
    int g = (blockIdx.x * blockDim.x + threadIdx.x) >> 5;
    int lane = threadIdx.x & 31;
    if (g >= G3) return;
    const float* w = w_ih + (size_t)g * HID;
    float s = 0.f;
    for (int d = lane; d < HID; d += 32) s += w[d] * tvec[d];
    #pragma unroll
    for (int o = 16; o; o >>= 1) s += __shfl_down_sync(0xffffffffu, s, o);
    if (!lane) beff[g] = s + b_ih[g];
}

__global__ void zero_bar(int* __restrict__ bar)
{
    bar[threadIdx.x] = 0;
}

// ======================= split / re-layout kernels =========================
__global__ void split_tiled(const float* __restrict__ s, half* __restrict__ dst,
                            int K, int n)
{
    int i = (blockIdx.x * blockDim.x + threadIdx.x) * 4;
    if (i >= n) return;
    int r = i / K, c = i % K;
    float4 v = *(const float4*)(s + i);
    half h[4], l[4];
    split2(v.x, h[0], l[0]); split2(v.y, h[1], l[1]);
    split2(v.z, h[2], l[2]); split2(v.w, h[3], l[3]);
    size_t base = (((size_t)(r >> 7) * (K >> 5) + (c >> 5)) * 2) * 5120
                + (size_t)(r & 127) * 40 + (c & 31);
    *(half2*)(dst + base)        = __halves2half2(h[0], h[1]);
    *(half2*)(dst + base + 2)    = __halves2half2(h[2], h[3]);
    *(half2*)(dst + base + 5120) = __halves2half2(l[0], l[1]);
    *(half2*)(dst + base + 5122) = __halves2half2(l[2], l[3]);
}

// w_hh -> persistent layouts: hi [jt][kt][48][40]; lo (z,n) [jt][kt][32][40]
__global__ void split_whh_hl(const float* __restrict__ s, half* __restrict__ dh,
                             half* __restrict__ dl)
{
    int i = (blockIdx.x * blockDim.x + threadIdx.x) * 4;
    int rw = i >> 10, c = i & 1023;
    int g = rw >> 10, j = rw & 1023;
    int jt = j >> 4, jr = j & 15, kt = c >> 5, kc = c & 31;
    float4 v = *(const float4*)(s + i);
    half h[4], l[4];
    split2(v.x, h[0], l[0]); split2(v.y, h[1], l[1]);
    split2(v.z, h[2], l[2]); split2(v.w, h[3], l[3]);
    size_t hb = ((size_t)jt * 32 + kt) * 1920 + (size_t)(g * 16 + jr) * 40 + kc;
    *(half2*)(dh + hb)     = __halves2half2(h[0], h[1]);
    *(half2*)(dh + hb + 2) = __halves2half2(h[2], h[3]);
    if (g >= 1) {
        size_t lb = ((size_t)jt * 32 + kt) * 1280 + (size_t)((g - 1) * 16 + jr) * 40 + kc;
        *(half2*)(dl + lb)     = __halves2half2(l[0], l[1]);
        *(half2*)(dl + lb + 2) = __halves2half2(l[2], l[3]);
    }
}

// h0 -> g_hbuf buffer 0: [mt][kt][plane][128][40]
__global__ void split_h0_b(const float* __restrict__ s, half* __restrict__ hbuf)
{
    int i = (blockIdx.x * blockDim.x + threadIdx.x) * 4;
    int r = i >> 10, c = i & 1023;
    int mt = r >> 7, rl = r & 127, kt = c >> 5, kc = c & 31;
    float4 v = *(const float4*)(s + i);
    half h[4], l[4];
    split2(v.x, h[0], l[0]); split2(v.y, h[1], l[1]);
    split2(v.z, h[2], l[2]); split2(v.w, h[3], l[3]);
    size_t base = (((size_t)mt * 32 + kt) * 2) * 5120 + (size_t)rl * 40 + kc;
    *(half2*)(hbuf + base)        = __halves2half2(h[0], h[1]);
    *(half2*)(hbuf + base + 2)    = __halves2half2(h[2], h[3]);
    *(half2*)(hbuf + base + 5120) = __halves2half2(l[0], l[1]);
    *(half2*)(hbuf + base + 5122) = __halves2half2(l[2], l[3]);
}

// final h -> hn_out f32 + relu(h) GEMM-A tiled (K=1024)
__global__ void finalize_h(const float* __restrict__ hsrc, float* __restrict__ out_hn,
                           half* __restrict__ rht)
{
    int i = (blockIdx.x * blockDim.x + threadIdx.x) * 4;
    int r = i >> 10, c = i & 1023;
    float4 v = *(const float4*)(hsrc + i);
    *(float4*)(out_hn + i) = v;
    float rv[4] = { fmaxf(v.x,0.f), fmaxf(v.y,0.f), fmaxf(v.z,0.f), fmaxf(v.w,0.f) };
    half h[4], l[4];
    #pragma unroll
    for (int k = 0; k < 4; k++) split2(rv[k], h[k], l[k]);
    size_t base = (((size_t)(r >> 7) * 32 + (c >> 5)) * 2) * 5120
                + (size_t)(r & 127) * 40 + (c & 31);
    *(half2*)(rht + base)        = __halves2half2(h[0], h[1]);
    *(half2*)(rht + base + 2)    = __halves2half2(h[2], h[3]);
    *(half2*)(rht + base + 5120) = __halves2half2(l[0], l[1]);
    *(half2*)(rht + base + 5122) = __halves2half2(l[2], l[3]);
}

// single extern dynamic-smem declaration for ALL kernels
extern __shared__ __align__(16) unsigned char dynsmem[];

// ======================= bulk-pipelined fp16x3 GEMM ========================
// C = (Ah+Al)@(Wh+Wl)^T + bias. BM=BN=128, BK=32, 256 thr, 3-stage.
// GILAYOUT: write to gi layout [t][jt][b][48] (m = b*256+t, n = g*1024+j).
template<bool RELU, bool GILAYOUT>
__global__ __launch_bounds__(256)
void gemm_h3b(const half* __restrict__ At, const half* __restrict__ Wt,
              const float* __restrict__ bias, float* __restrict__ C,
              int N, int KT)
{
    half* sA = (half*)dynsmem;
    half* sW = (half*)dynsmem + 3 * 10240;
    __shared__ __align__(8) unsigned long long mbar[3];

    const int tid = threadIdx.x, wid = tid >> 5, lane = tid & 31;
    const int n0 = blockIdx.x * 128, m0 = blockIdx.y * 128;
    const int wm = wid & 3, wn = wid >> 2;
    const half* Ab = At + (size_t)blockIdx.y * KT * 10240;
    const half* Wb = Wt + (size_t)blockIdx.x * KT * 10240;

    if (tid == 0)
        for (int s = 0; s < 3; s++) MBAR_INIT(saddr(&mbar[s]), 1);
    __syncthreads();
    if (tid == 0) {
        for (int s = 0; s < 2 && s < KT; s++) {
            EXPECT_TX(saddr(&mbar[s]), 40960);
            BULK_G2S(saddr(sA + s*10240), Ab + (size_t)s*10240, 20480, saddr(&mbar[s]));
            BULK_G2S(saddr(sW + s*10240), Wb + (size_t)s*10240, 20480, saddr(&mbar[s]));
        }
    }

    float acc[2][8][4] = {};
    const unsigned aOff = (unsigned)((wm*32 + (lane & 15)) * 80 + ((lane >> 4) & 1) * 16);
    const unsigned bOff = (unsigned)((wn*64 + (lane & 7) + ((lane >> 4) & 1) * 8) * 80
                                     + ((lane >> 3) & 1) * 16);
    const unsigned baseA = saddr(sA), baseW = saddr(sW);

    for (int kt = 0; kt < KT; kt++) {
        __syncthreads();
        if (tid == 0) {
            int ks = kt + 2;
            if (ks < KT) {
                int sl = ks % 3;
                EXPECT_TX(saddr(&mbar[sl]), 40960);
                BULK_G2S(saddr(sA + sl*10240), Ab + (size_t)ks*10240, 20480, saddr(&mbar[sl]));
                BULK_G2S(saddr(sW + sl*10240), Wb + (size_t)ks*10240, 20480, saddr(&mbar[sl]));
            }
        }
        const int slot = kt % 3, par = (kt / 3) & 1;
        MBWAIT(saddr(&mbar[slot]), par);

        const unsigned bAh = baseA + slot * 20480;
        const unsigned bAl = bAh + 10240;
        const unsigned bWh = baseW + slot * 20480;
        const unsigned bWl = bWh + 10240;

        #pragma unroll
        for (int kk = 0; kk < 2; kk++) {
            unsigned ah[2][4], al[2][4];
            #pragma unroll
            for (int mt = 0; mt < 2; mt++) {
                unsigned off = aOff + mt * (16*80) + kk * 32;
                ldsm4(ah[mt], bAh + off);
                ldsm4(al[mt], bAl + off);
            }
            #pragma unroll
            for (int p4 = 0; p4 < 4; p4++) {
                unsigned off = bOff + p4 * (16*80) + kk * 32;
                unsigned bh[4], bl[4];
                ldsm4(bh, bWh + off);
                ldsm4(bl, bWl + off);
                #pragma unroll
                for (int t2 = 0; t2 < 2; t2++) {
                    int nt = p4 * 2 + t2;
                    #pragma unroll
                    for (int mt = 0; mt < 2; mt++) {
                        mma16(acc[mt][nt], ah[mt], bh + t2*2);
                        mma16(acc[mt][nt], ah[mt], bl + t2*2);
                        mma16(acc[mt][nt], al[mt], bh + t2*2);
                    }
                }
            }
        }
    }

    #pragma unroll
    for (int mt = 0; mt < 2; mt++)
        #pragma unroll
        for (int nt = 0; nt < 8; nt++) {
            int n = n0 + wn*64 + nt*8 + (lane & 3) * 2;
            float bx = bias[n], by = bias[n + 1];
            #pragma unroll
            for (int h2 = 0; h2 < 2; h2++) {
                int m = m0 + wm*32 + mt*16 + (lane >> 2) + h2*8;
                float vx = acc[mt][nt][h2*2+0] + bx;
                float vy = acc[mt][nt][h2*2+1] + by;
                if (RELU) { vx = fmaxf(vx, 0.f); vy = fmaxf(vy, 0.f); }
                float2 v; v.x = vx; v.y = vy;
                if (GILAYOUT) {
                    int b = m >> 8, tt = m & 255;
                    int g = n >> 10, j = n & 1023;
                    size_t addr = (((size_t)tt * 64 + (j >> 4)) * 256 + b) * 48
                                + g * 16 + (j & 15);
                    *(float2*)(C + addr) = v;
                } else {
                    *(float2*)(C + (size_t)m * N + n) = v;
                }
            }
        }
}

// ======================= persistent GRU kernel ==============================
// Grid (jt=64, mt=2) = 128 blocks, 256 thr (8 warps; warp w = m rows w*16..+16,
// all 48 gate-cols of this block's 16-j tile). One launch covers all 256 steps.
// SMEM: W_hi resident [kt32][48][40] (122880B) | 3 stages (H 20480 + Wlo(z,n) 2560)
//       | gi chunk [128][48] f32 (24576B).
#define STG_SZ   23040
#define OFF_STG  122880
#define OFF_GI   (122880 + 3*STG_SZ)        // 192000
#define PERS_SMEM (OFF_GI + 24576)          // 216576

__global__ __launch_bounds__(256)
void gru_persist(const float* __restrict__ hn,
                 const half* __restrict__ whhH, const half* __restrict__ whhL,
                 const float* __restrict__ gi2, const float* __restrict__ b_hh,
                 half* __restrict__ hbuf, float* __restrict__ hf_final,
                 int* __restrict__ bar)
{
    __shared__ __align__(8) unsigned long long mbar[5];
    const unsigned sb = saddr(dynsmem);
    const int tid = threadIdx.x, w = tid >> 5, lane = tid & 31;
    const int jt = blockIdx.x, mt = blockIdx.y;

    if (tid == 0)
        for (int i = 0; i < 5; i++) MBAR_INIT(saddr(&mbar[i]), 1);
    __syncthreads();
    const unsigned mbW = saddr(&mbar[0]);
    const unsigned mbS = saddr(&mbar[1]);   // +8*s
    const unsigned mbG = saddr(&mbar[4]);

    // resident W_hi load (once)
    if (tid == 0) {
        EXPECT_TX(mbW, 122880);
        BULK_G2S(sb, (const char*)whhH + (size_t)jt * 122880, 122880, mbW);
    }

    // per-thread output coordinates
    const int mrow = w * 16 + (lane >> 2);        // + h2*8
    const int jl0  = (lane & 3) * 2;              // + t2*8 (+c)
    float hprev[8];
    float bb[12];
    #pragma unroll
    for (int h2 = 0; h2 < 2; h2++)
        #pragma unroll
        for (int t2 = 0; t2 < 2; t2++) {
            int m = mt*128 + mrow + h2*8;
            int j = jt*16 + t2*8 + jl0;
            float2 hv = *(const float2*)(hn + (size_t)m * HID + j);
            hprev[h2*4 + t2*2 + 0] = hv.x;
            hprev[h2*4 + t2*2 + 1] = hv.y;
        }
    #pragma unroll
    for (int g = 0; g < 3; g++)
        #pragma unroll
        for (int t2 = 0; t2 < 2; t2++) {
            float2 bv = *(const float2*)(b_hh + g*HID + jt*16 + t2*8 + jl0);
            bb[g*4 + t2*2 + 0] = bv.x;
            bb[g*4 + t2*2 + 1] = bv.y;
        }

    const unsigned aOff = (unsigned)((w*16 + (lane & 15)) * 80 + ((lane >> 4) & 1) * 16);
    const unsigned bOff = (unsigned)(((lane & 7) + ((lane >> 4) & 1) * 8) * 80
                                     + ((lane >> 3) & 1) * 16);

    int us0 = 0, us1 = 0, us2 = 0;   // per-slot use counters (parity)
    MBWAIT(mbW, 0);

    for (int t = 0; t < T_SZ; t++) {
        const char* Hb = (const char*)hbuf
            + (((size_t)(t & 1) * 2 + mt) * 32) * 20480;
        const char* Lb = (const char*)whhL + (size_t)jt * 32 * 2560;
        if (tid == 0) {
            EXPECT_TX(mbG, 24576);
            BULK_G2S(sb + OFF_GI,
                     (const char*)gi2 + ((((size_t)t * 64 + jt) * 256 + mt*128) * 48) * 4,
                     24576, mbG);
            #pragma unroll
            for (int s = 0; s < 3; s++) {
                EXPECT_TX(mbS + 8*s, STG_SZ);
                BULK_G2S(sb + OFF_STG + s*STG_SZ,         Hb + (size_t)s*20480, 20480, mbS + 8*s);
                BULK_G2S(sb + OFF_STG + s*STG_SZ + 20480, Lb + (size_t)s*2560,  2560,  mbS + 8*s);
            }
        }

        float acc[6][4] = {};
        int slot = 0;
        for (int kt = 0; kt < 32; kt++) {
            int par;
            if (slot == 0)      { par = us0 & 1; us0++; }
            else if (slot == 1) { par = us1 & 1; us1++; }
            else                { par = us2 & 1; us2++; }
            MBWAIT(mbS + 8*slot, par);

            const unsigned hHi = sb + OFF_STG + slot*STG_SZ;
            const unsigned hLo = hHi + 10240;
            const unsigned wLo = hHi + 20480;
            const unsigned wHi = sb + kt * 3840;

            #pragma unroll
            for (int kk = 0; kk < 2; kk++) {
                unsigned ah[4], al[4];
                ldsm4(ah, hHi + aOff + kk*32);
                ldsm4(al, hLo + aOff + kk*32);
                unsigned br[4], bz[4], bn[4], blz[4], bln[4];
                ldsm4(br,  wHi + bOff + kk*32);
                ldsm4(bz,  wHi + bOff + 16*80 + kk*32);
                ldsm4(bn,  wHi + bOff + 32*80 + kk*32);
                ldsm4(blz, wLo + bOff + kk*32);
                ldsm4(bln, wLo + bOff + 16*80 + kk*32);
                #pragma unroll
                for (int t2 = 0; t2 < 2; t2++) {
                    // r gate: 2-term (W hi only)
                    mma16(acc[0+t2], ah, br + t2*2);
                    mma16(acc[0+t2], al, br + t2*2);
                    // z gate: 3-term
                    mma16(acc[2+t2], ah, bz + t2*2);
                    mma16(acc[2+t2], al, bz + t2*2);
                    mma16(acc[2+t2], ah, blz + t2*2);
                    // n gate: 3-term
                    mma16(acc[4+t2], ah, bn + t2*2);
                    mma16(acc[4+t2], al, bn + t2*2);
                    mma16(acc[4+t2], ah, bln + t2*2);
                }
            }
            __syncthreads();
            if (tid == 0 && kt + 3 < 32) {
                int ks = kt + 3;
                EXPECT_TX(mbS + 8*slot, STG_SZ);
                BULK_G2S(sb + OFF_STG + slot*STG_SZ,         Hb + (size_t)ks*20480, 20480, mbS + 8*slot);
                BULK_G2S(sb + OFF_STG + slot*STG_SZ + 20480, Lb + (size_t)ks*2560,  2560,  mbS + 8*slot);
            }
            slot = (slot == 2) ? 0 : slot + 1;
        }

        // epilogue: gates + state update
        MBWAIT(mbG, t & 1);
        const float* gis = (const float*)(dynsmem + OFF_GI);
        char* ob = (char*)hbuf
            + ((((size_t)((t+1) & 1) * 2 + mt) * 32 + (jt >> 1))) * 20480;
        const int kc0 = (jt & 1) * 16;

        #pragma unroll
        for (int h2 = 0; h2 < 2; h2++) {
            int ml = mrow + h2*8;
            #pragma unroll
            for (int t2 = 0; t2 < 2; t2++) {
                float hh[2];
                #pragma unroll
                for (int c = 0; c < 2; c++) {
                    int fi = h2*2 + c;
                    int jl = t2*8 + jl0 + c;
                    float rpre = acc[0+t2][fi] + bb[0 + t2*2 + c] + gis[ml*48 + jl];
                    float zpre = acc[2+t2][fi] + bb[4 + t2*2 + c] + gis[ml*48 + 16 + jl];
                    float hnn  = acc[4+t2][fi] + bb[8 + t2*2 + c];
                    float r_ = 1.f / (1.f + expf(-rpre));
                    float z_ = 1.f / (1.f + expf(-zpre));
                    float n_ = tanhf(gis[ml*48 + 32 + jl] + r_ * hnn);
                    int pi = h2*4 + t2*2 + c;
                    float hv = (1.f - z_) * n_ + z_ * hprev[pi];
                    hprev[pi] = hv;
                    hh[c] = hv;
                }
                half a0, b0, a1, b1;
                split2(hh[0], a0, b0);
                split2(hh[1], a1, b1);
                int kc = kc0 + t2*8 + jl0;
                *(half2*)(ob + (size_t)ml*80 + kc*2)         = __halves2half2(a0, a1);
                *(half2*)(ob + 10240 + (size_t)ml*80 + kc*2) = __halves2half2(b0, b1);
                if (t == T_SZ - 1) {
                    float2 fv; fv.x = hh[0]; fv.y = hh[1];
                    *(float2*)(hf_final + (size_t)(mt*128 + ml) * HID
                               + jt*16 + t2*8 + jl0) = fv;
                }
            }
        }

        // inter-step barrier (per m-group of 64 blocks)
        if (t < T_SZ - 1) {
            __threadfence();
            __syncthreads();
            if (tid == 0) {
                int* cnt = bar + mt * T_SZ + t;
                atomicAdd(cnt, 1);
                while (atomicAdd(cnt, 0) < 64) { }
            }
            __syncthreads();
        }
    }
}

// ======================= tail ==============================================
__global__ __launch_bounds__(128)
void heads_kernel(const float* __restrict__ o3, const int* __restrict__ cult,
                  const float* __restrict__ hw, const float* __restrict__ hb,
                  float* __restrict__ outp)
{
    int b = blockIdx.x;
    int c = cult[b];
    __shared__ float sv[DIM2];
    for (int i = threadIdx.x; i < DIM2; i += blockDim.x)
        sv[i] = o3[(size_t)b * DIM2 + i];
    __syncthreads();
    int o = threadIdx.x >> 3, l = threadIdx.x & 7;
    const float* w = hw + ((size_t)c * OUT_DIM + o) * DIM2;
    float s = 0.f;
    for (int d = l; d < DIM2; d += 8) s += sv[d] * w[d];
    s += __shfl_down_sync(0xffffffffu, s, 4);
    s += __shfl_down_sync(0xffffffffu, s, 2);
    s += __shfl_down_sync(0xffffffffu, s, 1);
    if (l == 0) outp[b * OUT_DIM + o] = s + hb[c * OUT_DIM + o];
}

// ======================= launch ============================================
#define GEMM_SMEM (3*10240*2*2)   // 122880 B

extern "C" void kernel_launch(void* const* d_in, const int* in_sizes, int n_in,
                              void* d_out, int out_size)
{
    const float* input = (const float*)d_in[0];
    const float* hn    = (const float*)d_in[1];
    const int*   cult  = (const int*)  d_in[2];
    const float* fc1_w = (const float*)d_in[3];
    const float* fc1_b = (const float*)d_in[4];
    const float* fc2_w = (const float*)d_in[5];
    const float* fc2_b = (const float*)d_in[6];
    const float* w_ih  = (const float*)d_in[7];
    const float* w_hh  = (const float*)d_in[8];
    const float* b_ih  = (const float*)d_in[9];
    const float* b_hh  = (const float*)d_in[10];
    const float* fc3_w = (const float*)d_in[11];
    const float* fc3_b = (const float*)d_in[12];
    const float* hw    = (const float*)d_in[13];
    const float* hb    = (const float*)d_in[14];
    float* outp = (float*)d_out;

    float *gi, *o3, *hf, *fc2T, *fc1T, *T1, *weff, *tvec, *beff, *zb;
    int* bar;
    half *intl, *wefft, *w3t, *rht, *whhH, *whhL, *hbuf;
    cudaGetSymbolAddress((void**)&gi, g_gi);
    cudaGetSymbolAddress((void**)&o3, g_o3);
    cudaGetSymbolAddress((void**)&hf, g_hf);
    cudaGetSymbolAddress((void**)&bar, g_bar);
    cudaGetSymbolAddress((void**)&fc2T, g_fc2T);
    cudaGetSymbolAddress((void**)&fc1T, g_fc1T);
    cudaGetSymbolAddress((void**)&T1, g_T1);
    cudaGetSymbolAddress((void**)&weff, g_weff);
    cudaGetSymbolAddress((void**)&tvec, g_tvec);
    cudaGetSymbolAddress((void**)&beff, g_beff);
    cudaGetSymbolAddress((void**)&zb, g_zbias);
    cudaGetSymbolAddress((void**)&intl, g_int);
    cudaGetSymbolAddress((void**)&wefft, g_wefft);
    cudaGetSymbolAddress((void**)&w3t, g_w3t);
    cudaGetSymbolAddress((void**)&rht, g_rht);
    cudaGetSymbolAddress((void**)&whhH, g_whhH);
    cudaGetSymbolAddress((void**)&whhL, g_whhL);
    cudaGetSymbolAddress((void**)&hbuf, g_hbuf);

    cudaFuncSetAttribute(gemm_h3b<false,true>,
                         cudaFuncAttributeMaxDynamicSharedMemorySize, GEMM_SMEM);
    cudaFuncSetAttribute(gemm_h3b<true,false>,
                         cudaFuncAttributeMaxDynamicSharedMemorySize, GEMM_SMEM);
    cudaFuncSetAttribute(gru_persist,
                         cudaFuncAttributeMaxDynamicSharedMemorySize, PERS_SMEM);

    // fold precompute: W_eff = w_ih @ fc2_w @ fc1_w, b_eff
    transpose_f32<<<dim3(DIM2/32, HID/32), dim3(32,8)>>>(fc2_w, fc2T, HID, DIM2);
    transpose_f32<<<dim3(IN_DIM/32, DIM2/32), dim3(32,8)>>>(fc1_w, fc1T, DIM2, IN_DIM);
    gemm_nt<<<dim3(G3/64, DIM2/64), 256>>>(w_ih, fc2T, zb, T1, G3, DIM2, HID);
    gemm_nt<<<dim3(G3/64, IN_DIM/64), 256>>>(T1, fc1T, zb, weff, G3, IN_DIM, DIM2);
    compute_tvec<<<HID*32/256, 256>>>(fc2_w, fc1_b, fc2_b, tvec);
    compute_beff<<<G3*32/256, 256>>>(w_ih, tvec, b_ih, beff);
    zero_bar<<<1, 2*T_SZ>>>(bar);

    // splits
    split_tiled<<<MT*IN_DIM/1024, 256>>>(input, intl, IN_DIM, MT*IN_DIM);
    split_tiled<<<G3*IN_DIM/1024, 256>>>(weff, wefft, IN_DIM, G3*IN_DIM);
    split_tiled<<<DIM2*HID/1024, 256>>>(fc3_w, w3t, HID, DIM2*HID);
    split_whh_hl<<<G3*HID/1024, 256>>>(w_hh, whhH, whhL);
    split_h0_b<<<B_SZ*HID/1024, 256>>>(hn, hbuf);

    // gi = input @ W_eff^T + b_eff, K=64, layout [t][jt][b][48]
    gemm_h3b<false,true><<<dim3(G3/128, MT/128), 256, GEMM_SMEM>>>(
        intl, wefft, beff, gi, G3, IN_DIM/32);

    // persistent GRU: one launch, 256 steps
    gru_persist<<<dim3(64, 2), 256, PERS_SMEM>>>(
        hn, whhH, whhL, gi, b_hh, hbuf, hf, bar);

    int hn_off = out_size - B_SZ * HID;
    finalize_h<<<B_SZ*HID/1024, 256>>>(hf, outp + hn_off, rht);

    // fc3: relu(h) @ fc3_w^T, relu epilogue
    gemm_h3b<true,false><<<dim3(DIM2/128, B_SZ/128), 256, GEMM_SMEM>>>(
        rht, w3t, fc3_b, o3, DIM2, HID/32);

    heads_kernel<<<B_SZ, 128>>>(o3, cult, hw, hb, outp);
}